// round 7
// baseline (speedup 1.0000x reference)
#include <cuda_runtime.h>
#include <cuda_bf16.h>
#include <math.h>
#include <stdint.h>

#define N_RBF 300
#define NBUCK 512
#define N_MAXN 100352
#define E_MAXE 400384
#define GE_MAX 3128
#define RBF_STEP (30.0f/299.0f)
#define RBF_INV  (299.0f/30.0f)
#define SLD 40
#define BUFB 10240
#define DSMEM2 81920
#define DSMEM3 116736

__device__ float g_h  [(size_t)N_MAXN*128];
__device__ float g_tmp[(size_t)N_MAXN*128];
__device__ float g_P  [3*400*428];
__device__ int   g_perm[E_MAXE];
__device__ int   g_hist[2*NBUCK];
__device__ int   g_klo [GE_MAX];
__device__ __nv_bfloat16 g_rAh[(size_t)E_MAXE*64],  g_rAl[(size_t)E_MAXE*64];
__device__ __nv_bfloat16 g_W1h[3*512*384],  g_W1l[3*512*384];
__device__ __nv_bfloat16 g_We2h[3*128*448], g_We2l[3*128*448];
__device__ __nv_bfloat16 g_Wn1h[3*128*128], g_Wn1l[3*128*128];
__device__ __nv_bfloat16 g_Wn2h[3*128*128], g_Wn2l[3*128*128];
__device__ __nv_bfloat16 g_Wch [3*128*128], g_Wcl [3*128*128];
__device__ __nv_bfloat16 g_Wr1h[128*128],   g_Wr1l[128*128];

__device__ __forceinline__ uint32_t smem_u32(const void* p) {
    uint32_t a;
    asm("{ .reg .u64 t; cvta.to.shared.u64 t, %1; cvt.u32.u64 %0, t; }" : "=r"(a) : "l"(p));
    return a;
}
__device__ __forceinline__ void ldmx4(uint32_t& r0, uint32_t& r1, uint32_t& r2, uint32_t& r3, uint32_t a) {
    asm volatile("ldmatrix.sync.aligned.m8n8.x4.shared.b16 {%0,%1,%2,%3}, [%4];"
        : "=r"(r0), "=r"(r1), "=r"(r2), "=r"(r3) : "r"(a));
}
__device__ __forceinline__ void mma16816(float* c, const uint32_t* a, const uint32_t* b) {
    asm volatile("mma.sync.aligned.m16n8k16.row.col.f32.bf16.bf16.f32 "
        "{%0,%1,%2,%3},{%4,%5,%6,%7},{%8,%9},{%0,%1,%2,%3};"
        : "+f"(c[0]), "+f"(c[1]), "+f"(c[2]), "+f"(c[3])
        : "r"(a[0]), "r"(a[1]), "r"(a[2]), "r"(a[3]), "r"(b[0]), "r"(b[1]));
}
__device__ __forceinline__ void pack2(float a, float b, uint32_t& h, uint32_t& l) {
    __nv_bfloat162 hb = __floats2bfloat162_rn(a, b);
    __nv_bfloat162 lb = __floats2bfloat162_rn(a - __low2float(hb), b - __high2float(hb));
    h = *reinterpret_cast<uint32_t*>(&hb);
    l = *reinterpret_cast<uint32_t*>(&lb);
}
#define CPA16(dst, src) asm volatile("cp.async.cg.shared.global [%0], [%1], 16;" :: "r"(dst), "l"(src))
#define CPC()  asm volatile("cp.async.commit_group;" ::: "memory")
#define CPW0() asm volatile("cp.async.wait_group 0;" ::: "memory")
#define CPW1() asm volatile("cp.async.wait_group 1;" ::: "memory")

__global__ void zero_hist_k() { int i = blockIdx.x*256 + threadIdx.x; if (i < 2*NBUCK) g_hist[i] = 0; }
__global__ void zero_f_k(float* p, int n) { int i = blockIdx.x*256 + threadIdx.x; if (i < n) p[i] = 0.f; }
__device__ __forceinline__ int bucket_of(float d) {
    int b = (int)(d * (512.0f/30.0f));
    return min(max(b, 0), NBUCK-1);
}
__global__ void hist_k(const float* __restrict__ dist, int E) {
    int e = blockIdx.x*256 + threadIdx.x;
    if (e < E) atomicAdd(&g_hist[bucket_of(dist[e])], 1);
}
__global__ void scan512_k() {
    __shared__ int s[NBUCK];
    int tid = threadIdx.x;
    int v0 = g_hist[tid];
    s[tid] = v0; __syncthreads();
    for (int off = 1; off < NBUCK; off <<= 1) {
        int v = 0;
        if (tid >= off) v = s[tid - off];
        __syncthreads(); s[tid] += v; __syncthreads();
    }
    g_hist[NBUCK + tid] = s[tid] - v0;
}
__global__ void scatter_perm_k(const float* __restrict__ dist, int E) {
    int e = blockIdx.x*256 + threadIdx.x;
    if (e < E) {
        int pos = atomicAdd(&g_hist[NBUCK + bucket_of(dist[e])], 1);
        g_perm[pos] = e;
    }
}
__global__ void init_h_k(const int* __restrict__ Z, const float* __restrict__ ne,
                         float* __restrict__ h, int N) {
    int idx = blockIdx.x*256 + threadIdx.x;
    if (idx < N*128) h[idx] = ne[Z[idx >> 7]*128 + (idx & 127)];
}
__global__ void split_pad_k(const float* __restrict__ src, __nv_bfloat16* __restrict__ dh,
                            __nv_bfloat16* __restrict__ dl,
                            int R, int Ks, int ld, int off, int Kpad, int tot) {
    int idx = blockIdx.x*256 + threadIdx.x;
    if (idx < tot) {
        int r = idx / Kpad, k = idx % Kpad;
        float v = (r < R && k < Ks) ? src[(size_t)r*ld + off + k] : 0.f;
        __nv_bfloat16 h = __float2bfloat16(v);
        dh[idx] = h;
        dl[idx] = __float2bfloat16(v - __bfloat162float(h));
    }
}
__global__ void p_kernel(const float* __restrict__ edge_emb, const float* __restrict__ We1,
                         const float* __restrict__ be1, float* __restrict__ P) {
    int ty = blockIdx.x, layer = blockIdx.y, j = threadIdx.x;
    __shared__ float em[128];
    if (j < 128) em[j] = edge_emb[ty*128 + j];
    __syncthreads();
    if (j < 428) {
        const float* wrow = We1 + ((size_t)layer*428 + j)*428;
        float acc = be1[layer*428 + j];
        #pragma unroll 8
        for (int k = 0; k < 128; k++) acc = fmaf(em[k], wrow[k], acc);
        P[((size_t)layer*400 + ty)*428 + j] = acc;
    }
}
__global__ void rbf_klo_k(const float* __restrict__ dist, int E) {
    __shared__ float s[128];
    int tid = threadIdx.x, gr = blockIdx.x*128 + tid;
    s[tid] = dist[g_perm[min(gr, E-1)]];
    __syncthreads();
    for (int o = 64; o > 0; o >>= 1) {
        if (tid < o) s[tid] = fminf(s[tid], s[tid + o]);
        __syncthreads();
    }
    if (tid == 0) {
        int k = (int)floorf((s[0] - 2.0f) * RBF_INV);
        if (k < 0) k = 0;
        g_klo[blockIdx.x] = k & ~7;
    }
}
__global__ void rbf_split_k(const float* __restrict__ dist, int E) {
    int tid = threadIdx.x, gr = blockIdx.x*128 + tid;
    float d = dist[g_perm[min(gr, E-1)]];
    int k0 = g_klo[blockIdx.x];
    float vals[64];
    #pragma unroll
    for (int i = 0; i < 64; i++) vals[i] = 0.f;
    int icen = (int)(d * RBF_INV) - k0;
    int ilo = max(0, icen - 22);
    int ihi = min(min(63, icen + 22), 299 - k0);
    for (int i = ilo; i <= ihi; i++) {
        float x = d - (float)(k0 + i) * RBF_STEP;
        vals[i] = __expf(-RBF_INV * x * x);
    }
    size_t base = (size_t)gr * 64;
    #pragma unroll
    for (int i = 0; i < 64; i += 8) {
        uint4 H, L;
        pack2(vals[i+0], vals[i+1], H.x, L.x);
        pack2(vals[i+2], vals[i+3], H.y, L.y);
        pack2(vals[i+4], vals[i+5], H.z, L.z);
        pack2(vals[i+6], vals[i+7], H.w, L.w);
        *(uint4*)(g_rAh + base + i) = H;
        *(uint4*)(g_rAl + base + i) = L;
    }
}

// ============ mega fused kernel: t -> ee -> mix -> scatter ============
// per CTA (128 edges):
//   t = relu(rbfA @ W1^T + P[etype])           (chunked, smem only)
//   ee = t @ We2^T + be2                       (registers)
//   m  = tanh((hn2[src] * ee) @ Wc^T + bc)
//   h[dst] += m                                (atomicAdd)
__global__ void __launch_bounds__(256)
fused_layer(const __nv_bfloat16* __restrict__ W1h, const __nv_bfloat16* __restrict__ W1l,
            const __nv_bfloat16* __restrict__ W2h, const __nv_bfloat16* __restrict__ W2l,
            const __nv_bfloat16* __restrict__ Wch, const __nv_bfloat16* __restrict__ Wcl,
            const float* __restrict__ P, const float* __restrict__ be2,
            const float* __restrict__ bc,
            const int* __restrict__ etype, const int* __restrict__ srci,
            const int* __restrict__ dsti,
            const float* __restrict__ hn2, float* __restrict__ h, int E) {
    extern __shared__ char ds[];
    __shared__ int sety[128], sidxs[128], sdsts[128];
    __shared__ float sb2[128], sbc[128];
    int tid = threadIdx.x, lane = tid & 31, warp = tid >> 5, bx = blockIdx.x;
    int klo = g_klo[bx];
    if (tid < 128) {
        int e = g_perm[min(bx*128 + tid, E-1)];
        sety[tid] = etype[e];
        sidxs[tid] = srci[e];
        sdsts[tid] = dsti[e];
        sb2[tid] = be2[tid];
        sbc[tid] = bc[tid];
    }
    uint32_t b0 = smem_u32(ds);
    uint32_t uTh = b0,          uTl = b0 + 10240;
    uint32_t uAh = b0 + 20480,  uAl = b0 + 38912;
    uint32_t uW1h = b0 + 57344, uW1l = b0 + 66560;
    uint32_t uW2h = b0 + 75776, uW2l = b0 + 96256;

    // load rbfA tile 128x64 hi/lo (stride 72)
    {
        int row = tid >> 2, k = (tid & 3) << 3;
        #pragma unroll
        for (int i = 0; i < 2; i++)
        #pragma unroll
        for (int j = 0; j < 2; j++) {
            int r = row + i*64, kk = k + j*32;
            uint32_t d = (uint32_t)(r*72 + kk)*2;
            size_t s = (size_t)(bx*128 + r)*64 + kk;
            CPA16(uAh + d, g_rAh + s);
            CPA16(uAl + d, g_rAl + s);
        }
    }
    // chunk 0 weights
    {
        int r1 = tid >> 3, k1 = (tid & 7) << 3;
        uint32_t d1 = (uint32_t)(r1*72 + k1)*2;
        size_t s1 = (size_t)r1*384 + klo + k1;
        CPA16(uW1h + d1, W1h + s1);
        CPA16(uW1l + d1, W1l + s1);
        int r2 = tid >> 2, k2 = (tid & 3) << 3;
        uint32_t d2a = (uint32_t)(r2*SLD + k2)*2, d2b = (uint32_t)((r2+64)*SLD + k2)*2;
        size_t s2a = (size_t)r2*448 + k2, s2b = (size_t)(r2+64)*448 + k2;
        CPA16(uW2h + d2a, W2h + s2a); CPA16(uW2h + d2b, W2h + s2b);
        CPA16(uW2l + d2a, W2l + s2a); CPA16(uW2l + d2b, W2l + s2b);
    }
    CPC(); CPW0();
    __syncthreads();

    int arow = lane & 15, acol = (lane >> 4) << 3;
    int brow = (lane & 7) + ((lane >> 1) & 8), bcol = lane & 8;
    uint32_t a1off = (uint32_t)((warp*16 + arow)*72 + acol)*2;
    uint32_t b1off0 = (uint32_t)(brow*72 + bcol)*2;
    uint32_t b1off1 = (uint32_t)((16 + brow)*72 + bcol)*2;
    int m0 = (warp >> 2)*64, n0 = (warp & 3)*32;
    uint32_t a2off[4];
    #pragma unroll
    for (int mi = 0; mi < 4; mi++) a2off[mi] = (uint32_t)((m0 + mi*16 + arow)*SLD + acol)*2;
    uint32_t b2off0 = (uint32_t)((n0 + brow)*SLD + bcol)*2;
    uint32_t b2off1 = (uint32_t)((n0 + 16 + brow)*SLD + bcol)*2;
    int lrow = lane >> 2, lcol = (lane & 3)*2;

    float eacc[4][4][4];
    #pragma unroll
    for (int mi = 0; mi < 4; mi++)
        #pragma unroll
        for (int ni = 0; ni < 4; ni++)
            #pragma unroll
            for (int q = 0; q < 4; q++) eacc[mi][ni][q] = 0.f;

    int buf = 0;
    for (int c = 0; c < 14; c++) {
        if (c < 13) {
            uint32_t cb = (uint32_t)(buf ^ 1);
            int r1 = tid >> 3, k1 = (tid & 7) << 3;
            uint32_t d1 = cb*4608 + (uint32_t)(r1*72 + k1)*2;
            size_t s1 = (size_t)((c+1)*32 + r1)*384 + klo + k1;
            CPA16(uW1h + d1, W1h + s1);
            CPA16(uW1l + d1, W1l + s1);
            int r2 = tid >> 2, k2 = (tid & 3) << 3;
            uint32_t d2a = cb*10240 + (uint32_t)(r2*SLD + k2)*2;
            uint32_t d2b = cb*10240 + (uint32_t)((r2+64)*SLD + k2)*2;
            size_t s2a = (size_t)r2*448 + (c+1)*32 + k2;
            size_t s2b = (size_t)(r2+64)*448 + (c+1)*32 + k2;
            CPA16(uW2h + d2a, W2h + s2a); CPA16(uW2h + d2b, W2h + s2b);
            CPA16(uW2l + d2a, W2l + s2a); CPA16(uW2l + d2b, W2l + s2b);
            CPC();
        }
        // MMA1: t_chunk[128,32]
        float acc1[4][4];
        #pragma unroll
        for (int ni = 0; ni < 4; ni++)
            #pragma unroll
            for (int q = 0; q < 4; q++) acc1[ni][q] = 0.f;
        {
            uint32_t w1b = (uint32_t)buf * 4608;
            #pragma unroll
            for (int ks = 0; ks < 4; ks++) {
                uint32_t ah[4], al[4], bh[8], bl[8];
                ldmx4(ah[0], ah[1], ah[2], ah[3], uAh + a1off + ks*32);
                ldmx4(al[0], al[1], al[2], al[3], uAl + a1off + ks*32);
                ldmx4(bh[0], bh[1], bh[2], bh[3], uW1h + w1b + b1off0 + ks*32);
                ldmx4(bh[4], bh[5], bh[6], bh[7], uW1h + w1b + b1off1 + ks*32);
                ldmx4(bl[0], bl[1], bl[2], bl[3], uW1l + w1b + b1off0 + ks*32);
                ldmx4(bl[4], bl[5], bl[6], bl[7], uW1l + w1b + b1off1 + ks*32);
                #pragma unroll
                for (int ni = 0; ni < 4; ni++) {
                    mma16816(acc1[ni], ah, &bh[ni*2]);
                    mma16816(acc1[ni], ah, &bl[ni*2]);
                    mma16816(acc1[ni], al, &bh[ni*2]);
                }
            }
        }
        // epilogue1: +P, relu, pack -> sT
        {
            int gcb = c*32;
            #pragma unroll
            for (int half = 0; half < 2; half++) {
                int r = warp*16 + lrow + half*8;
                const float* Pr = P + (size_t)sety[r]*428;
                #pragma unroll
                for (int ni = 0; ni < 4; ni++) {
                    int col = ni*8 + lcol;
                    int gcol = gcb + col;
                    float v0 = 0.f, v1 = 0.f;
                    if (gcol < 428) {
                        float2 pv = *(const float2*)(Pr + gcol);
                        v0 = fmaxf(acc1[ni][half*2+0] + pv.x, 0.f);
                        v1 = fmaxf(acc1[ni][half*2+1] + pv.y, 0.f);
                    }
                    uint32_t H, L;
                    pack2(v0, v1, H, L);
                    uint32_t doff = (uint32_t)(r*SLD + col)*2;
                    *(uint32_t*)(ds + doff) = H;
                    *(uint32_t*)(ds + 10240 + doff) = L;
                }
            }
        }
        __syncthreads();
        // MMA2: ee += t_chunk @ We2_chunk^T
        {
            uint32_t w2b = (uint32_t)buf * 10240;
            #pragma unroll
            for (int ks = 0; ks < 2; ks++) {
                uint32_t bh[8], bl[8];
                ldmx4(bh[0], bh[1], bh[2], bh[3], uW2h + w2b + b2off0 + ks*32);
                ldmx4(bh[4], bh[5], bh[6], bh[7], uW2h + w2b + b2off1 + ks*32);
                ldmx4(bl[0], bl[1], bl[2], bl[3], uW2l + w2b + b2off0 + ks*32);
                ldmx4(bl[4], bl[5], bl[6], bl[7], uW2l + w2b + b2off1 + ks*32);
                #pragma unroll
                for (int mi = 0; mi < 4; mi++) {
                    uint32_t ah[4], al[4];
                    ldmx4(ah[0], ah[1], ah[2], ah[3], uTh + a2off[mi] + ks*32);
                    ldmx4(al[0], al[1], al[2], al[3], uTl + a2off[mi] + ks*32);
                    #pragma unroll
                    for (int ni = 0; ni < 4; ni++) {
                        mma16816(eacc[mi][ni], ah, &bh[ni*2]);
                        mma16816(eacc[mi][ni], ah, &bl[ni*2]);
                        mma16816(eacc[mi][ni], al, &bh[ni*2]);
                    }
                }
            }
        }
        if (c < 13) CPW0();
        __syncthreads();
        buf ^= 1;
    }

    // ===== stage 3: m = tanh((hn2[src]*ee) @ Wc^T + bc), scatter =====
    // Wc chunks stream into the W2 double buffers (free now).
    {
        int r = tid >> 1, cc = (tid & 1) * 16;
        // issue chunk 0 -> slot 0, chunk 1 -> slot 1
        #pragma unroll
        for (int kc = 0; kc < 2; kc++) {
            uint32_t sb = (uint32_t)kc * 10240;
            uint32_t dh0 = sb + (uint32_t)(r*SLD + cc)*2,  dh1 = sb + (uint32_t)(r*SLD + cc + 8)*2;
            size_t s = (size_t)r*128 + kc*32 + cc;
            CPA16(uW2h + dh0, Wch + s); CPA16(uW2h + dh1, Wch + s + 8);
            CPA16(uW2l + dh0, Wcl + s); CPA16(uW2l + dh1, Wcl + s + 8);
            CPC();
        }
    }

    float acc3[4][4][4];
    #pragma unroll
    for (int mi = 0; mi < 4; mi++)
        #pragma unroll
        for (int ni = 0; ni < 4; ni++)
            #pragma unroll
            for (int q = 0; q < 4; q++) acc3[mi][ni][q] = 0.f;

    #pragma unroll
    for (int kc = 0; kc < 4; kc++) {
        // owning warps write product chunk into sT
        if ((warp & 3) == kc) {
            #pragma unroll
            for (int mi = 0; mi < 4; mi++) {
                #pragma unroll
                for (int half = 0; half < 2; half++) {
                    int r = m0 + mi*16 + lrow + half*8;
                    const float* hrow = hn2 + (size_t)sidxs[r]*128;
                    #pragma unroll
                    for (int ni = 0; ni < 4; ni++) {
                        int col = ni*8 + lcol;
                        int gcol = kc*32 + col;
                        float2 hv = *(const float2*)(hrow + gcol);
                        float v0 = (eacc[mi][ni][half*2+0] + sb2[gcol])   * hv.x;
                        float v1 = (eacc[mi][ni][half*2+1] + sb2[gcol+1]) * hv.y;
                        uint32_t H, L;
                        pack2(v0, v1, H, L);
                        uint32_t doff = (uint32_t)(r*SLD + col)*2;
                        *(uint32_t*)(ds + doff) = H;
                        *(uint32_t*)(ds + 10240 + doff) = L;
                    }
                }
            }
        }
        if (kc < 3) CPW1(); else CPW0();
        __syncthreads();
        // MMA3 over K=32 with Wc chunk
        {
            uint32_t wb = (uint32_t)(kc & 1) * 10240;
            #pragma unroll
            for (int ks = 0; ks < 2; ks++) {
                uint32_t bh[8], bl[8];
                ldmx4(bh[0], bh[1], bh[2], bh[3], uW2h + wb + b2off0 + ks*32);
                ldmx4(bh[4], bh[5], bh[6], bh[7], uW2h + wb + b2off1 + ks*32);
                ldmx4(bl[0], bl[1], bl[2], bl[3], uW2l + wb + b2off0 + ks*32);
                ldmx4(bl[4], bl[5], bl[6], bl[7], uW2l + wb + b2off1 + ks*32);
                #pragma unroll
                for (int mi = 0; mi < 4; mi++) {
                    uint32_t ah[4], al[4];
                    ldmx4(ah[0], ah[1], ah[2], ah[3], uTh + a2off[mi] + ks*32);
                    ldmx4(al[0], al[1], al[2], al[3], uTl + a2off[mi] + ks*32);
                    #pragma unroll
                    for (int ni = 0; ni < 4; ni++) {
                        mma16816(acc3[mi][ni], ah, &bh[ni*2]);
                        mma16816(acc3[mi][ni], ah, &bl[ni*2]);
                        mma16816(acc3[mi][ni], al, &bh[ni*2]);
                    }
                }
            }
        }
        __syncthreads();
        if (kc + 2 <= 3) {
            int r = tid >> 1, cc = (tid & 1) * 16;
            uint32_t sb = (uint32_t)(kc & 1) * 10240;
            uint32_t dh0 = sb + (uint32_t)(r*SLD + cc)*2,  dh1 = sb + (uint32_t)(r*SLD + cc + 8)*2;
            size_t s = (size_t)r*128 + (kc+2)*32 + cc;
            CPA16(uW2h + dh0, Wch + s); CPA16(uW2h + dh1, Wch + s + 8);
            CPA16(uW2l + dh0, Wcl + s); CPA16(uW2l + dh1, Wcl + s + 8);
            CPC();
        }
    }

    // final epilogue: h[dst] += tanh(acc3 + bc)
    #pragma unroll
    for (int mi = 0; mi < 4; mi++) {
        #pragma unroll
        for (int half = 0; half < 2; half++) {
            int rl = m0 + mi*16 + lrow + half*8;
            int row = bx*128 + rl;
            if (row < E) {
                float* Hr = h + (size_t)sdsts[rl] * 128;
                #pragma unroll
                for (int ni = 0; ni < 4; ni++) {
                    int col = n0 + ni*8 + lcol;
                    atomicAdd(Hr + col,     tanhf(acc3[mi][ni][half*2+0] + sbc[col]));
                    atomicAdd(Hr + col + 1, tanhf(acc3[mi][ni][half*2+1] + sbc[col+1]));
                }
            }
        }
    }
}

// ============ generic pipelined GEMM (node MLP / readout) ============
template<int EPI>   // 0 store, 1 relu store
__global__ void __launch_bounds__(256)
gemm_mma(const float* __restrict__ Af, int lda, int Kloop,
         const __nv_bfloat16* __restrict__ Bh, const __nv_bfloat16* __restrict__ Bl, int Kpad,
         const float* __restrict__ bias, float* __restrict__ C, int M) {
    extern __shared__ char ds[];
    __shared__ float sbias[128];
    int tid = threadIdx.x, lane = tid & 31, warp = tid >> 5;
    if (tid < 128) sbias[tid] = bias[tid];

    uint32_t b0 = smem_u32(ds);
    uint32_t uAh = b0, uAl = b0 + 2*BUFB, uBh = b0 + 4*BUFB, uBl = b0 + 6*BUFB;

    const float *p1[4];
    #pragma unroll
    for (int i = 0; i < 4; i++) {
        int r = blockIdx.x*128 + i*32 + (tid >> 3);
        p1[i] = Af + (size_t)min(r, M-1) * lda;
    }
    int akoff = (tid & 7) << 2;
    int ckoff = (tid & 3) << 3;
    int crow  = tid >> 2;
    uint32_t cdst0 = ((uint32_t)crow * SLD + ckoff) * 2;
    uint32_t cdst1 = ((uint32_t)(crow + 64) * SLD + ckoff) * 2;
    uint32_t asts[4];
    #pragma unroll
    for (int i = 0; i < 4; i++) asts[i] = ((uint32_t)(i*32 + (tid >> 3)) * SLD + akoff) * 2;

    int m0 = (warp >> 2) * 64, n0 = (warp & 3) * 32;
    int arow = lane & 15, acol = (lane >> 4) << 3;
    int brow = (lane & 7) + ((lane >> 1) & 8), bcol = lane & 8;
    uint32_t aoff[4];
    #pragma unroll
    for (int mi = 0; mi < 4; mi++) aoff[mi] = ((m0 + mi*16 + arow)*SLD + acol) * 2;
    uint32_t boff0 = ((n0 + brow)*SLD + bcol) * 2;
    uint32_t boff1 = ((n0 + 16 + brow)*SLD + bcol) * 2;

    float acc[4][4][4];
    #pragma unroll
    for (int mi = 0; mi < 4; mi++)
        #pragma unroll
        for (int ni = 0; ni < 4; ni++)
            #pragma unroll
            for (int q = 0; q < 4; q++) acc[mi][ni][q] = 0.f;

    uint2 rAh[4], rAl[4];
    int nch = Kloop >> 5;

    {
        CPA16(uBh + cdst0, Bh + (size_t)crow * Kpad + ckoff);
        CPA16(uBh + cdst1, Bh + (size_t)(crow + 64) * Kpad + ckoff);
        CPA16(uBl + cdst0, Bl + (size_t)crow * Kpad + ckoff);
        CPA16(uBl + cdst1, Bl + (size_t)(crow + 64) * Kpad + ckoff);
        CPC();
        #pragma unroll
        for (int i = 0; i < 4; i++) {
            float4 f = *(const float4*)(p1[i] + akoff);
            pack2(f.x, f.y, rAh[i].x, rAl[i].x);
            pack2(f.z, f.w, rAh[i].y, rAl[i].y);
        }
        #pragma unroll
        for (int i = 0; i < 4; i++) {
            *(uint2*)(ds + asts[i]) = rAh[i];
            *(uint2*)(ds + 2*BUFB + asts[i]) = rAl[i];
        }
        CPW0();
        __syncthreads();
    }

    int buf = 0;
    for (int c = 0; c < nch; c++) {
        int k1 = (c + 1) << 5;
        bool more = (c + 1) < nch;
        if (more) {
            uint32_t bb = (uint32_t)(buf ^ 1) * BUFB;
            CPA16(uBh + bb + cdst0, Bh + (size_t)crow * Kpad + k1 + ckoff);
            CPA16(uBh + bb + cdst1, Bh + (size_t)(crow + 64) * Kpad + k1 + ckoff);
            CPA16(uBl + bb + cdst0, Bl + (size_t)crow * Kpad + k1 + ckoff);
            CPA16(uBl + bb + cdst1, Bl + (size_t)(crow + 64) * Kpad + k1 + ckoff);
            CPC();
            #pragma unroll
            for (int i = 0; i < 4; i++) {
                float4 f = *(const float4*)(p1[i] + k1 + akoff);
                pack2(f.x, f.y, rAh[i].x, rAl[i].x);
                pack2(f.z, f.w, rAh[i].y, rAl[i].y);
            }
        }
        {
            uint32_t bb = (uint32_t)buf * BUFB;
            #pragma unroll
            for (int ks = 0; ks < 2; ks++) {
                uint32_t bh[8], bl[8];
                ldmx4(bh[0], bh[1], bh[2], bh[3], uBh + bb + boff0 + ks*32);
                ldmx4(bh[4], bh[5], bh[6], bh[7], uBh + bb + boff1 + ks*32);
                ldmx4(bl[0], bl[1], bl[2], bl[3], uBl + bb + boff0 + ks*32);
                ldmx4(bl[4], bl[5], bl[6], bl[7], uBl + bb + boff1 + ks*32);
                #pragma unroll
                for (int mi = 0; mi < 4; mi++) {
                    uint32_t ah[4], al[4];
                    ldmx4(ah[0], ah[1], ah[2], ah[3], uAh + bb + aoff[mi] + ks*32);
                    ldmx4(al[0], al[1], al[2], al[3], uAl + bb + aoff[mi] + ks*32);
                    #pragma unroll
                    for (int ni = 0; ni < 4; ni++) {
                        mma16816(acc[mi][ni], ah, &bh[ni*2]);
                        mma16816(acc[mi][ni], ah, &bl[ni*2]);
                        mma16816(acc[mi][ni], al, &bh[ni*2]);
                    }
                }
            }
        }
        if (more) {
            uint32_t bb = (uint32_t)(buf ^ 1) * BUFB;
            #pragma unroll
            for (int i = 0; i < 4; i++) {
                *(uint2*)(ds + bb + asts[i]) = rAh[i];
                *(uint2*)(ds + 2*BUFB + bb + asts[i]) = rAl[i];
            }
            CPW0();
            __syncthreads();
            buf ^= 1;
        }
    }

    int rowb = blockIdx.x*128 + m0;
    #pragma unroll
    for (int mi = 0; mi < 4; mi++) {
        #pragma unroll
        for (int half = 0; half < 2; half++) {
            int row = rowb + mi*16 + (lane >> 2) + half*8;
            if (row < M) {
                size_t cb = (size_t)row * 128;
                #pragma unroll
                for (int ni = 0; ni < 4; ni++) {
                    int col = n0 + ni*8 + (lane & 3)*2;
                    float v0 = acc[mi][ni][half*2+0] + sbias[col];
                    float v1 = acc[mi][ni][half*2+1] + sbias[col+1];
                    if (EPI == 1) { v0 = fmaxf(v0, 0.f); v1 = fmaxf(v1, 0.f); }
                    float2 o = make_float2(v0, v1);
                    *(float2*)(C + cb + col) = o;
                }
            }
        }
    }
}

__global__ void readout2_k(const float* __restrict__ rr, const float* __restrict__ Wr2,
                           const float* __restrict__ br2, const int* __restrict__ gid,
                           float* __restrict__ out, int N) {
    __shared__ float w[128];
    int tid = threadIdx.x;
    if (tid < 128) w[tid] = Wr2[tid];
    __syncthreads();
    int warp = tid >> 5, lane = tid & 31;
    int n = blockIdx.x*4 + warp;
    if (n >= N) return;
    const float* hr = rr + (size_t)n * 128;
    float s = 0.f;
    #pragma unroll
    for (int i = 0; i < 4; i++) s = fmaf(hr[lane + i*32], w[lane + i*32], s);
    #pragma unroll
    for (int o = 16; o > 0; o >>= 1) s += __shfl_down_sync(0xffffffffu, s, o);
    if (lane == 0) atomicAdd(&out[gid[n]], s + br2[0]);
}

extern "C" void kernel_launch(void* const* d_in, const int* in_sizes, int n_in,
                              void* d_out, int out_size) {
    const int*   Z     = (const int*)  d_in[0];
    const int*   etype = (const int*)  d_in[1];
    const float* dist  = (const float*)d_in[2];
    const int*   src   = (const int*)  d_in[3];
    const int*   dst   = (const int*)  d_in[4];
    const int*   gid   = (const int*)  d_in[5];
    const float* node_emb = (const float*)d_in[6];
    const float* edge_emb = (const float*)d_in[7];
    const float* Wn1 = (const float*)d_in[8];
    const float* bn1 = (const float*)d_in[9];
    const float* Wn2 = (const float*)d_in[10];
    const float* bn2 = (const float*)d_in[11];
    const float* We1 = (const float*)d_in[12];
    const float* be1 = (const float*)d_in[13];
    const float* We2 = (const float*)d_in[14];
    const float* be2 = (const float*)d_in[15];
    const float* Wc  = (const float*)d_in[16];
    const float* bc  = (const float*)d_in[17];
    const float* Wr1 = (const float*)d_in[18];
    const float* br1 = (const float*)d_in[19];
    const float* Wr2 = (const float*)d_in[20];
    const float* br2 = (const float*)d_in[21];

    int N = in_sizes[0], E = in_sizes[1], G = out_size;
    float* out = (float*)d_out;

    cudaFuncSetAttribute((const void*)fused_layer, cudaFuncAttributeMaxDynamicSharedMemorySize, DSMEM3);
    cudaFuncSetAttribute((const void*)gemm_mma<1>, cudaFuncAttributeMaxDynamicSharedMemorySize, DSMEM2);
    cudaFuncSetAttribute((const void*)gemm_mma<0>, cudaFuncAttributeMaxDynamicSharedMemorySize, DSMEM2);

    void* p;
    float *h, *tmp, *P;
    __nv_bfloat16 *W1h,*W1l,*We2h,*We2l,*Wn1h,*Wn1l,*Wn2h,*Wn2l,*Wch,*Wcl,*Wr1h,*Wr1l;
    cudaGetSymbolAddress(&p, g_h);   h   = (float*)p;
    cudaGetSymbolAddress(&p, g_tmp); tmp = (float*)p;
    cudaGetSymbolAddress(&p, g_P);   P   = (float*)p;
    cudaGetSymbolAddress(&p, g_W1h);  W1h  = (__nv_bfloat16*)p;
    cudaGetSymbolAddress(&p, g_W1l);  W1l  = (__nv_bfloat16*)p;
    cudaGetSymbolAddress(&p, g_We2h); We2h = (__nv_bfloat16*)p;
    cudaGetSymbolAddress(&p, g_We2l); We2l = (__nv_bfloat16*)p;
    cudaGetSymbolAddress(&p, g_Wn1h); Wn1h = (__nv_bfloat16*)p;
    cudaGetSymbolAddress(&p, g_Wn1l); Wn1l = (__nv_bfloat16*)p;
    cudaGetSymbolAddress(&p, g_Wn2h); Wn2h = (__nv_bfloat16*)p;
    cudaGetSymbolAddress(&p, g_Wn2l); Wn2l = (__nv_bfloat16*)p;
    cudaGetSymbolAddress(&p, g_Wch);  Wch  = (__nv_bfloat16*)p;
    cudaGetSymbolAddress(&p, g_Wcl);  Wcl  = (__nv_bfloat16*)p;
    cudaGetSymbolAddress(&p, g_Wr1h); Wr1h = (__nv_bfloat16*)p;
    cudaGetSymbolAddress(&p, g_Wr1l); Wr1l = (__nv_bfloat16*)p;

    zero_hist_k<<<(2*NBUCK + 255)/256, 256>>>();
    hist_k<<<(E + 255)/256, 256>>>(dist, E);
    scan512_k<<<1, NBUCK>>>();
    scatter_perm_k<<<(E + 255)/256, 256>>>(dist, E);

    int gE = (E + 127)/128, gN = (N + 127)/128;
    init_h_k<<<(N*128 + 255)/256, 256>>>(Z, node_emb, h, N);
    for (int i = 0; i < 3; i++) {
        split_pad_k<<<(512*384 + 255)/256, 256>>>(We1 + (size_t)i*428*428, W1h + (size_t)i*512*384, W1l + (size_t)i*512*384, 428, 300, 428, 128, 384, 512*384);
        split_pad_k<<<(128*448 + 255)/256, 256>>>(We2 + (size_t)i*128*428, We2h + (size_t)i*128*448, We2l + (size_t)i*128*448, 128, 428, 428, 0, 448, 128*448);
        split_pad_k<<<(128*128 + 255)/256, 256>>>(Wn1 + (size_t)i*128*128, Wn1h + (size_t)i*128*128, Wn1l + (size_t)i*128*128, 128, 128, 128, 0, 128, 128*128);
        split_pad_k<<<(128*128 + 255)/256, 256>>>(Wn2 + (size_t)i*128*128, Wn2h + (size_t)i*128*128, Wn2l + (size_t)i*128*128, 128, 128, 128, 0, 128, 128*128);
        split_pad_k<<<(128*128 + 255)/256, 256>>>(Wc  + (size_t)i*128*128, Wch  + (size_t)i*128*128, Wcl  + (size_t)i*128*128, 128, 128, 128, 0, 128, 128*128);
    }
    split_pad_k<<<(128*128 + 255)/256, 256>>>(Wr1, Wr1h, Wr1l, 128, 128, 128, 0, 128, 128*128);
    p_kernel<<<dim3(400, 3), 448>>>(edge_emb, We1, be1, P);
    rbf_klo_k<<<gE, 128>>>(dist, E);
    rbf_split_k<<<gE, 128>>>(dist, E);

    for (int i = 0; i < 3; i++) {
        // node MLP first (hn2 -> tmp)
        gemm_mma<1><<<gN, 256, DSMEM2>>>(h, 128, 128,
            Wn1h + (size_t)i*128*128, Wn1l + (size_t)i*128*128, 128,
            bn1 + i*128, tmp, N);
        gemm_mma<0><<<gN, 256, DSMEM2>>>(tmp, 128, 128,
            Wn2h + (size_t)i*128*128, Wn2l + (size_t)i*128*128, 128,
            bn2 + i*128, tmp, N);
        // mega fused: t -> ee -> mix -> scatter into h
        fused_layer<<<gE, 256, DSMEM3>>>(W1h + (size_t)i*512*384, W1l + (size_t)i*512*384,
                                         We2h + (size_t)i*128*448, We2l + (size_t)i*128*448,
                                         Wch + (size_t)i*128*128, Wcl + (size_t)i*128*128,
                                         P + (size_t)i*400*428, be2 + i*128, bc + i*128,
                                         etype, src, dst, tmp, h, E);
    }

    gemm_mma<1><<<gN, 256, DSMEM2>>>(h, 128, 128, Wr1h, Wr1l, 128, br1, tmp, N);
    zero_f_k<<<(G + 255)/256, 256>>>(out, G);
    readout2_k<<<(N + 3)/4, 128>>>(tmp, Wr2, br2, gid, out, N);
}

// round 8
// speedup vs baseline: 1.2373x; 1.2373x over previous
#include <cuda_runtime.h>
#include <cuda_bf16.h>
#include <math.h>
#include <stdint.h>

#define N_RBF 300
#define NBUCK 512
#define N_MAXN 100352
#define E_MAXE 400384
#define GE_MAX 3128
#define RBF_STEP (30.0f/299.0f)
#define RBF_INV  (299.0f/30.0f)
#define SLD 40
#define BUFB 10240
#define DSMEM2 81920
#define DSMEM3 116736

__device__ float g_h  [(size_t)N_MAXN*128];
__device__ float g_ee [2*(size_t)E_MAXE*128];
__device__ float g_tmp[(size_t)N_MAXN*128];
__device__ float g_P  [3*400*428];
__device__ int   g_perm[E_MAXE];
__device__ int   g_hist[2*NBUCK];
__device__ int   g_klo [GE_MAX];
__device__ __nv_bfloat16 g_rAh[(size_t)E_MAXE*64],  g_rAl[(size_t)E_MAXE*64];
__device__ __nv_bfloat16 g_W1h[3*512*384],  g_W1l[3*512*384];
__device__ __nv_bfloat16 g_We2h[3*128*448], g_We2l[3*128*448];
__device__ __nv_bfloat16 g_Wn1h[3*128*128], g_Wn1l[3*128*128];
__device__ __nv_bfloat16 g_Wn2h[3*128*128], g_Wn2l[3*128*128];
__device__ __nv_bfloat16 g_Wch [3*128*128], g_Wcl [3*128*128];
__device__ __nv_bfloat16 g_Wr1h[128*128],   g_Wr1l[128*128];

__device__ __forceinline__ uint32_t smem_u32(const void* p) {
    uint32_t a;
    asm("{ .reg .u64 t; cvta.to.shared.u64 t, %1; cvt.u32.u64 %0, t; }" : "=r"(a) : "l"(p));
    return a;
}
__device__ __forceinline__ void ldmx4(uint32_t& r0, uint32_t& r1, uint32_t& r2, uint32_t& r3, uint32_t a) {
    asm volatile("ldmatrix.sync.aligned.m8n8.x4.shared.b16 {%0,%1,%2,%3}, [%4];"
        : "=r"(r0), "=r"(r1), "=r"(r2), "=r"(r3) : "r"(a));
}
__device__ __forceinline__ void mma16816(float* c, const uint32_t* a, const uint32_t* b) {
    asm volatile("mma.sync.aligned.m16n8k16.row.col.f32.bf16.bf16.f32 "
        "{%0,%1,%2,%3},{%4,%5,%6,%7},{%8,%9},{%0,%1,%2,%3};"
        : "+f"(c[0]), "+f"(c[1]), "+f"(c[2]), "+f"(c[3])
        : "r"(a[0]), "r"(a[1]), "r"(a[2]), "r"(a[3]), "r"(b[0]), "r"(b[1]));
}
__device__ __forceinline__ void pack2(float a, float b, uint32_t& h, uint32_t& l) {
    __nv_bfloat162 hb = __floats2bfloat162_rn(a, b);
    __nv_bfloat162 lb = __floats2bfloat162_rn(a - __low2float(hb), b - __high2float(hb));
    h = *reinterpret_cast<uint32_t*>(&hb);
    l = *reinterpret_cast<uint32_t*>(&lb);
}
#define CPA16(dst, src) asm volatile("cp.async.cg.shared.global [%0], [%1], 16;" :: "r"(dst), "l"(src))
#define CPC()  asm volatile("cp.async.commit_group;" ::: "memory")
#define CPW0() asm volatile("cp.async.wait_group 0;" ::: "memory")

__global__ void zero_hist_k() { int i = blockIdx.x*256 + threadIdx.x; if (i < 2*NBUCK) g_hist[i] = 0; }
__global__ void zero_f_k(float* p, int n) { int i = blockIdx.x*256 + threadIdx.x; if (i < n) p[i] = 0.f; }
__device__ __forceinline__ int bucket_of(float d) {
    int b = (int)(d * (512.0f/30.0f));
    return min(max(b, 0), NBUCK-1);
}
__global__ void hist_k(const float* __restrict__ dist, int E) {
    int e = blockIdx.x*256 + threadIdx.x;
    if (e < E) atomicAdd(&g_hist[bucket_of(dist[e])], 1);
}
__global__ void scan512_k() {
    __shared__ int s[NBUCK];
    int tid = threadIdx.x;
    int v0 = g_hist[tid];
    s[tid] = v0; __syncthreads();
    for (int off = 1; off < NBUCK; off <<= 1) {
        int v = 0;
        if (tid >= off) v = s[tid - off];
        __syncthreads(); s[tid] += v; __syncthreads();
    }
    g_hist[NBUCK + tid] = s[tid] - v0;
}
__global__ void scatter_perm_k(const float* __restrict__ dist, int E) {
    int e = blockIdx.x*256 + threadIdx.x;
    if (e < E) {
        int pos = atomicAdd(&g_hist[NBUCK + bucket_of(dist[e])], 1);
        g_perm[pos] = e;
    }
}
__global__ void init_h_k(const int* __restrict__ Z, const float* __restrict__ ne,
                         float* __restrict__ h, int N) {
    int idx = blockIdx.x*256 + threadIdx.x;
    if (idx < N*128) h[idx] = ne[Z[idx >> 7]*128 + (idx & 127)];
}
__global__ void split_pad_k(const float* __restrict__ src, __nv_bfloat16* __restrict__ dh,
                            __nv_bfloat16* __restrict__ dl,
                            int R, int Ks, int ld, int off, int Kpad, int tot) {
    int idx = blockIdx.x*256 + threadIdx.x;
    if (idx < tot) {
        int r = idx / Kpad, k = idx % Kpad;
        float v = (r < R && k < Ks) ? src[(size_t)r*ld + off + k] : 0.f;
        __nv_bfloat16 h = __float2bfloat16(v);
        dh[idx] = h;
        dl[idx] = __float2bfloat16(v - __bfloat162float(h));
    }
}
__global__ void p_kernel(const float* __restrict__ edge_emb, const float* __restrict__ We1,
                         const float* __restrict__ be1, float* __restrict__ P) {
    int ty = blockIdx.x, layer = blockIdx.y, j = threadIdx.x;
    __shared__ float em[128];
    if (j < 128) em[j] = edge_emb[ty*128 + j];
    __syncthreads();
    if (j < 428) {
        const float* wrow = We1 + ((size_t)layer*428 + j)*428;
        float acc = be1[layer*428 + j];
        #pragma unroll 8
        for (int k = 0; k < 128; k++) acc = fmaf(em[k], wrow[k], acc);
        P[((size_t)layer*400 + ty)*428 + j] = acc;
    }
}
__global__ void rbf_klo_k(const float* __restrict__ dist, int E) {
    __shared__ float s[128];
    int tid = threadIdx.x, gr = blockIdx.x*128 + tid;
    s[tid] = dist[g_perm[min(gr, E-1)]];
    __syncthreads();
    for (int o = 64; o > 0; o >>= 1) {
        if (tid < o) s[tid] = fminf(s[tid], s[tid + o]);
        __syncthreads();
    }
    if (tid == 0) {
        int k = (int)floorf((s[0] - 2.0f) * RBF_INV);
        if (k < 0) k = 0;
        g_klo[blockIdx.x] = k & ~7;
    }
}
__global__ void rbf_split_k(const float* __restrict__ dist, int E) {
    int tid = threadIdx.x, gr = blockIdx.x*128 + tid;
    float d = dist[g_perm[min(gr, E-1)]];
    int k0 = g_klo[blockIdx.x];
    float vals[64];
    #pragma unroll
    for (int i = 0; i < 64; i++) vals[i] = 0.f;
    int icen = (int)(d * RBF_INV) - k0;
    int ilo = max(0, icen - 22);
    int ihi = min(min(63, icen + 22), 299 - k0);
    for (int i = ilo; i <= ihi; i++) {
        float x = d - (float)(k0 + i) * RBF_STEP;
        vals[i] = __expf(-RBF_INV * x * x);
    }
    size_t base = (size_t)gr * 64;
    #pragma unroll
    for (int i = 0; i < 64; i += 8) {
        uint4 H, L;
        pack2(vals[i+0], vals[i+1], H.x, L.x);
        pack2(vals[i+2], vals[i+3], H.y, L.y);
        pack2(vals[i+4], vals[i+5], H.z, L.z);
        pack2(vals[i+6], vals[i+7], H.w, L.w);
        *(uint4*)(g_rAh + base + i) = H;
        *(uint4*)(g_rAl + base + i) = L;
    }
}

// ============ fused t -> ee kernel (round-6 proven) ============
__global__ void __launch_bounds__(256)
fused_t_ee(const __nv_bfloat16* __restrict__ W1h, const __nv_bfloat16* __restrict__ W1l,
           const __nv_bfloat16* __restrict__ W2h, const __nv_bfloat16* __restrict__ W2l,
           const float* __restrict__ P, const float* __restrict__ be2,
           const int* __restrict__ etype, float* __restrict__ ee, int E) {
    extern __shared__ char ds[];
    __shared__ int sety[128];
    __shared__ float sbias[128];
    int tid = threadIdx.x, lane = tid & 31, warp = tid >> 5, bx = blockIdx.x;
    int klo = g_klo[bx];
    if (tid < 128) {
        sety[tid] = etype[g_perm[min(bx*128 + tid, E-1)]];
        sbias[tid] = be2[tid];
    }
    uint32_t b0 = smem_u32(ds);
    uint32_t uTh = b0,          uTl = b0 + 10240;
    uint32_t uAh = b0 + 20480,  uAl = b0 + 38912;
    uint32_t uW1h = b0 + 57344, uW1l = b0 + 66560;
    uint32_t uW2h = b0 + 75776, uW2l = b0 + 96256;

    {
        int row = tid >> 2, k = (tid & 3) << 3;
        #pragma unroll
        for (int i = 0; i < 2; i++)
        #pragma unroll
        for (int j = 0; j < 2; j++) {
            int r = row + i*64, kk = k + j*32;
            uint32_t d = (uint32_t)(r*72 + kk)*2;
            size_t s = (size_t)(bx*128 + r)*64 + kk;
            CPA16(uAh + d, g_rAh + s);
            CPA16(uAl + d, g_rAl + s);
        }
    }
    {
        int r1 = tid >> 3, k1 = (tid & 7) << 3;
        uint32_t d1 = (uint32_t)(r1*72 + k1)*2;
        size_t s1 = (size_t)r1*384 + klo + k1;
        CPA16(uW1h + d1, W1h + s1);
        CPA16(uW1l + d1, W1l + s1);
        int r2 = tid >> 2, k2 = (tid & 3) << 3;
        uint32_t d2a = (uint32_t)(r2*SLD + k2)*2, d2b = (uint32_t)((r2+64)*SLD + k2)*2;
        size_t s2a = (size_t)r2*448 + k2, s2b = (size_t)(r2+64)*448 + k2;
        CPA16(uW2h + d2a, W2h + s2a); CPA16(uW2h + d2b, W2h + s2b);
        CPA16(uW2l + d2a, W2l + s2a); CPA16(uW2l + d2b, W2l + s2b);
    }
    CPC(); CPW0();
    __syncthreads();

    int arow = lane & 15, acol = (lane >> 4) << 3;
    int brow = (lane & 7) + ((lane >> 1) & 8), bcol = lane & 8;
    uint32_t a1off = (uint32_t)((warp*16 + arow)*72 + acol)*2;
    uint32_t b1off0 = (uint32_t)(brow*72 + bcol)*2;
    uint32_t b1off1 = (uint32_t)((16 + brow)*72 + bcol)*2;
    int m0 = (warp >> 2)*64, n0 = (warp & 3)*32;
    uint32_t a2off[4];
    #pragma unroll
    for (int mi = 0; mi < 4; mi++) a2off[mi] = (uint32_t)((m0 + mi*16 + arow)*SLD + acol)*2;
    uint32_t b2off0 = (uint32_t)((n0 + brow)*SLD + bcol)*2;
    uint32_t b2off1 = (uint32_t)((n0 + 16 + brow)*SLD + bcol)*2;
    int lrow = lane >> 2, lcol = (lane & 3)*2;

    float eacc[4][4][4];
    #pragma unroll
    for (int mi = 0; mi < 4; mi++)
        #pragma unroll
        for (int ni = 0; ni < 4; ni++)
            #pragma unroll
            for (int q = 0; q < 4; q++) eacc[mi][ni][q] = 0.f;

    int buf = 0;
    for (int c = 0; c < 14; c++) {
        if (c < 13) {
            uint32_t cb = (uint32_t)(buf ^ 1);
            int r1 = tid >> 3, k1 = (tid & 7) << 3;
            uint32_t d1 = cb*4608 + (uint32_t)(r1*72 + k1)*2;
            size_t s1 = (size_t)((c+1)*32 + r1)*384 + klo + k1;
            CPA16(uW1h + d1, W1h + s1);
            CPA16(uW1l + d1, W1l + s1);
            int r2 = tid >> 2, k2 = (tid & 3) << 3;
            uint32_t d2a = cb*10240 + (uint32_t)(r2*SLD + k2)*2;
            uint32_t d2b = cb*10240 + (uint32_t)((r2+64)*SLD + k2)*2;
            size_t s2a = (size_t)r2*448 + (c+1)*32 + k2;
            size_t s2b = (size_t)(r2+64)*448 + (c+1)*32 + k2;
            CPA16(uW2h + d2a, W2h + s2a); CPA16(uW2h + d2b, W2h + s2b);
            CPA16(uW2l + d2a, W2l + s2a); CPA16(uW2l + d2b, W2l + s2b);
            CPC();
        }
        float acc1[4][4];
        #pragma unroll
        for (int ni = 0; ni < 4; ni++)
            #pragma unroll
            for (int q = 0; q < 4; q++) acc1[ni][q] = 0.f;
        {
            uint32_t w1b = (uint32_t)buf * 4608;
            #pragma unroll
            for (int ks = 0; ks < 4; ks++) {
                uint32_t ah[4], al[4], bh[8], bl[8];
                ldmx4(ah[0], ah[1], ah[2], ah[3], uAh + a1off + ks*32);
                ldmx4(al[0], al[1], al[2], al[3], uAl + a1off + ks*32);
                ldmx4(bh[0], bh[1], bh[2], bh[3], uW1h + w1b + b1off0 + ks*32);
                ldmx4(bh[4], bh[5], bh[6], bh[7], uW1h + w1b + b1off1 + ks*32);
                ldmx4(bl[0], bl[1], bl[2], bl[3], uW1l + w1b + b1off0 + ks*32);
                ldmx4(bl[4], bl[5], bl[6], bl[7], uW1l + w1b + b1off1 + ks*32);
                #pragma unroll
                for (int ni = 0; ni < 4; ni++) {
                    mma16816(acc1[ni], ah, &bh[ni*2]);
                    mma16816(acc1[ni], ah, &bl[ni*2]);
                    mma16816(acc1[ni], al, &bh[ni*2]);
                }
            }
        }
        {
            int gcb = c*32;
            #pragma unroll
            for (int half = 0; half < 2; half++) {
                int r = warp*16 + lrow + half*8;
                const float* Pr = P + (size_t)sety[r]*428;
                #pragma unroll
                for (int ni = 0; ni < 4; ni++) {
                    int col = ni*8 + lcol;
                    int gcol = gcb + col;
                    float v0 = 0.f, v1 = 0.f;
                    if (gcol < 428) {
                        float2 pv = *(const float2*)(Pr + gcol);
                        v0 = fmaxf(acc1[ni][half*2+0] + pv.x, 0.f);
                        v1 = fmaxf(acc1[ni][half*2+1] + pv.y, 0.f);
                    }
                    uint32_t H, L;
                    pack2(v0, v1, H, L);
                    uint32_t doff = (uint32_t)(r*SLD + col)*2;
                    *(uint32_t*)(ds + doff) = H;
                    *(uint32_t*)(ds + 10240 + doff) = L;
                }
            }
        }
        __syncthreads();
        {
            uint32_t w2b = (uint32_t)buf * 10240;
            #pragma unroll
            for (int ks = 0; ks < 2; ks++) {
                uint32_t bh[8], bl[8];
                ldmx4(bh[0], bh[1], bh[2], bh[3], uW2h + w2b + b2off0 + ks*32);
                ldmx4(bh[4], bh[5], bh[6], bh[7], uW2h + w2b + b2off1 + ks*32);
                ldmx4(bl[0], bl[1], bl[2], bl[3], uW2l + w2b + b2off0 + ks*32);
                ldmx4(bl[4], bl[5], bl[6], bl[7], uW2l + w2b + b2off1 + ks*32);
                #pragma unroll
                for (int mi = 0; mi < 4; mi++) {
                    uint32_t ah[4], al[4];
                    ldmx4(ah[0], ah[1], ah[2], ah[3], uTh + a2off[mi] + ks*32);
                    ldmx4(al[0], al[1], al[2], al[3], uTl + a2off[mi] + ks*32);
                    #pragma unroll
                    for (int ni = 0; ni < 4; ni++) {
                        mma16816(eacc[mi][ni], ah, &bh[ni*2]);
                        mma16816(eacc[mi][ni], ah, &bl[ni*2]);
                        mma16816(eacc[mi][ni], al, &bh[ni*2]);
                    }
                }
            }
        }
        if (c < 13) CPW0();
        __syncthreads();
        buf ^= 1;
    }

    int rowb = bx*128 + m0;
    #pragma unroll
    for (int mi = 0; mi < 4; mi++) {
        #pragma unroll
        for (int half = 0; half < 2; half++) {
            int row = rowb + mi*16 + lrow + half*8;
            if (row < E) {
                size_t cb = (size_t)row * 128;
                #pragma unroll
                for (int ni = 0; ni < 4; ni++) {
                    int col = n0 + ni*8 + lcol;
                    float2 o;
                    o.x = eacc[mi][ni][half*2+0] + sbias[col];
                    o.y = eacc[mi][ni][half*2+1] + sbias[col+1];
                    *(float2*)(ee + cb + col) = o;
                }
            }
        }
    }
}

// ============ generic pipelined GEMM ============
// EPI: 0 store, 1 relu store, 3 tanh + atomicAdd scatter to Hout[sidx[perm[row]]]
// AMODE: 0 fp32 rows direct; 2 product Af[gidx[perm[row]]]*A2[row]
template<int EPI, int AMODE>
__global__ void __launch_bounds__(256)
gemm_mma(const float* __restrict__ Af, const float* __restrict__ A2,
         int lda, int Kloop,
         const __nv_bfloat16* __restrict__ Bh, const __nv_bfloat16* __restrict__ Bl, int Kpad,
         const float* __restrict__ bias, float* __restrict__ C, int M,
         const int* __restrict__ gidx, const int* __restrict__ sidx, float* __restrict__ Hout) {
    extern __shared__ char ds[];
    __shared__ float sbias[128];
    int tid = threadIdx.x, lane = tid & 31, warp = tid >> 5;
    if (tid < 128) sbias[tid] = bias[tid];

    uint32_t b0 = smem_u32(ds);
    uint32_t uAh = b0, uAl = b0 + 2*BUFB, uBh = b0 + 4*BUFB, uBl = b0 + 6*BUFB;

    const float *p1[4], *p2[4];
    if (AMODE == 0) {
        #pragma unroll
        for (int i = 0; i < 4; i++) {
            int r = blockIdx.x*128 + i*32 + (tid >> 3);
            p1[i] = Af + (size_t)min(r, M-1) * lda;
        }
    } else {
        #pragma unroll
        for (int i = 0; i < 4; i++) {
            int r = blockIdx.x*128 + i*32 + (tid >> 3);
            int rc = min(r, M-1);
            p1[i] = Af + (size_t)gidx[g_perm[rc]] * 128;
            p2[i] = A2 + (size_t)rc * 128;
        }
    }
    int akoff = (tid & 7) << 2;
    int ckoff = (tid & 3) << 3;
    int crow  = tid >> 2;
    uint32_t cdst0 = ((uint32_t)crow * SLD + ckoff) * 2;
    uint32_t cdst1 = ((uint32_t)(crow + 64) * SLD + ckoff) * 2;
    uint32_t asts[4];
    #pragma unroll
    for (int i = 0; i < 4; i++) asts[i] = ((uint32_t)(i*32 + (tid >> 3)) * SLD + akoff) * 2;

    int m0 = (warp >> 2) * 64, n0 = (warp & 3) * 32;
    int arow = lane & 15, acol = (lane >> 4) << 3;
    int brow = (lane & 7) + ((lane >> 1) & 8), bcol = lane & 8;
    uint32_t aoff[4];
    #pragma unroll
    for (int mi = 0; mi < 4; mi++) aoff[mi] = ((m0 + mi*16 + arow)*SLD + acol) * 2;
    uint32_t boff0 = ((n0 + brow)*SLD + bcol) * 2;
    uint32_t boff1 = ((n0 + 16 + brow)*SLD + bcol) * 2;

    float acc[4][4][4];
    #pragma unroll
    for (int mi = 0; mi < 4; mi++)
        #pragma unroll
        for (int ni = 0; ni < 4; ni++)
            #pragma unroll
            for (int q = 0; q < 4; q++) acc[mi][ni][q] = 0.f;

    uint2 rAh[4], rAl[4];
    int nch = Kloop >> 5;

    {
        CPA16(uBh + cdst0, Bh + (size_t)crow * Kpad + ckoff);
        CPA16(uBh + cdst1, Bh + (size_t)(crow + 64) * Kpad + ckoff);
        CPA16(uBl + cdst0, Bl + (size_t)crow * Kpad + ckoff);
        CPA16(uBl + cdst1, Bl + (size_t)(crow + 64) * Kpad + ckoff);
        CPC();
        #pragma unroll
        for (int i = 0; i < 4; i++) {
            float4 f;
            if (AMODE == 0) f = *(const float4*)(p1[i] + akoff);
            else {
                float4 f1 = *(const float4*)(p1[i] + akoff);
                float4 f2 = *(const float4*)(p2[i] + akoff);
                f.x = f1.x*f2.x; f.y = f1.y*f2.y; f.z = f1.z*f2.z; f.w = f1.w*f2.w;
            }
            pack2(f.x, f.y, rAh[i].x, rAl[i].x);
            pack2(f.z, f.w, rAh[i].y, rAl[i].y);
        }
        #pragma unroll
        for (int i = 0; i < 4; i++) {
            *(uint2*)(ds + asts[i]) = rAh[i];
            *(uint2*)(ds + 2*BUFB + asts[i]) = rAl[i];
        }
        CPW0();
        __syncthreads();
    }

    int buf = 0;
    for (int c = 0; c < nch; c++) {
        int k1 = (c + 1) << 5;
        bool more = (c + 1) < nch;
        if (more) {
            uint32_t bb = (uint32_t)(buf ^ 1) * BUFB;
            CPA16(uBh + bb + cdst0, Bh + (size_t)crow * Kpad + k1 + ckoff);
            CPA16(uBh + bb + cdst1, Bh + (size_t)(crow + 64) * Kpad + k1 + ckoff);
            CPA16(uBl + bb + cdst0, Bl + (size_t)crow * Kpad + k1 + ckoff);
            CPA16(uBl + bb + cdst1, Bl + (size_t)(crow + 64) * Kpad + k1 + ckoff);
            CPC();
            #pragma unroll
            for (int i = 0; i < 4; i++) {
                float4 f;
                if (AMODE == 0) f = *(const float4*)(p1[i] + k1 + akoff);
                else {
                    float4 f1 = *(const float4*)(p1[i] + k1 + akoff);
                    float4 f2 = *(const float4*)(p2[i] + k1 + akoff);
                    f.x = f1.x*f2.x; f.y = f1.y*f2.y; f.z = f1.z*f2.z; f.w = f1.w*f2.w;
                }
                pack2(f.x, f.y, rAh[i].x, rAl[i].x);
                pack2(f.z, f.w, rAh[i].y, rAl[i].y);
            }
        }
        {
            uint32_t bb = (uint32_t)buf * BUFB;
            #pragma unroll
            for (int ks = 0; ks < 2; ks++) {
                uint32_t bh[8], bl[8];
                ldmx4(bh[0], bh[1], bh[2], bh[3], uBh + bb + boff0 + ks*32);
                ldmx4(bh[4], bh[5], bh[6], bh[7], uBh + bb + boff1 + ks*32);
                ldmx4(bl[0], bl[1], bl[2], bl[3], uBl + bb + boff0 + ks*32);
                ldmx4(bl[4], bl[5], bl[6], bl[7], uBl + bb + boff1 + ks*32);
                #pragma unroll
                for (int mi = 0; mi < 4; mi++) {
                    uint32_t ah[4], al[4];
                    ldmx4(ah[0], ah[1], ah[2], ah[3], uAh + bb + aoff[mi] + ks*32);
                    ldmx4(al[0], al[1], al[2], al[3], uAl + bb + aoff[mi] + ks*32);
                    #pragma unroll
                    for (int ni = 0; ni < 4; ni++) {
                        mma16816(acc[mi][ni], ah, &bh[ni*2]);
                        mma16816(acc[mi][ni], ah, &bl[ni*2]);
                        mma16816(acc[mi][ni], al, &bh[ni*2]);
                    }
                }
            }
        }
        if (more) {
            uint32_t bb = (uint32_t)(buf ^ 1) * BUFB;
            #pragma unroll
            for (int i = 0; i < 4; i++) {
                *(uint2*)(ds + bb + asts[i]) = rAh[i];
                *(uint2*)(ds + 2*BUFB + bb + asts[i]) = rAl[i];
            }
            CPW0();
            __syncthreads();
            buf ^= 1;
        }
    }

    int rowb = blockIdx.x*128 + m0;
    #pragma unroll
    for (int mi = 0; mi < 4; mi++) {
        #pragma unroll
        for (int half = 0; half < 2; half++) {
            int row = rowb + mi*16 + (lane >> 2) + half*8;
            if (row < M) {
                if (EPI == 3) {
                    int dg = sidx[g_perm[row]];
                    float* Hr = Hout + (size_t)dg * 128;
                    #pragma unroll
                    for (int ni = 0; ni < 4; ni++) {
                        int col = n0 + ni*8 + (lane & 3)*2;
                        atomicAdd(Hr + col,     tanhf(acc[mi][ni][half*2+0] + sbias[col]));
                        atomicAdd(Hr + col + 1, tanhf(acc[mi][ni][half*2+1] + sbias[col+1]));
                    }
                } else {
                    size_t cb = (size_t)row * 128;
                    #pragma unroll
                    for (int ni = 0; ni < 4; ni++) {
                        int col = n0 + ni*8 + (lane & 3)*2;
                        float v0 = acc[mi][ni][half*2+0] + sbias[col];
                        float v1 = acc[mi][ni][half*2+1] + sbias[col+1];
                        if (EPI == 1) { v0 = fmaxf(v0, 0.f); v1 = fmaxf(v1, 0.f); }
                        float2 o = make_float2(v0, v1);
                        *(float2*)(C + cb + col) = o;
                    }
                }
            }
        }
    }
}

__global__ void readout2_k(const float* __restrict__ rr, const float* __restrict__ Wr2,
                           const float* __restrict__ br2, const int* __restrict__ gid,
                           float* __restrict__ out, int N) {
    __shared__ float w[128];
    int tid = threadIdx.x;
    if (tid < 128) w[tid] = Wr2[tid];
    __syncthreads();
    int warp = tid >> 5, lane = tid & 31;
    int n = blockIdx.x*4 + warp;
    if (n >= N) return;
    const float* hr = rr + (size_t)n * 128;
    float s = 0.f;
    #pragma unroll
    for (int i = 0; i < 4; i++) s = fmaf(hr[lane + i*32], w[lane + i*32], s);
    #pragma unroll
    for (int o = 16; o > 0; o >>= 1) s += __shfl_down_sync(0xffffffffu, s, o);
    if (lane == 0) atomicAdd(&out[gid[n]], s + br2[0]);
}

extern "C" void kernel_launch(void* const* d_in, const int* in_sizes, int n_in,
                              void* d_out, int out_size) {
    const int*   Z     = (const int*)  d_in[0];
    const int*   etype = (const int*)  d_in[1];
    const float* dist  = (const float*)d_in[2];
    const int*   src   = (const int*)  d_in[3];
    const int*   dst   = (const int*)  d_in[4];
    const int*   gid   = (const int*)  d_in[5];
    const float* node_emb = (const float*)d_in[6];
    const float* edge_emb = (const float*)d_in[7];
    const float* Wn1 = (const float*)d_in[8];
    const float* bn1 = (const float*)d_in[9];
    const float* Wn2 = (const float*)d_in[10];
    const float* bn2 = (const float*)d_in[11];
    const float* We1 = (const float*)d_in[12];
    const float* be1 = (const float*)d_in[13];
    const float* We2 = (const float*)d_in[14];
    const float* be2 = (const float*)d_in[15];
    const float* Wc  = (const float*)d_in[16];
    const float* bc  = (const float*)d_in[17];
    const float* Wr1 = (const float*)d_in[18];
    const float* br1 = (const float*)d_in[19];
    const float* Wr2 = (const float*)d_in[20];
    const float* br2 = (const float*)d_in[21];

    int N = in_sizes[0], E = in_sizes[1], G = out_size;
    float* out = (float*)d_out;

    // one-time stream/event setup (first call is the uncaptured correctness run)
    static cudaStream_t s1 = 0, s2 = 0;
    static cudaEvent_t evF, evRBF, evA[3], evB[3], evC[3];
    static bool sinit = false;
    if (!sinit) {
        cudaStreamCreateWithFlags(&s1, cudaStreamNonBlocking);
        cudaStreamCreateWithFlags(&s2, cudaStreamNonBlocking);
        cudaEventCreateWithFlags(&evF,   cudaEventDisableTiming);
        cudaEventCreateWithFlags(&evRBF, cudaEventDisableTiming);
        for (int i = 0; i < 3; i++) {
            cudaEventCreateWithFlags(&evA[i], cudaEventDisableTiming);
            cudaEventCreateWithFlags(&evB[i], cudaEventDisableTiming);
            cudaEventCreateWithFlags(&evC[i], cudaEventDisableTiming);
        }
        cudaFuncSetAttribute((const void*)fused_t_ee,    cudaFuncAttributeMaxDynamicSharedMemorySize, DSMEM3);
        cudaFuncSetAttribute((const void*)gemm_mma<1,0>, cudaFuncAttributeMaxDynamicSharedMemorySize, DSMEM2);
        cudaFuncSetAttribute((const void*)gemm_mma<0,0>, cudaFuncAttributeMaxDynamicSharedMemorySize, DSMEM2);
        cudaFuncSetAttribute((const void*)gemm_mma<3,2>, cudaFuncAttributeMaxDynamicSharedMemorySize, DSMEM2);
        sinit = true;
    }

    void* p;
    float *h, *ee, *tmp, *P;
    __nv_bfloat16 *W1h,*W1l,*We2h,*We2l,*Wn1h,*Wn1l,*Wn2h,*Wn2l,*Wch,*Wcl,*Wr1h,*Wr1l;
    cudaGetSymbolAddress(&p, g_h);   h   = (float*)p;
    cudaGetSymbolAddress(&p, g_ee);  ee  = (float*)p;
    cudaGetSymbolAddress(&p, g_tmp); tmp = (float*)p;
    cudaGetSymbolAddress(&p, g_P);   P   = (float*)p;
    cudaGetSymbolAddress(&p, g_W1h);  W1h  = (__nv_bfloat16*)p;
    cudaGetSymbolAddress(&p, g_W1l);  W1l  = (__nv_bfloat16*)p;
    cudaGetSymbolAddress(&p, g_We2h); We2h = (__nv_bfloat16*)p;
    cudaGetSymbolAddress(&p, g_We2l); We2l = (__nv_bfloat16*)p;
    cudaGetSymbolAddress(&p, g_Wn1h); Wn1h = (__nv_bfloat16*)p;
    cudaGetSymbolAddress(&p, g_Wn1l); Wn1l = (__nv_bfloat16*)p;
    cudaGetSymbolAddress(&p, g_Wn2h); Wn2h = (__nv_bfloat16*)p;
    cudaGetSymbolAddress(&p, g_Wn2l); Wn2l = (__nv_bfloat16*)p;
    cudaGetSymbolAddress(&p, g_Wch);  Wch  = (__nv_bfloat16*)p;
    cudaGetSymbolAddress(&p, g_Wcl);  Wcl  = (__nv_bfloat16*)p;
    cudaGetSymbolAddress(&p, g_Wr1h); Wr1h = (__nv_bfloat16*)p;
    cudaGetSymbolAddress(&p, g_Wr1l); Wr1l = (__nv_bfloat16*)p;

    int gE = (E + 127)/128, gN = (N + 127)/128;

    // fork side streams off the capture (default) stream
    cudaEventRecord(evF, 0);
    cudaStreamWaitEvent(s1, evF, 0);
    cudaStreamWaitEvent(s2, evF, 0);

    // main stream: edge sort + rbf operand chain
    zero_hist_k<<<(2*NBUCK + 255)/256, 256>>>();
    hist_k<<<(E + 255)/256, 256>>>(dist, E);
    scan512_k<<<1, NBUCK>>>();
    scatter_perm_k<<<(E + 255)/256, 256>>>(dist, E);
    rbf_klo_k<<<gE, 128, 0, 0>>>(dist, E);
    rbf_split_k<<<gE, 128, 0, 0>>>(dist, E);
    cudaEventRecord(evRBF, 0);

    // s1: node-side prep (h init + node weight splits)
    init_h_k<<<(N*128 + 255)/256, 256, 0, s1>>>(Z, node_emb, h, N);
    for (int i = 0; i < 3; i++) {
        split_pad_k<<<(128*128 + 255)/256, 256, 0, s1>>>(Wn1 + (size_t)i*128*128, Wn1h + (size_t)i*128*128, Wn1l + (size_t)i*128*128, 128, 128, 128, 0, 128, 128*128);
        split_pad_k<<<(128*128 + 255)/256, 256, 0, s1>>>(Wn2 + (size_t)i*128*128, Wn2h + (size_t)i*128*128, Wn2l + (size_t)i*128*128, 128, 128, 128, 0, 128, 128*128);
    }
    split_pad_k<<<(128*128 + 255)/256, 256, 0, s1>>>(Wr1, Wr1h, Wr1l, 128, 128, 128, 0, 128, 128*128);

    // s2: edge-side prep (We1/We2/Wc splits + P table)
    for (int i = 0; i < 3; i++) {
        split_pad_k<<<(512*384 + 255)/256, 256, 0, s2>>>(We1 + (size_t)i*428*428, W1h + (size_t)i*512*384, W1l + (size_t)i*512*384, 428, 300, 428, 128, 384, 512*384);
        split_pad_k<<<(128*448 + 255)/256, 256, 0, s2>>>(We2 + (size_t)i*128*428, We2h + (size_t)i*128*448, We2l + (size_t)i*128*448, 128, 428, 428, 0, 448, 128*448);
        split_pad_k<<<(128*128 + 255)/256, 256, 0, s2>>>(Wc  + (size_t)i*128*128, Wch  + (size_t)i*128*128, Wcl  + (size_t)i*128*128, 128, 128, 128, 0, 128, 128*128);
    }
    p_kernel<<<dim3(400, 3), 448, 0, s2>>>(edge_emb, We1, be1, P);
    cudaStreamWaitEvent(s2, evRBF, 0);   // fused needs perm/klo/rbfA

    for (int i = 0; i < 3; i++) {
        float* eeb = ee + (size_t)(i & 1) * E_MAXE * 128;
        // s2: fused t->ee (independent of h); ee buffer reuse guarded by mix(i-2)
        if (i >= 2) cudaStreamWaitEvent(s2, evC[i-2], 0);
        fused_t_ee<<<gE, 256, DSMEM3, s2>>>(W1h + (size_t)i*512*384, W1l + (size_t)i*512*384,
                                            We2h + (size_t)i*128*448, We2l + (size_t)i*128*448,
                                            P + (size_t)i*400*428, be2 + i*128, etype, eeb, E);
        cudaEventRecord(evB[i], s2);

        // s1: node MLP (needs h after mix(i-1))
        if (i >= 1) cudaStreamWaitEvent(s1, evC[i-1], 0);
        gemm_mma<1,0><<<gN, 256, DSMEM2, s1>>>(h, nullptr, 128, 128,
            Wn1h + (size_t)i*128*128, Wn1l + (size_t)i*128*128, 128,
            bn1 + i*128, tmp, N, nullptr, nullptr, nullptr);
        gemm_mma<0,0><<<gN, 256, DSMEM2, s1>>>(tmp, nullptr, 128, 128,
            Wn2h + (size_t)i*128*128, Wn2l + (size_t)i*128*128, 128,
            bn2 + i*128, tmp, N, nullptr, nullptr, nullptr);
        cudaEventRecord(evA[i], s1);

        // main: mix = tanh((tmp[src]*ee) @ Wc^T + bc), scatter into h
        cudaStreamWaitEvent(0, evA[i], 0);
        cudaStreamWaitEvent(0, evB[i], 0);
        gemm_mma<3,2><<<gE, 256, DSMEM2, 0>>>(tmp, eeb, 128, 128,
            Wch + (size_t)i*128*128, Wcl + (size_t)i*128*128, 128,
            bc + i*128, nullptr, E, src, dst, h);
        cudaEventRecord(evC[i], 0);
    }

    // readout on main stream (h final; Wr1 split ordered via evA chain on s1 -> evA[0] -> main)
    gemm_mma<1,0><<<gN, 256, DSMEM2, 0>>>(h, nullptr, 128, 128,
        Wr1h, Wr1l, 128, br1, tmp, N, nullptr, nullptr, nullptr);
    zero_f_k<<<(G + 255)/256, 256>>>(out, G);
    readout2_k<<<(N + 3)/4, 128>>>(tmp, Wr2, br2, gid, out, N);
}

// round 9
// speedup vs baseline: 1.3763x; 1.1123x over previous
#include <cuda_runtime.h>
#include <cuda_bf16.h>
#include <math.h>
#include <stdint.h>

#define N_RBF 300
#define NBUCK 512
#define N_MAXN 100352
#define E_MAXE 400384
#define GE2_MAX 6256
#define RBF_STEP (30.0f/299.0f)
#define RBF_INV  (299.0f/30.0f)
#define SLD 40
#define ASLD 56
#define WK 48
#define BUFB 10240
#define DSMEM2 81920
#define DSMEM4 79872

__device__ float g_h  [(size_t)N_MAXN*128];
__device__ float g_ee [2*(size_t)E_MAXE*128];
__device__ float g_tmp[(size_t)N_MAXN*128];
__device__ float g_P  [3*400*428];
__device__ int   g_perm[E_MAXE];
__device__ int   g_hist[2*NBUCK];
__device__ int   g_klo [GE2_MAX];
__device__ __nv_bfloat16 g_rAh[(size_t)E_MAXE*WK],  g_rAl[(size_t)E_MAXE*WK];
__device__ __nv_bfloat16 g_W1h[3*512*384],  g_W1l[3*512*384];
__device__ __nv_bfloat16 g_We2h[3*128*448], g_We2l[3*128*448];
__device__ __nv_bfloat16 g_Wn1h[3*128*128], g_Wn1l[3*128*128];
__device__ __nv_bfloat16 g_Wn2h[3*128*128], g_Wn2l[3*128*128];
__device__ __nv_bfloat16 g_Wch [3*128*128], g_Wcl [3*128*128];
__device__ __nv_bfloat16 g_Wr1h[128*128],   g_Wr1l[128*128];

__device__ __forceinline__ uint32_t smem_u32(const void* p) {
    uint32_t a;
    asm("{ .reg .u64 t; cvta.to.shared.u64 t, %1; cvt.u32.u64 %0, t; }" : "=r"(a) : "l"(p));
    return a;
}
__device__ __forceinline__ void ldmx4(uint32_t& r0, uint32_t& r1, uint32_t& r2, uint32_t& r3, uint32_t a) {
    asm volatile("ldmatrix.sync.aligned.m8n8.x4.shared.b16 {%0,%1,%2,%3}, [%4];"
        : "=r"(r0), "=r"(r1), "=r"(r2), "=r"(r3) : "r"(a));
}
__device__ __forceinline__ void mma16816(float* c, const uint32_t* a, const uint32_t* b) {
    asm volatile("mma.sync.aligned.m16n8k16.row.col.f32.bf16.bf16.f32 "
        "{%0,%1,%2,%3},{%4,%5,%6,%7},{%8,%9},{%0,%1,%2,%3};"
        : "+f"(c[0]), "+f"(c[1]), "+f"(c[2]), "+f"(c[3])
        : "r"(a[0]), "r"(a[1]), "r"(a[2]), "r"(a[3]), "r"(b[0]), "r"(b[1]));
}
__device__ __forceinline__ void pack2(float a, float b, uint32_t& h, uint32_t& l) {
    __nv_bfloat162 hb = __floats2bfloat162_rn(a, b);
    __nv_bfloat162 lb = __floats2bfloat162_rn(a - __low2float(hb), b - __high2float(hb));
    h = *reinterpret_cast<uint32_t*>(&hb);
    l = *reinterpret_cast<uint32_t*>(&lb);
}
#define CPA16(dst, src) asm volatile("cp.async.cg.shared.global [%0], [%1], 16;" :: "r"(dst), "l"(src))
#define CPC()  asm volatile("cp.async.commit_group;" ::: "memory")
#define CPW0() asm volatile("cp.async.wait_group 0;" ::: "memory")

__global__ void zero_hist_k() { int i = blockIdx.x*256 + threadIdx.x; if (i < 2*NBUCK) g_hist[i] = 0; }
__global__ void zero_f_k(float* p, int n) { int i = blockIdx.x*256 + threadIdx.x; if (i < n) p[i] = 0.f; }
__device__ __forceinline__ int bucket_of(float d) {
    int b = (int)(d * (512.0f/30.0f));
    return min(max(b, 0), NBUCK-1);
}
// privatized histogram: grid 148 x 512 threads
__global__ void hist_k(const float* __restrict__ dist, int E) {
    __shared__ int lh[NBUCK];
    int tid = threadIdx.x;
    int per = (E + gridDim.x - 1) / gridDim.x;
    int lo = blockIdx.x * per, hi = min(E, lo + per);
    for (int i = tid; i < NBUCK; i += 512) lh[i] = 0;
    __syncthreads();
    for (int e = lo + tid; e < hi; e += 512) atomicAdd(&lh[bucket_of(dist[e])], 1);
    __syncthreads();
    for (int i = tid; i < NBUCK; i += 512) if (lh[i]) atomicAdd(&g_hist[i], lh[i]);
}
__global__ void scan512_k() {
    __shared__ int s[NBUCK];
    int tid = threadIdx.x;
    int v0 = g_hist[tid];
    s[tid] = v0; __syncthreads();
    for (int off = 1; off < NBUCK; off <<= 1) {
        int v = 0;
        if (tid >= off) v = s[tid - off];
        __syncthreads(); s[tid] += v; __syncthreads();
    }
    g_hist[NBUCK + tid] = s[tid] - v0;
}
// privatized scatter: grid 148 x 512 threads
__global__ void scatter_perm_k(const float* __restrict__ dist, int E) {
    __shared__ int lh[NBUCK], base[NBUCK];
    int tid = threadIdx.x;
    int per = (E + gridDim.x - 1) / gridDim.x;
    int lo = blockIdx.x * per, hi = min(E, lo + per);
    for (int i = tid; i < NBUCK; i += 512) lh[i] = 0;
    __syncthreads();
    for (int e = lo + tid; e < hi; e += 512) atomicAdd(&lh[bucket_of(dist[e])], 1);
    __syncthreads();
    for (int i = tid; i < NBUCK; i += 512)
        base[i] = lh[i] ? atomicAdd(&g_hist[NBUCK + i], lh[i]) : 0;
    __syncthreads();
    for (int i = tid; i < NBUCK; i += 512) lh[i] = 0;
    __syncthreads();
    for (int e = lo + tid; e < hi; e += 512) {
        int b = bucket_of(dist[e]);
        int r = atomicAdd(&lh[b], 1);
        g_perm[base[b] + r] = e;
    }
}
__global__ void init_h_k(const int* __restrict__ Z, const float* __restrict__ ne,
                         float* __restrict__ h, int N) {
    int idx = blockIdx.x*256 + threadIdx.x;
    if (idx < N*128) h[idx] = ne[Z[idx >> 7]*128 + (idx & 127)];
}
__global__ void split_pad_k(const float* __restrict__ src, __nv_bfloat16* __restrict__ dh,
                            __nv_bfloat16* __restrict__ dl,
                            int R, int Ks, int ld, int off, int Kpad, int tot) {
    int idx = blockIdx.x*256 + threadIdx.x;
    if (idx < tot) {
        int r = idx / Kpad, k = idx % Kpad;
        float v = (r < R && k < Ks) ? src[(size_t)r*ld + off + k] : 0.f;
        __nv_bfloat16 h = __float2bfloat16(v);
        dh[idx] = h;
        dl[idx] = __float2bfloat16(v - __bfloat162float(h));
    }
}
__global__ void p_kernel(const float* __restrict__ edge_emb, const float* __restrict__ We1,
                         const float* __restrict__ be1, float* __restrict__ P) {
    int ty = blockIdx.x, layer = blockIdx.y, j = threadIdx.x;
    __shared__ float em[128];
    if (j < 128) em[j] = edge_emb[ty*128 + j];
    __syncthreads();
    if (j < 428) {
        const float* wrow = We1 + ((size_t)layer*428 + j)*428;
        float acc = be1[layer*428 + j];
        #pragma unroll 8
        for (int k = 0; k < 128; k++) acc = fmaf(em[k], wrow[k], acc);
        P[((size_t)layer*400 + ty)*428 + j] = acc;
    }
}
// per 64-edge tile window start
__global__ void rbf_klo_k(const float* __restrict__ dist, int E) {
    __shared__ float s[64];
    int tid = threadIdx.x, gr = blockIdx.x*64 + tid;
    s[tid] = dist[g_perm[min(gr, E-1)]];
    __syncthreads();
    for (int o = 32; o > 0; o >>= 1) {
        if (tid < o) s[tid] = fminf(s[tid], s[tid + o]);
        __syncthreads();
    }
    if (tid == 0) {
        int k = (int)floorf((s[0] - 1.6f) * RBF_INV);
        if (k < 0) k = 0;
        g_klo[blockIdx.x] = k & ~7;
    }
}
__global__ void rbf_split_k(const float* __restrict__ dist, int E) {
    int tid = threadIdx.x, gr = blockIdx.x*64 + tid;
    float d = dist[g_perm[min(gr, E-1)]];
    int k0 = g_klo[blockIdx.x];
    float vals[WK];
    #pragma unroll
    for (int i = 0; i < WK; i++) vals[i] = 0.f;
    int icen = (int)(d * RBF_INV) - k0;
    int ilo = max(0, icen - 16);
    int ihi = min(min(WK-1, icen + 16), 299 - k0);
    for (int i = ilo; i <= ihi; i++) {
        float x = d - (float)(k0 + i) * RBF_STEP;
        vals[i] = __expf(-RBF_INV * x * x);
    }
    size_t base = (size_t)gr * WK;
    #pragma unroll
    for (int i = 0; i < WK; i += 8) {
        uint4 H, L;
        pack2(vals[i+0], vals[i+1], H.x, L.x);
        pack2(vals[i+2], vals[i+3], H.y, L.y);
        pack2(vals[i+4], vals[i+5], H.z, L.z);
        pack2(vals[i+6], vals[i+7], H.w, L.w);
        *(uint4*)(g_rAh + base + i) = H;
        *(uint4*)(g_rAl + base + i) = L;
    }
}

// ============ fused t -> ee kernel, 64-edge tiles, 2 CTAs/SM ============
// smem (bytes): Th 0..5120, Tl 5120..10240, Ah 10240..17408, Al 17408..24576,
// W1h 24576(2x3584), W1l 31744(2x3584), W2h 38912(2x10240), W2l 59392(2x10240) = 79872
__global__ void __launch_bounds__(256, 2)
fused_t_ee(const __nv_bfloat16* __restrict__ W1h, const __nv_bfloat16* __restrict__ W1l,
           const __nv_bfloat16* __restrict__ W2h, const __nv_bfloat16* __restrict__ W2l,
           const float* __restrict__ P, const float* __restrict__ be2,
           const int* __restrict__ etype, float* __restrict__ ee, int E) {
    extern __shared__ char ds[];
    __shared__ int sety[64];
    __shared__ float sbias[128];
    int tid = threadIdx.x, lane = tid & 31, warp = tid >> 5, bx = blockIdx.x;
    int klo = g_klo[bx];
    if (tid < 64) sety[tid] = etype[g_perm[min(bx*64 + tid, E-1)]];
    if (tid < 128) sbias[tid] = be2[tid];
    uint32_t b0 = smem_u32(ds);
    uint32_t uTh = b0,          uTl = b0 + 5120;
    uint32_t uAh = b0 + 10240,  uAl = b0 + 17408;
    uint32_t uW1h = b0 + 24576, uW1l = b0 + 31744;
    uint32_t uW2h = b0 + 38912, uW2l = b0 + 59392;

    // A tile 64xWK hi/lo (stride ASLD)
    for (int i = tid; i < 384; i += 256) {
        int row = i / 6, kk = (i % 6) * 8;
        uint32_t d = (uint32_t)(row*ASLD + kk)*2;
        size_t s = (size_t)(bx*64 + row)*WK + kk;
        CPA16(uAh + d, g_rAh + s);
        CPA16(uAl + d, g_rAl + s);
    }
    // chunk 0 weights
    if (tid < 192) {
        int row = tid / 6, kk = (tid % 6) * 8;
        uint32_t d = (uint32_t)(row*ASLD + kk)*2;
        size_t s = (size_t)row*384 + klo + kk;
        CPA16(uW1h + d, W1h + s);
        CPA16(uW1l + d, W1l + s);
    }
    for (int i = tid; i < 512; i += 256) {
        int row = i >> 2, kk = (i & 3) * 8;
        uint32_t d = (uint32_t)(row*SLD + kk)*2;
        size_t s = (size_t)row*448 + kk;
        CPA16(uW2h + d, W2h + s);
        CPA16(uW2l + d, W2l + s);
    }
    CPC(); CPW0();
    __syncthreads();

    int arow = lane & 15, acol = (lane >> 4) << 3;
    int brow = (lane & 7) + ((lane >> 1) & 8), bcol = lane & 8;
    // MMA1: 4x2 warp layout (rows (warp>>1)*16, cols (warp&1)*16)
    int r1 = (warp >> 1)*16, c1 = (warp & 1)*16;
    uint32_t a1off = (uint32_t)((r1 + arow)*ASLD + acol)*2;
    uint32_t b1off = (uint32_t)((c1 + brow)*ASLD + bcol)*2;
    // MMA2: 2x4 warp layout
    int m0 = (warp >> 2)*32, n0 = (warp & 3)*32;
    uint32_t a2off[2];
    #pragma unroll
    for (int mi = 0; mi < 2; mi++) a2off[mi] = (uint32_t)((m0 + mi*16 + arow)*SLD + acol)*2;
    uint32_t b2off0 = (uint32_t)((n0 + brow)*SLD + bcol)*2;
    uint32_t b2off1 = (uint32_t)((n0 + 16 + brow)*SLD + bcol)*2;
    int lrow = lane >> 2, lcol = (lane & 3)*2;

    float eacc[2][4][4];
    #pragma unroll
    for (int mi = 0; mi < 2; mi++)
        #pragma unroll
        for (int ni = 0; ni < 4; ni++)
            #pragma unroll
            for (int q = 0; q < 4; q++) eacc[mi][ni][q] = 0.f;

    int buf = 0;
    for (int c = 0; c < 14; c++) {
        if (c < 13) {
            uint32_t cb = (uint32_t)(buf ^ 1);
            if (tid < 192) {
                int row = tid / 6, kk = (tid % 6) * 8;
                uint32_t d = cb*3584 + (uint32_t)(row*ASLD + kk)*2;
                size_t s = (size_t)((c+1)*32 + row)*384 + klo + kk;
                CPA16(uW1h + d, W1h + s);
                CPA16(uW1l + d, W1l + s);
            }
            for (int i = tid; i < 512; i += 256) {
                int row = i >> 2, kk = (i & 3) * 8;
                uint32_t d = cb*10240 + (uint32_t)(row*SLD + kk)*2;
                size_t s = (size_t)row*448 + (c+1)*32 + kk;
                CPA16(uW2h + d, W2h + s);
                CPA16(uW2l + d, W2l + s);
            }
            CPC();
        }
        // MMA1: t_chunk[64,32], K=48 (3 ks)
        float acc1[2][4];
        #pragma unroll
        for (int ni = 0; ni < 2; ni++)
            #pragma unroll
            for (int q = 0; q < 4; q++) acc1[ni][q] = 0.f;
        {
            uint32_t w1b = (uint32_t)buf * 3584;
            #pragma unroll
            for (int ks = 0; ks < 3; ks++) {
                uint32_t ah[4], al[4], bh[4], bl[4];
                ldmx4(ah[0], ah[1], ah[2], ah[3], uAh + a1off + ks*32);
                ldmx4(al[0], al[1], al[2], al[3], uAl + a1off + ks*32);
                ldmx4(bh[0], bh[1], bh[2], bh[3], uW1h + w1b + b1off + ks*32);
                ldmx4(bl[0], bl[1], bl[2], bl[3], uW1l + w1b + b1off + ks*32);
                #pragma unroll
                for (int ni = 0; ni < 2; ni++) {
                    mma16816(acc1[ni], ah, &bh[ni*2]);
                    mma16816(acc1[ni], ah, &bl[ni*2]);
                    mma16816(acc1[ni], al, &bh[ni*2]);
                }
            }
        }
        // epilogue1: +P, relu, pack -> sT
        {
            int gcb = c*32;
            #pragma unroll
            for (int half = 0; half < 2; half++) {
                int r = r1 + lrow + half*8;
                const float* Pr = P + (size_t)sety[r]*428;
                #pragma unroll
                for (int ni = 0; ni < 2; ni++) {
                    int col = c1 + ni*8 + lcol;
                    int gcol = gcb + col;
                    float v0 = 0.f, v1 = 0.f;
                    if (gcol < 428) {
                        float2 pv = *(const float2*)(Pr + gcol);
                        v0 = fmaxf(acc1[ni][half*2+0] + pv.x, 0.f);
                        v1 = fmaxf(acc1[ni][half*2+1] + pv.y, 0.f);
                    }
                    uint32_t H, L;
                    pack2(v0, v1, H, L);
                    uint32_t doff = (uint32_t)(r*SLD + col)*2;
                    *(uint32_t*)(ds + doff) = H;
                    *(uint32_t*)(ds + 5120 + doff) = L;
                }
            }
        }
        __syncthreads();
        // MMA2: ee += t_chunk @ We2_chunk^T
        {
            uint32_t w2b = (uint32_t)buf * 10240;
            #pragma unroll
            for (int ks = 0; ks < 2; ks++) {
                uint32_t bh[8], bl[8];
                ldmx4(bh[0], bh[1], bh[2], bh[3], uW2h + w2b + b2off0 + ks*32);
                ldmx4(bh[4], bh[5], bh[6], bh[7], uW2h + w2b + b2off1 + ks*32);
                ldmx4(bl[0], bl[1], bl[2], bl[3], uW2l + w2b + b2off0 + ks*32);
                ldmx4(bl[4], bl[5], bl[6], bl[7], uW2l + w2b + b2off1 + ks*32);
                #pragma unroll
                for (int mi = 0; mi < 2; mi++) {
                    uint32_t ah[4], al[4];
                    ldmx4(ah[0], ah[1], ah[2], ah[3], uTh + a2off[mi] + ks*32);
                    ldmx4(al[0], al[1], al[2], al[3], uTl + a2off[mi] + ks*32);
                    #pragma unroll
                    for (int ni = 0; ni < 4; ni++) {
                        mma16816(eacc[mi][ni], ah, &bh[ni*2]);
                        mma16816(eacc[mi][ni], ah, &bl[ni*2]);
                        mma16816(eacc[mi][ni], al, &bh[ni*2]);
                    }
                }
            }
        }
        if (c < 13) CPW0();
        __syncthreads();
        buf ^= 1;
    }

    int rowb = bx*64 + m0;
    #pragma unroll
    for (int mi = 0; mi < 2; mi++) {
        #pragma unroll
        for (int half = 0; half < 2; half++) {
            int row = rowb + mi*16 + lrow + half*8;
            if (row < E) {
                size_t cb = (size_t)row * 128;
                #pragma unroll
                for (int ni = 0; ni < 4; ni++) {
                    int col = n0 + ni*8 + lcol;
                    float2 o;
                    o.x = eacc[mi][ni][half*2+0] + sbias[col];
                    o.y = eacc[mi][ni][half*2+1] + sbias[col+1];
                    *(float2*)(ee + cb + col) = o;
                }
            }
        }
    }
}

// ============ generic pipelined GEMM ============
// EPI: 0 store, 1 relu store, 3 tanh + atomicAdd scatter to Hout[sidx[perm[row]]]
// AMODE: 0 fp32 rows direct; 2 product Af[gidx[perm[row]]]*A2[row]
template<int EPI, int AMODE>
__global__ void __launch_bounds__(256)
gemm_mma(const float* __restrict__ Af, const float* __restrict__ A2,
         int lda, int Kloop,
         const __nv_bfloat16* __restrict__ Bh, const __nv_bfloat16* __restrict__ Bl, int Kpad,
         const float* __restrict__ bias, float* __restrict__ C, int M,
         const int* __restrict__ gidx, const int* __restrict__ sidx, float* __restrict__ Hout) {
    extern __shared__ char ds[];
    __shared__ float sbias[128];
    int tid = threadIdx.x, lane = tid & 31, warp = tid >> 5;
    if (tid < 128) sbias[tid] = bias[tid];

    uint32_t b0 = smem_u32(ds);
    uint32_t uAh = b0, uAl = b0 + 2*BUFB, uBh = b0 + 4*BUFB, uBl = b0 + 6*BUFB;

    const float *p1[4], *p2[4];
    if (AMODE == 0) {
        #pragma unroll
        for (int i = 0; i < 4; i++) {
            int r = blockIdx.x*128 + i*32 + (tid >> 3);
            p1[i] = Af + (size_t)min(r, M-1) * lda;
        }
    } else {
        #pragma unroll
        for (int i = 0; i < 4; i++) {
            int r = blockIdx.x*128 + i*32 + (tid >> 3);
            int rc = min(r, M-1);
            p1[i] = Af + (size_t)gidx[g_perm[rc]] * 128;
            p2[i] = A2 + (size_t)rc * 128;
        }
    }
    int akoff = (tid & 7) << 2;
    int ckoff = (tid & 3) << 3;
    int crow  = tid >> 2;
    uint32_t cdst0 = ((uint32_t)crow * SLD + ckoff) * 2;
    uint32_t cdst1 = ((uint32_t)(crow + 64) * SLD + ckoff) * 2;
    uint32_t asts[4];
    #pragma unroll
    for (int i = 0; i < 4; i++) asts[i] = ((uint32_t)(i*32 + (tid >> 3)) * SLD + akoff) * 2;

    int m0 = (warp >> 2) * 64, n0 = (warp & 3) * 32;
    int arow = lane & 15, acol = (lane >> 4) << 3;
    int brow = (lane & 7) + ((lane >> 1) & 8), bcol = lane & 8;
    uint32_t aoff[4];
    #pragma unroll
    for (int mi = 0; mi < 4; mi++) aoff[mi] = ((m0 + mi*16 + arow)*SLD + acol) * 2;
    uint32_t boff0 = ((n0 + brow)*SLD + bcol) * 2;
    uint32_t boff1 = ((n0 + 16 + brow)*SLD + bcol) * 2;

    float acc[4][4][4];
    #pragma unroll
    for (int mi = 0; mi < 4; mi++)
        #pragma unroll
        for (int ni = 0; ni < 4; ni++)
            #pragma unroll
            for (int q = 0; q < 4; q++) acc[mi][ni][q] = 0.f;

    uint2 rAh[4], rAl[4];
    int nch = Kloop >> 5;

    {
        CPA16(uBh + cdst0, Bh + (size_t)crow * Kpad + ckoff);
        CPA16(uBh + cdst1, Bh + (size_t)(crow + 64) * Kpad + ckoff);
        CPA16(uBl + cdst0, Bl + (size_t)crow * Kpad + ckoff);
        CPA16(uBl + cdst1, Bl + (size_t)(crow + 64) * Kpad + ckoff);
        CPC();
        #pragma unroll
        for (int i = 0; i < 4; i++) {
            float4 f;
            if (AMODE == 0) f = *(const float4*)(p1[i] + akoff);
            else {
                float4 f1 = *(const float4*)(p1[i] + akoff);
                float4 f2 = *(const float4*)(p2[i] + akoff);
                f.x = f1.x*f2.x; f.y = f1.y*f2.y; f.z = f1.z*f2.z; f.w = f1.w*f2.w;
            }
            pack2(f.x, f.y, rAh[i].x, rAl[i].x);
            pack2(f.z, f.w, rAh[i].y, rAl[i].y);
        }
        #pragma unroll
        for (int i = 0; i < 4; i++) {
            *(uint2*)(ds + asts[i]) = rAh[i];
            *(uint2*)(ds + 2*BUFB + asts[i]) = rAl[i];
        }
        CPW0();
        __syncthreads();
    }

    int buf = 0;
    for (int c = 0; c < nch; c++) {
        int k1 = (c + 1) << 5;
        bool more = (c + 1) < nch;
        if (more) {
            uint32_t bb = (uint32_t)(buf ^ 1) * BUFB;
            CPA16(uBh + bb + cdst0, Bh + (size_t)crow * Kpad + k1 + ckoff);
            CPA16(uBh + bb + cdst1, Bh + (size_t)(crow + 64) * Kpad + k1 + ckoff);
            CPA16(uBl + bb + cdst0, Bl + (size_t)crow * Kpad + k1 + ckoff);
            CPA16(uBl + bb + cdst1, Bl + (size_t)(crow + 64) * Kpad + k1 + ckoff);
            CPC();
            #pragma unroll
            for (int i = 0; i < 4; i++) {
                float4 f;
                if (AMODE == 0) f = *(const float4*)(p1[i] + k1 + akoff);
                else {
                    float4 f1 = *(const float4*)(p1[i] + k1 + akoff);
                    float4 f2 = *(const float4*)(p2[i] + k1 + akoff);
                    f.x = f1.x*f2.x; f.y = f1.y*f2.y; f.z = f1.z*f2.z; f.w = f1.w*f2.w;
                }
                pack2(f.x, f.y, rAh[i].x, rAl[i].x);
                pack2(f.z, f.w, rAh[i].y, rAl[i].y);
            }
        }
        {
            uint32_t bb = (uint32_t)buf * BUFB;
            #pragma unroll
            for (int ks = 0; ks < 2; ks++) {
                uint32_t bh[8], bl[8];
                ldmx4(bh[0], bh[1], bh[2], bh[3], uBh + bb + boff0 + ks*32);
                ldmx4(bh[4], bh[5], bh[6], bh[7], uBh + bb + boff1 + ks*32);
                ldmx4(bl[0], bl[1], bl[2], bl[3], uBl + bb + boff0 + ks*32);
                ldmx4(bl[4], bl[5], bl[6], bl[7], uBl + bb + boff1 + ks*32);
                #pragma unroll
                for (int mi = 0; mi < 4; mi++) {
                    uint32_t ah[4], al[4];
                    ldmx4(ah[0], ah[1], ah[2], ah[3], uAh + bb + aoff[mi] + ks*32);
                    ldmx4(al[0], al[1], al[2], al[3], uAl + bb + aoff[mi] + ks*32);
                    #pragma unroll
                    for (int ni = 0; ni < 4; ni++) {
                        mma16816(acc[mi][ni], ah, &bh[ni*2]);
                        mma16816(acc[mi][ni], ah, &bl[ni*2]);
                        mma16816(acc[mi][ni], al, &bh[ni*2]);
                    }
                }
            }
        }
        if (more) {
            uint32_t bb = (uint32_t)(buf ^ 1) * BUFB;
            #pragma unroll
            for (int i = 0; i < 4; i++) {
                *(uint2*)(ds + bb + asts[i]) = rAh[i];
                *(uint2*)(ds + 2*BUFB + bb + asts[i]) = rAl[i];
            }
            CPW0();
            __syncthreads();
            buf ^= 1;
        }
    }

    int rowb = blockIdx.x*128 + m0;
    #pragma unroll
    for (int mi = 0; mi < 4; mi++) {
        #pragma unroll
        for (int half = 0; half < 2; half++) {
            int row = rowb + mi*16 + (lane >> 2) + half*8;
            if (row < M) {
                if (EPI == 3) {
                    int dg = sidx[g_perm[row]];
                    float* Hr = Hout + (size_t)dg * 128;
                    #pragma unroll
                    for (int ni = 0; ni < 4; ni++) {
                        int col = n0 + ni*8 + (lane & 3)*2;
                        atomicAdd(Hr + col,     tanhf(acc[mi][ni][half*2+0] + sbias[col]));
                        atomicAdd(Hr + col + 1, tanhf(acc[mi][ni][half*2+1] + sbias[col+1]));
                    }
                } else {
                    size_t cb = (size_t)row * 128;
                    #pragma unroll
                    for (int ni = 0; ni < 4; ni++) {
                        int col = n0 + ni*8 + (lane & 3)*2;
                        float v0 = acc[mi][ni][half*2+0] + sbias[col];
                        float v1 = acc[mi][ni][half*2+1] + sbias[col+1];
                        if (EPI == 1) { v0 = fmaxf(v0, 0.f); v1 = fmaxf(v1, 0.f); }
                        float2 o = make_float2(v0, v1);
                        *(float2*)(C + cb + col) = o;
                    }
                }
            }
        }
    }
}

__global__ void readout2_k(const float* __restrict__ rr, const float* __restrict__ Wr2,
                           const float* __restrict__ br2, const int* __restrict__ gid,
                           float* __restrict__ out, int N) {
    __shared__ float w[128];
    int tid = threadIdx.x;
    if (tid < 128) w[tid] = Wr2[tid];
    __syncthreads();
    int warp = tid >> 5, lane = tid & 31;
    int n = blockIdx.x*4 + warp;
    if (n >= N) return;
    const float* hr = rr + (size_t)n * 128;
    float s = 0.f;
    #pragma unroll
    for (int i = 0; i < 4; i++) s = fmaf(hr[lane + i*32], w[lane + i*32], s);
    #pragma unroll
    for (int o = 16; o > 0; o >>= 1) s += __shfl_down_sync(0xffffffffu, s, o);
    if (lane == 0) atomicAdd(&out[gid[n]], s + br2[0]);
}

extern "C" void kernel_launch(void* const* d_in, const int* in_sizes, int n_in,
                              void* d_out, int out_size) {
    const int*   Z     = (const int*)  d_in[0];
    const int*   etype = (const int*)  d_in[1];
    const float* dist  = (const float*)d_in[2];
    const int*   src   = (const int*)  d_in[3];
    const int*   dst   = (const int*)  d_in[4];
    const int*   gid   = (const int*)  d_in[5];
    const float* node_emb = (const float*)d_in[6];
    const float* edge_emb = (const float*)d_in[7];
    const float* Wn1 = (const float*)d_in[8];
    const float* bn1 = (const float*)d_in[9];
    const float* Wn2 = (const float*)d_in[10];
    const float* bn2 = (const float*)d_in[11];
    const float* We1 = (const float*)d_in[12];
    const float* be1 = (const float*)d_in[13];
    const float* We2 = (const float*)d_in[14];
    const float* be2 = (const float*)d_in[15];
    const float* Wc  = (const float*)d_in[16];
    const float* bc  = (const float*)d_in[17];
    const float* Wr1 = (const float*)d_in[18];
    const float* br1 = (const float*)d_in[19];
    const float* Wr2 = (const float*)d_in[20];
    const float* br2 = (const float*)d_in[21];

    int N = in_sizes[0], E = in_sizes[1], G = out_size;
    float* out = (float*)d_out;

    static cudaStream_t s1 = 0, s2 = 0;
    static cudaEvent_t evF, evRBF, evA[3], evB[3], evC[3];
    static bool sinit = false;
    if (!sinit) {
        cudaStreamCreateWithFlags(&s1, cudaStreamNonBlocking);
        cudaStreamCreateWithFlags(&s2, cudaStreamNonBlocking);
        cudaEventCreateWithFlags(&evF,   cudaEventDisableTiming);
        cudaEventCreateWithFlags(&evRBF, cudaEventDisableTiming);
        for (int i = 0; i < 3; i++) {
            cudaEventCreateWithFlags(&evA[i], cudaEventDisableTiming);
            cudaEventCreateWithFlags(&evB[i], cudaEventDisableTiming);
            cudaEventCreateWithFlags(&evC[i], cudaEventDisableTiming);
        }
        cudaFuncSetAttribute((const void*)fused_t_ee,    cudaFuncAttributeMaxDynamicSharedMemorySize, DSMEM4);
        cudaFuncSetAttribute((const void*)gemm_mma<1,0>, cudaFuncAttributeMaxDynamicSharedMemorySize, DSMEM2);
        cudaFuncSetAttribute((const void*)gemm_mma<0,0>, cudaFuncAttributeMaxDynamicSharedMemorySize, DSMEM2);
        cudaFuncSetAttribute((const void*)gemm_mma<3,2>, cudaFuncAttributeMaxDynamicSharedMemorySize, DSMEM2);
        sinit = true;
    }

    void* p;
    float *h, *ee, *tmp, *P;
    __nv_bfloat16 *W1h,*W1l,*We2h,*We2l,*Wn1h,*Wn1l,*Wn2h,*Wn2l,*Wch,*Wcl,*Wr1h,*Wr1l;
    cudaGetSymbolAddress(&p, g_h);   h   = (float*)p;
    cudaGetSymbolAddress(&p, g_ee);  ee  = (float*)p;
    cudaGetSymbolAddress(&p, g_tmp); tmp = (float*)p;
    cudaGetSymbolAddress(&p, g_P);   P   = (float*)p;
    cudaGetSymbolAddress(&p, g_W1h);  W1h  = (__nv_bfloat16*)p;
    cudaGetSymbolAddress(&p, g_W1l);  W1l  = (__nv_bfloat16*)p;
    cudaGetSymbolAddress(&p, g_We2h); We2h = (__nv_bfloat16*)p;
    cudaGetSymbolAddress(&p, g_We2l); We2l = (__nv_bfloat16*)p;
    cudaGetSymbolAddress(&p, g_Wn1h); Wn1h = (__nv_bfloat16*)p;
    cudaGetSymbolAddress(&p, g_Wn1l); Wn1l = (__nv_bfloat16*)p;
    cudaGetSymbolAddress(&p, g_Wn2h); Wn2h = (__nv_bfloat16*)p;
    cudaGetSymbolAddress(&p, g_Wn2l); Wn2l = (__nv_bfloat16*)p;
    cudaGetSymbolAddress(&p, g_Wch);  Wch  = (__nv_bfloat16*)p;
    cudaGetSymbolAddress(&p, g_Wcl);  Wcl  = (__nv_bfloat16*)p;
    cudaGetSymbolAddress(&p, g_Wr1h); Wr1h = (__nv_bfloat16*)p;
    cudaGetSymbolAddress(&p, g_Wr1l); Wr1l = (__nv_bfloat16*)p;

    int gE = (E + 127)/128, gE2 = (E + 63)/64, gN = (N + 127)/128;

    cudaEventRecord(evF, 0);
    cudaStreamWaitEvent(s1, evF, 0);
    cudaStreamWaitEvent(s2, evF, 0);

    // main: sort + rbf chain
    zero_hist_k<<<(2*NBUCK + 255)/256, 256>>>();
    hist_k<<<148, 512>>>(dist, E);
    scan512_k<<<1, NBUCK>>>();
    scatter_perm_k<<<148, 512>>>(dist, E);
    rbf_klo_k<<<gE2, 64>>>(dist, E);
    rbf_split_k<<<gE2, 64>>>(dist, E);
    cudaEventRecord(evRBF, 0);

    // s1: node-side prep
    init_h_k<<<(N*128 + 255)/256, 256, 0, s1>>>(Z, node_emb, h, N);
    for (int i = 0; i < 3; i++) {
        split_pad_k<<<(128*128 + 255)/256, 256, 0, s1>>>(Wn1 + (size_t)i*128*128, Wn1h + (size_t)i*128*128, Wn1l + (size_t)i*128*128, 128, 128, 128, 0, 128, 128*128);
        split_pad_k<<<(128*128 + 255)/256, 256, 0, s1>>>(Wn2 + (size_t)i*128*128, Wn2h + (size_t)i*128*128, Wn2l + (size_t)i*128*128, 128, 128, 128, 0, 128, 128*128);
    }
    split_pad_k<<<(128*128 + 255)/256, 256, 0, s1>>>(Wr1, Wr1h, Wr1l, 128, 128, 128, 0, 128, 128*128);

    // s2: edge-side prep
    for (int i = 0; i < 3; i++) {
        split_pad_k<<<(512*384 + 255)/256, 256, 0, s2>>>(We1 + (size_t)i*428*428, W1h + (size_t)i*512*384, W1l + (size_t)i*512*384, 428, 300, 428, 128, 384, 512*384);
        split_pad_k<<<(128*448 + 255)/256, 256, 0, s2>>>(We2 + (size_t)i*128*428, We2h + (size_t)i*128*448, We2l + (size_t)i*128*448, 128, 428, 428, 0, 448, 128*448);
        split_pad_k<<<(128*128 + 255)/256, 256, 0, s2>>>(Wc  + (size_t)i*128*128, Wch  + (size_t)i*128*128, Wcl  + (size_t)i*128*128, 128, 128, 128, 0, 128, 128*128);
    }
    p_kernel<<<dim3(400, 3), 448, 0, s2>>>(edge_emb, We1, be1, P);
    cudaStreamWaitEvent(s2, evRBF, 0);

    for (int i = 0; i < 3; i++) {
        float* eeb = ee + (size_t)(i & 1) * E_MAXE * 128;
        if (i >= 2) cudaStreamWaitEvent(s2, evC[i-2], 0);
        fused_t_ee<<<gE2, 256, DSMEM4, s2>>>(W1h + (size_t)i*512*384, W1l + (size_t)i*512*384,
                                             We2h + (size_t)i*128*448, We2l + (size_t)i*128*448,
                                             P + (size_t)i*400*428, be2 + i*128, etype, eeb, E);
        cudaEventRecord(evB[i], s2);

        if (i >= 1) cudaStreamWaitEvent(s1, evC[i-1], 0);
        gemm_mma<1,0><<<gN, 256, DSMEM2, s1>>>(h, nullptr, 128, 128,
            Wn1h + (size_t)i*128*128, Wn1l + (size_t)i*128*128, 128,
            bn1 + i*128, tmp, N, nullptr, nullptr, nullptr);
        gemm_mma<0,0><<<gN, 256, DSMEM2, s1>>>(tmp, nullptr, 128, 128,
            Wn2h + (size_t)i*128*128, Wn2l + (size_t)i*128*128, 128,
            bn2 + i*128, tmp, N, nullptr, nullptr, nullptr);
        cudaEventRecord(evA[i], s1);

        cudaStreamWaitEvent(0, evA[i], 0);
        cudaStreamWaitEvent(0, evB[i], 0);
        gemm_mma<3,2><<<gE, 256, DSMEM2, 0>>>(tmp, eeb, 128, 128,
            Wch + (size_t)i*128*128, Wcl + (size_t)i*128*128, 128,
            bc + i*128, nullptr, E, src, dst, h);
        cudaEventRecord(evC[i], 0);
    }

    gemm_mma<1,0><<<gN, 256, DSMEM2, 0>>>(h, nullptr, 128, 128,
        Wr1h, Wr1l, 128, br1, tmp, N, nullptr, nullptr, nullptr);
    zero_f_k<<<(G + 255)/256, 256>>>(out, G);
    readout2_k<<<(N + 3)/4, 128>>>(tmp, Wr2, br2, gid, out, N);
}

// round 10
// speedup vs baseline: 1.4669x; 1.0658x over previous
#include <cuda_runtime.h>
#include <cuda_bf16.h>
#include <math.h>
#include <stdint.h>

#define N_RBF 300
#define NBUCK 512
#define N_MAXN 100352
#define E_MAXE 400384
#define GE2_MAX 6256
#define RBF_STEP (30.0f/299.0f)
#define RBF_INV  (299.0f/30.0f)
#define SLD 40
#define WK 32
#define BUFB 10240
#define DSMEM2 81920
#define DSMEM4 71680

__device__ float g_h  [(size_t)N_MAXN*128];
__device__ float g_ee [2*(size_t)E_MAXE*128];
__device__ float g_tmp[(size_t)N_MAXN*128];
__device__ float g_P  [3*400*428];
__device__ int   g_perm[E_MAXE];
__device__ int   g_hist[2*NBUCK];
__device__ int   g_klo [GE2_MAX];
__device__ __nv_bfloat16 g_rAh[(size_t)E_MAXE*WK],  g_rAl[(size_t)E_MAXE*WK];
__device__ __nv_bfloat16 g_W1h[3*512*384],  g_W1l[3*512*384];
__device__ __nv_bfloat16 g_We2h[3*128*448], g_We2l[3*128*448];
__device__ __nv_bfloat16 g_Wn1h[3*128*128], g_Wn1l[3*128*128];
__device__ __nv_bfloat16 g_Wn2h[3*128*128], g_Wn2l[3*128*128];
__device__ __nv_bfloat16 g_Wch [3*128*128], g_Wcl [3*128*128];
__device__ __nv_bfloat16 g_Wr1h[128*128],   g_Wr1l[128*128];

__device__ __forceinline__ uint32_t smem_u32(const void* p) {
    uint32_t a;
    asm("{ .reg .u64 t; cvta.to.shared.u64 t, %1; cvt.u32.u64 %0, t; }" : "=r"(a) : "l"(p));
    return a;
}
__device__ __forceinline__ void ldmx4(uint32_t& r0, uint32_t& r1, uint32_t& r2, uint32_t& r3, uint32_t a) {
    asm volatile("ldmatrix.sync.aligned.m8n8.x4.shared.b16 {%0,%1,%2,%3}, [%4];"
        : "=r"(r0), "=r"(r1), "=r"(r2), "=r"(r3) : "r"(a));
}
__device__ __forceinline__ void mma16816(float* c, const uint32_t* a, const uint32_t* b) {
    asm volatile("mma.sync.aligned.m16n8k16.row.col.f32.bf16.bf16.f32 "
        "{%0,%1,%2,%3},{%4,%5,%6,%7},{%8,%9},{%0,%1,%2,%3};"
        : "+f"(c[0]), "+f"(c[1]), "+f"(c[2]), "+f"(c[3])
        : "r"(a[0]), "r"(a[1]), "r"(a[2]), "r"(a[3]), "r"(b[0]), "r"(b[1]));
}
__device__ __forceinline__ void pack2(float a, float b, uint32_t& h, uint32_t& l) {
    __nv_bfloat162 hb = __floats2bfloat162_rn(a, b);
    __nv_bfloat162 lb = __floats2bfloat162_rn(a - __low2float(hb), b - __high2float(hb));
    h = *reinterpret_cast<uint32_t*>(&hb);
    l = *reinterpret_cast<uint32_t*>(&lb);
}
__device__ __forceinline__ void redv2(float* addr, float v0, float v1) {
    asm volatile("red.global.add.v2.f32 [%0], {%1,%2};" :: "l"(addr), "f"(v0), "f"(v1) : "memory");
}
#define CPA16(dst, src) asm volatile("cp.async.cg.shared.global [%0], [%1], 16;" :: "r"(dst), "l"(src))
#define CPC()  asm volatile("cp.async.commit_group;" ::: "memory")
#define CPW0() asm volatile("cp.async.wait_group 0;" ::: "memory")

__global__ void zero_hist_k() { int i = blockIdx.x*256 + threadIdx.x; if (i < 2*NBUCK) g_hist[i] = 0; }
__global__ void zero_f_k(float* p, int n) { int i = blockIdx.x*256 + threadIdx.x; if (i < n) p[i] = 0.f; }
__device__ __forceinline__ int bucket_of(float d) {
    int b = (int)(d * (512.0f/30.0f));
    return min(max(b, 0), NBUCK-1);
}
__global__ void hist_k(const float* __restrict__ dist, int E) {
    __shared__ int lh[NBUCK];
    int tid = threadIdx.x;
    int per = (E + gridDim.x - 1) / gridDim.x;
    int lo = blockIdx.x * per, hi = min(E, lo + per);
    for (int i = tid; i < NBUCK; i += 512) lh[i] = 0;
    __syncthreads();
    for (int e = lo + tid; e < hi; e += 512) atomicAdd(&lh[bucket_of(dist[e])], 1);
    __syncthreads();
    for (int i = tid; i < NBUCK; i += 512) if (lh[i]) atomicAdd(&g_hist[i], lh[i]);
}
__global__ void scan512_k() {
    __shared__ int s[NBUCK];
    int tid = threadIdx.x;
    int v0 = g_hist[tid];
    s[tid] = v0; __syncthreads();
    for (int off = 1; off < NBUCK; off <<= 1) {
        int v = 0;
        if (tid >= off) v = s[tid - off];
        __syncthreads(); s[tid] += v; __syncthreads();
    }
    g_hist[NBUCK + tid] = s[tid] - v0;
}
__global__ void scatter_perm_k(const float* __restrict__ dist, int E) {
    __shared__ int lh[NBUCK], base[NBUCK];
    int tid = threadIdx.x;
    int per = (E + gridDim.x - 1) / gridDim.x;
    int lo = blockIdx.x * per, hi = min(E, lo + per);
    for (int i = tid; i < NBUCK; i += 512) lh[i] = 0;
    __syncthreads();
    for (int e = lo + tid; e < hi; e += 512) atomicAdd(&lh[bucket_of(dist[e])], 1);
    __syncthreads();
    for (int i = tid; i < NBUCK; i += 512)
        base[i] = lh[i] ? atomicAdd(&g_hist[NBUCK + i], lh[i]) : 0;
    __syncthreads();
    for (int i = tid; i < NBUCK; i += 512) lh[i] = 0;
    __syncthreads();
    for (int e = lo + tid; e < hi; e += 512) {
        int b = bucket_of(dist[e]);
        int r = atomicAdd(&lh[b], 1);
        g_perm[base[b] + r] = e;
    }
}
__global__ void init_h_k(const int* __restrict__ Z, const float* __restrict__ ne,
                         float* __restrict__ h, int N) {
    int idx = blockIdx.x*256 + threadIdx.x;
    if (idx < N*128) h[idx] = ne[Z[idx >> 7]*128 + (idx & 127)];
}
__global__ void split_pad_k(const float* __restrict__ src, __nv_bfloat16* __restrict__ dh,
                            __nv_bfloat16* __restrict__ dl,
                            int R, int Ks, int ld, int off, int Kpad, int tot) {
    int idx = blockIdx.x*256 + threadIdx.x;
    if (idx < tot) {
        int r = idx / Kpad, k = idx % Kpad;
        float v = (r < R && k < Ks) ? src[(size_t)r*ld + off + k] : 0.f;
        __nv_bfloat16 h = __float2bfloat16(v);
        dh[idx] = h;
        dl[idx] = __float2bfloat16(v - __bfloat162float(h));
    }
}
__global__ void p_kernel(const float* __restrict__ edge_emb, const float* __restrict__ We1,
                         const float* __restrict__ be1, float* __restrict__ P) {
    int ty = blockIdx.x, layer = blockIdx.y, j = threadIdx.x;
    __shared__ float em[128];
    if (j < 128) em[j] = edge_emb[ty*128 + j];
    __syncthreads();
    if (j < 428) {
        const float* wrow = We1 + ((size_t)layer*428 + j)*428;
        float acc = be1[layer*428 + j];
        #pragma unroll 8
        for (int k = 0; k < 128; k++) acc = fmaf(em[k], wrow[k], acc);
        P[((size_t)layer*400 + ty)*428 + j] = acc;
    }
}
__global__ void rbf_klo_k(const float* __restrict__ dist, int E) {
    __shared__ float s[64];
    int tid = threadIdx.x, gr = blockIdx.x*64 + tid;
    s[tid] = dist[g_perm[min(gr, E-1)]];
    __syncthreads();
    for (int o = 32; o > 0; o >>= 1) {
        if (tid < o) s[tid] = fminf(s[tid], s[tid + o]);
        __syncthreads();
    }
    if (tid == 0) {
        int k = (int)floorf((s[0] - 1.055f) * RBF_INV);
        if (k < 0) k = 0;
        g_klo[blockIdx.x] = k & ~7;
    }
}
__global__ void rbf_split_k(const float* __restrict__ dist, int E) {
    int tid = threadIdx.x, gr = blockIdx.x*64 + tid;
    float d = dist[g_perm[min(gr, E-1)]];
    int k0 = g_klo[blockIdx.x];
    float vals[WK];
    #pragma unroll
    for (int i = 0; i < WK; i++) vals[i] = 0.f;
    int icen = (int)(d * RBF_INV) - k0;
    int ilo = max(0, icen - 10);
    int ihi = min(min(WK-1, icen + 10), 299 - k0);
    for (int i = ilo; i <= ihi; i++) {
        float x = d - (float)(k0 + i) * RBF_STEP;
        vals[i] = __expf(-RBF_INV * x * x);
    }
    size_t base = (size_t)gr * WK;
    #pragma unroll
    for (int i = 0; i < WK; i += 8) {
        uint4 H, L;
        pack2(vals[i+0], vals[i+1], H.x, L.x);
        pack2(vals[i+2], vals[i+3], H.y, L.y);
        pack2(vals[i+4], vals[i+5], H.z, L.z);
        pack2(vals[i+6], vals[i+7], H.w, L.w);
        *(uint4*)(g_rAh + base + i) = H;
        *(uint4*)(g_rAl + base + i) = L;
    }
}

// ============ fused t -> ee kernel, 64-edge tiles, WK=32, 2 CTAs/SM ============
// smem: Th 0..5120, Tl 5120..10240, Ah 10240..15360, Al 15360..20480,
// W1h 20480(2x2560), W1l 25600(2x2560), W2h 30720(2x10240), W2l 51200(2x10240) = 71680
__global__ void __launch_bounds__(256, 2)
fused_t_ee(const __nv_bfloat16* __restrict__ W1h, const __nv_bfloat16* __restrict__ W1l,
           const __nv_bfloat16* __restrict__ W2h, const __nv_bfloat16* __restrict__ W2l,
           const float* __restrict__ P, const float* __restrict__ be2,
           const int* __restrict__ etype, float* __restrict__ ee, int E) {
    extern __shared__ char ds[];
    __shared__ int sety[64];
    __shared__ float sbias[128];
    int tid = threadIdx.x, lane = tid & 31, warp = tid >> 5, bx = blockIdx.x;
    int klo = g_klo[bx];
    if (tid < 64) sety[tid] = etype[g_perm[min(bx*64 + tid, E-1)]];
    if (tid < 128) sbias[tid] = be2[tid];
    uint32_t b0 = smem_u32(ds);
    uint32_t uTh = b0,          uTl = b0 + 5120;
    uint32_t uAh = b0 + 10240,  uAl = b0 + 15360;
    uint32_t uW1h = b0 + 20480, uW1l = b0 + 25600;
    uint32_t uW2h = b0 + 30720, uW2l = b0 + 51200;

    // A tile 64xWK hi/lo (stride SLD)
    {
        int row = tid >> 2, kk = (tid & 3) << 3;
        uint32_t d = (uint32_t)(row*SLD + kk)*2;
        size_t s = (size_t)(bx*64 + row)*WK + kk;
        CPA16(uAh + d, g_rAh + s);
        CPA16(uAl + d, g_rAl + s);
    }
    // chunk 0 weights: W1 32 rows x 32 K, We2 128 rows x 32 K
    if (tid < 128) {
        int row = tid >> 2, kk = (tid & 3) << 3;
        uint32_t d = (uint32_t)(row*SLD + kk)*2;
        size_t s = (size_t)row*384 + klo + kk;
        CPA16(uW1h + d, W1h + s);
        CPA16(uW1l + d, W1l + s);
    }
    for (int i = tid; i < 512; i += 256) {
        int row = i >> 2, kk = (i & 3) * 8;
        uint32_t d = (uint32_t)(row*SLD + kk)*2;
        size_t s = (size_t)row*448 + kk;
        CPA16(uW2h + d, W2h + s);
        CPA16(uW2l + d, W2l + s);
    }
    CPC(); CPW0();
    __syncthreads();

    int arow = lane & 15, acol = (lane >> 4) << 3;
    int brow = (lane & 7) + ((lane >> 1) & 8), bcol = lane & 8;
    int r1 = (warp >> 1)*16, c1 = (warp & 1)*16;
    uint32_t a1off = (uint32_t)((r1 + arow)*SLD + acol)*2;
    uint32_t b1off = (uint32_t)((c1 + brow)*SLD + bcol)*2;
    int m0 = (warp >> 2)*32, n0 = (warp & 3)*32;
    uint32_t a2off[2];
    #pragma unroll
    for (int mi = 0; mi < 2; mi++) a2off[mi] = (uint32_t)((m0 + mi*16 + arow)*SLD + acol)*2;
    uint32_t b2off0 = (uint32_t)((n0 + brow)*SLD + bcol)*2;
    uint32_t b2off1 = (uint32_t)((n0 + 16 + brow)*SLD + bcol)*2;
    int lrow = lane >> 2, lcol = (lane & 3)*2;

    float eacc[2][4][4];
    #pragma unroll
    for (int mi = 0; mi < 2; mi++)
        #pragma unroll
        for (int ni = 0; ni < 4; ni++)
            #pragma unroll
            for (int q = 0; q < 4; q++) eacc[mi][ni][q] = 0.f;

    int buf = 0;
    for (int c = 0; c < 14; c++) {
        if (c < 13) {
            uint32_t cb = (uint32_t)(buf ^ 1);
            if (tid < 128) {
                int row = tid >> 2, kk = (tid & 3) << 3;
                uint32_t d = cb*2560 + (uint32_t)(row*SLD + kk)*2;
                size_t s = (size_t)((c+1)*32 + row)*384 + klo + kk;
                CPA16(uW1h + d, W1h + s);
                CPA16(uW1l + d, W1l + s);
            }
            for (int i = tid; i < 512; i += 256) {
                int row = i >> 2, kk = (i & 3) * 8;
                uint32_t d = cb*10240 + (uint32_t)(row*SLD + kk)*2;
                size_t s = (size_t)row*448 + (c+1)*32 + kk;
                CPA16(uW2h + d, W2h + s);
                CPA16(uW2l + d, W2l + s);
            }
            CPC();
        }
        // MMA1: t_chunk[64,32], K=32 (2 ks)
        float acc1[2][4];
        #pragma unroll
        for (int ni = 0; ni < 2; ni++)
            #pragma unroll
            for (int q = 0; q < 4; q++) acc1[ni][q] = 0.f;
        {
            uint32_t w1b = (uint32_t)buf * 2560;
            #pragma unroll
            for (int ks = 0; ks < 2; ks++) {
                uint32_t ah[4], al[4], bh[4], bl[4];
                ldmx4(ah[0], ah[1], ah[2], ah[3], uAh + a1off + ks*32);
                ldmx4(al[0], al[1], al[2], al[3], uAl + a1off + ks*32);
                ldmx4(bh[0], bh[1], bh[2], bh[3], uW1h + w1b + b1off + ks*32);
                ldmx4(bl[0], bl[1], bl[2], bl[3], uW1l + w1b + b1off + ks*32);
                #pragma unroll
                for (int ni = 0; ni < 2; ni++) {
                    mma16816(acc1[ni], ah, &bh[ni*2]);
                    mma16816(acc1[ni], ah, &bl[ni*2]);
                    mma16816(acc1[ni], al, &bh[ni*2]);
                }
            }
        }
        // epilogue1: +P, relu, pack -> sT
        {
            int gcb = c*32;
            #pragma unroll
            for (int half = 0; half < 2; half++) {
                int r = r1 + lrow + half*8;
                const float* Pr = P + (size_t)sety[r]*428;
                #pragma unroll
                for (int ni = 0; ni < 2; ni++) {
                    int col = c1 + ni*8 + lcol;
                    int gcol = gcb + col;
                    float v0 = 0.f, v1 = 0.f;
                    if (gcol < 428) {
                        float2 pv = *(const float2*)(Pr + gcol);
                        v0 = fmaxf(acc1[ni][half*2+0] + pv.x, 0.f);
                        v1 = fmaxf(acc1[ni][half*2+1] + pv.y, 0.f);
                    }
                    uint32_t H, L;
                    pack2(v0, v1, H, L);
                    uint32_t doff = (uint32_t)(r*SLD + col)*2;
                    *(uint32_t*)(ds + doff) = H;
                    *(uint32_t*)(ds + 5120 + doff) = L;
                }
            }
        }
        __syncthreads();
        // MMA2: ee += t_chunk @ We2_chunk^T
        {
            uint32_t w2b = (uint32_t)buf * 10240;
            #pragma unroll
            for (int ks = 0; ks < 2; ks++) {
                uint32_t bh[8], bl[8];
                ldmx4(bh[0], bh[1], bh[2], bh[3], uW2h + w2b + b2off0 + ks*32);
                ldmx4(bh[4], bh[5], bh[6], bh[7], uW2h + w2b + b2off1 + ks*32);
                ldmx4(bl[0], bl[1], bl[2], bl[3], uW2l + w2b + b2off0 + ks*32);
                ldmx4(bl[4], bl[5], bl[6], bl[7], uW2l + w2b + b2off1 + ks*32);
                #pragma unroll
                for (int mi = 0; mi < 2; mi++) {
                    uint32_t ah[4], al[4];
                    ldmx4(ah[0], ah[1], ah[2], ah[3], uTh + a2off[mi] + ks*32);
                    ldmx4(al[0], al[1], al[2], al[3], uTl + a2off[mi] + ks*32);
                    #pragma unroll
                    for (int ni = 0; ni < 4; ni++) {
                        mma16816(eacc[mi][ni], ah, &bh[ni*2]);
                        mma16816(eacc[mi][ni], ah, &bl[ni*2]);
                        mma16816(eacc[mi][ni], al, &bh[ni*2]);
                    }
                }
            }
        }
        if (c < 13) CPW0();
        __syncthreads();
        buf ^= 1;
    }

    int rowb = bx*64 + m0;
    #pragma unroll
    for (int mi = 0; mi < 2; mi++) {
        #pragma unroll
        for (int half = 0; half < 2; half++) {
            int row = rowb + mi*16 + lrow + half*8;
            if (row < E) {
                size_t cb = (size_t)row * 128;
                #pragma unroll
                for (int ni = 0; ni < 4; ni++) {
                    int col = n0 + ni*8 + lcol;
                    float2 o;
                    o.x = eacc[mi][ni][half*2+0] + sbias[col];
                    o.y = eacc[mi][ni][half*2+1] + sbias[col+1];
                    *(float2*)(ee + cb + col) = o;
                }
            }
        }
    }
}

// ============ generic pipelined GEMM ============
// EPI: 0 store, 1 relu store, 3 tanh + red.v2 scatter to Hout[sidx[perm[row]]]
// AMODE: 0 fp32 rows direct; 2 product Af[gidx[perm[row]]]*A2[row]
template<int EPI, int AMODE>
__global__ void __launch_bounds__(256)
gemm_mma(const float* __restrict__ Af, const float* __restrict__ A2,
         int lda, int Kloop,
         const __nv_bfloat16* __restrict__ Bh, const __nv_bfloat16* __restrict__ Bl, int Kpad,
         const float* __restrict__ bias, float* __restrict__ C, int M,
         const int* __restrict__ gidx, const int* __restrict__ sidx, float* __restrict__ Hout) {
    extern __shared__ char ds[];
    __shared__ float sbias[128];
    int tid = threadIdx.x, lane = tid & 31, warp = tid >> 5;
    if (tid < 128) sbias[tid] = bias[tid];

    uint32_t b0 = smem_u32(ds);
    uint32_t uAh = b0, uAl = b0 + 2*BUFB, uBh = b0 + 4*BUFB, uBl = b0 + 6*BUFB;

    const float *p1[4], *p2[4];
    if (AMODE == 0) {
        #pragma unroll
        for (int i = 0; i < 4; i++) {
            int r = blockIdx.x*128 + i*32 + (tid >> 3);
            p1[i] = Af + (size_t)min(r, M-1) * lda;
        }
    } else {
        #pragma unroll
        for (int i = 0; i < 4; i++) {
            int r = blockIdx.x*128 + i*32 + (tid >> 3);
            int rc = min(r, M-1);
            p1[i] = Af + (size_t)gidx[g_perm[rc]] * 128;
            p2[i] = A2 + (size_t)rc * 128;
        }
    }
    int akoff = (tid & 7) << 2;
    int ckoff = (tid & 3) << 3;
    int crow  = tid >> 2;
    uint32_t cdst0 = ((uint32_t)crow * SLD + ckoff) * 2;
    uint32_t cdst1 = ((uint32_t)(crow + 64) * SLD + ckoff) * 2;
    uint32_t asts[4];
    #pragma unroll
    for (int i = 0; i < 4; i++) asts[i] = ((uint32_t)(i*32 + (tid >> 3)) * SLD + akoff) * 2;

    int m0 = (warp >> 2) * 64, n0 = (warp & 3) * 32;
    int arow = lane & 15, acol = (lane >> 4) << 3;
    int brow = (lane & 7) + ((lane >> 1) & 8), bcol = lane & 8;
    uint32_t aoff[4];
    #pragma unroll
    for (int mi = 0; mi < 4; mi++) aoff[mi] = ((m0 + mi*16 + arow)*SLD + acol) * 2;
    uint32_t boff0 = ((n0 + brow)*SLD + bcol) * 2;
    uint32_t boff1 = ((n0 + 16 + brow)*SLD + bcol) * 2;

    float acc[4][4][4];
    #pragma unroll
    for (int mi = 0; mi < 4; mi++)
        #pragma unroll
        for (int ni = 0; ni < 4; ni++)
            #pragma unroll
            for (int q = 0; q < 4; q++) acc[mi][ni][q] = 0.f;

    uint2 rAh[4], rAl[4];
    int nch = Kloop >> 5;

    {
        CPA16(uBh + cdst0, Bh + (size_t)crow * Kpad + ckoff);
        CPA16(uBh + cdst1, Bh + (size_t)(crow + 64) * Kpad + ckoff);
        CPA16(uBl + cdst0, Bl + (size_t)crow * Kpad + ckoff);
        CPA16(uBl + cdst1, Bl + (size_t)(crow + 64) * Kpad + ckoff);
        CPC();
        #pragma unroll
        for (int i = 0; i < 4; i++) {
            float4 f;
            if (AMODE == 0) f = *(const float4*)(p1[i] + akoff);
            else {
                float4 f1 = *(const float4*)(p1[i] + akoff);
                float4 f2 = *(const float4*)(p2[i] + akoff);
                f.x = f1.x*f2.x; f.y = f1.y*f2.y; f.z = f1.z*f2.z; f.w = f1.w*f2.w;
            }
            pack2(f.x, f.y, rAh[i].x, rAl[i].x);
            pack2(f.z, f.w, rAh[i].y, rAl[i].y);
        }
        #pragma unroll
        for (int i = 0; i < 4; i++) {
            *(uint2*)(ds + asts[i]) = rAh[i];
            *(uint2*)(ds + 2*BUFB + asts[i]) = rAl[i];
        }
        CPW0();
        __syncthreads();
    }

    int buf = 0;
    for (int c = 0; c < nch; c++) {
        int k1 = (c + 1) << 5;
        bool more = (c + 1) < nch;
        if (more) {
            uint32_t bb = (uint32_t)(buf ^ 1) * BUFB;
            CPA16(uBh + bb + cdst0, Bh + (size_t)crow * Kpad + k1 + ckoff);
            CPA16(uBh + bb + cdst1, Bh + (size_t)(crow + 64) * Kpad + k1 + ckoff);
            CPA16(uBl + bb + cdst0, Bl + (size_t)crow * Kpad + k1 + ckoff);
            CPA16(uBl + bb + cdst1, Bl + (size_t)(crow + 64) * Kpad + k1 + ckoff);
            CPC();
            #pragma unroll
            for (int i = 0; i < 4; i++) {
                float4 f;
                if (AMODE == 0) f = *(const float4*)(p1[i] + k1 + akoff);
                else {
                    float4 f1 = *(const float4*)(p1[i] + k1 + akoff);
                    float4 f2 = *(const float4*)(p2[i] + k1 + akoff);
                    f.x = f1.x*f2.x; f.y = f1.y*f2.y; f.z = f1.z*f2.z; f.w = f1.w*f2.w;
                }
                pack2(f.x, f.y, rAh[i].x, rAl[i].x);
                pack2(f.z, f.w, rAh[i].y, rAl[i].y);
            }
        }
        {
            uint32_t bb = (uint32_t)buf * BUFB;
            #pragma unroll
            for (int ks = 0; ks < 2; ks++) {
                uint32_t bh[8], bl[8];
                ldmx4(bh[0], bh[1], bh[2], bh[3], uBh + bb + boff0 + ks*32);
                ldmx4(bh[4], bh[5], bh[6], bh[7], uBh + bb + boff1 + ks*32);
                ldmx4(bl[0], bl[1], bl[2], bl[3], uBl + bb + boff0 + ks*32);
                ldmx4(bl[4], bl[5], bl[6], bl[7], uBl + bb + boff1 + ks*32);
                #pragma unroll
                for (int mi = 0; mi < 4; mi++) {
                    uint32_t ah[4], al[4];
                    ldmx4(ah[0], ah[1], ah[2], ah[3], uAh + bb + aoff[mi] + ks*32);
                    ldmx4(al[0], al[1], al[2], al[3], uAl + bb + aoff[mi] + ks*32);
                    #pragma unroll
                    for (int ni = 0; ni < 4; ni++) {
                        mma16816(acc[mi][ni], ah, &bh[ni*2]);
                        mma16816(acc[mi][ni], ah, &bl[ni*2]);
                        mma16816(acc[mi][ni], al, &bh[ni*2]);
                    }
                }
            }
        }
        if (more) {
            uint32_t bb = (uint32_t)(buf ^ 1) * BUFB;
            #pragma unroll
            for (int i = 0; i < 4; i++) {
                *(uint2*)(ds + bb + asts[i]) = rAh[i];
                *(uint2*)(ds + 2*BUFB + bb + asts[i]) = rAl[i];
            }
            CPW0();
            __syncthreads();
            buf ^= 1;
        }
    }

    int rowb = blockIdx.x*128 + m0;
    #pragma unroll
    for (int mi = 0; mi < 4; mi++) {
        #pragma unroll
        for (int half = 0; half < 2; half++) {
            int row = rowb + mi*16 + (lane >> 2) + half*8;
            if (row < M) {
                if (EPI == 3) {
                    int dg = sidx[g_perm[row]];
                    float* Hr = Hout + (size_t)dg * 128;
                    #pragma unroll
                    for (int ni = 0; ni < 4; ni++) {
                        int col = n0 + ni*8 + (lane & 3)*2;
                        float v0 = tanhf(acc[mi][ni][half*2+0] + sbias[col]);
                        float v1 = tanhf(acc[mi][ni][half*2+1] + sbias[col+1]);
                        redv2(Hr + col, v0, v1);
                    }
                } else {
                    size_t cb = (size_t)row * 128;
                    #pragma unroll
                    for (int ni = 0; ni < 4; ni++) {
                        int col = n0 + ni*8 + (lane & 3)*2;
                        float v0 = acc[mi][ni][half*2+0] + sbias[col];
                        float v1 = acc[mi][ni][half*2+1] + sbias[col+1];
                        if (EPI == 1) { v0 = fmaxf(v0, 0.f); v1 = fmaxf(v1, 0.f); }
                        float2 o = make_float2(v0, v1);
                        *(float2*)(C + cb + col) = o;
                    }
                }
            }
        }
    }
}

__global__ void readout2_k(const float* __restrict__ rr, const float* __restrict__ Wr2,
                           const float* __restrict__ br2, const int* __restrict__ gid,
                           float* __restrict__ out, int N) {
    __shared__ float w[128];
    int tid = threadIdx.x;
    if (tid < 128) w[tid] = Wr2[tid];
    __syncthreads();
    int warp = tid >> 5, lane = tid & 31;
    int n = blockIdx.x*4 + warp;
    if (n >= N) return;
    const float* hr = rr + (size_t)n * 128;
    float s = 0.f;
    #pragma unroll
    for (int i = 0; i < 4; i++) s = fmaf(hr[lane + i*32], w[lane + i*32], s);
    #pragma unroll
    for (int o = 16; o > 0; o >>= 1) s += __shfl_down_sync(0xffffffffu, s, o);
    if (lane == 0) atomicAdd(&out[gid[n]], s + br2[0]);
}

extern "C" void kernel_launch(void* const* d_in, const int* in_sizes, int n_in,
                              void* d_out, int out_size) {
    const int*   Z     = (const int*)  d_in[0];
    const int*   etype = (const int*)  d_in[1];
    const float* dist  = (const float*)d_in[2];
    const int*   src   = (const int*)  d_in[3];
    const int*   dst   = (const int*)  d_in[4];
    const int*   gid   = (const int*)  d_in[5];
    const float* node_emb = (const float*)d_in[6];
    const float* edge_emb = (const float*)d_in[7];
    const float* Wn1 = (const float*)d_in[8];
    const float* bn1 = (const float*)d_in[9];
    const float* Wn2 = (const float*)d_in[10];
    const float* bn2 = (const float*)d_in[11];
    const float* We1 = (const float*)d_in[12];
    const float* be1 = (const float*)d_in[13];
    const float* We2 = (const float*)d_in[14];
    const float* be2 = (const float*)d_in[15];
    const float* Wc  = (const float*)d_in[16];
    const float* bc  = (const float*)d_in[17];
    const float* Wr1 = (const float*)d_in[18];
    const float* br1 = (const float*)d_in[19];
    const float* Wr2 = (const float*)d_in[20];
    const float* br2 = (const float*)d_in[21];

    int N = in_sizes[0], E = in_sizes[1], G = out_size;
    float* out = (float*)d_out;

    static cudaStream_t s1 = 0, s2 = 0;
    static cudaEvent_t evF, evRBF, evA[3], evB[3], evC[3];
    static bool sinit = false;
    if (!sinit) {
        cudaStreamCreateWithFlags(&s1, cudaStreamNonBlocking);
        cudaStreamCreateWithFlags(&s2, cudaStreamNonBlocking);
        cudaEventCreateWithFlags(&evF,   cudaEventDisableTiming);
        cudaEventCreateWithFlags(&evRBF, cudaEventDisableTiming);
        for (int i = 0; i < 3; i++) {
            cudaEventCreateWithFlags(&evA[i], cudaEventDisableTiming);
            cudaEventCreateWithFlags(&evB[i], cudaEventDisableTiming);
            cudaEventCreateWithFlags(&evC[i], cudaEventDisableTiming);
        }
        cudaFuncSetAttribute((const void*)fused_t_ee,    cudaFuncAttributeMaxDynamicSharedMemorySize, DSMEM4);
        cudaFuncSetAttribute((const void*)gemm_mma<1,0>, cudaFuncAttributeMaxDynamicSharedMemorySize, DSMEM2);
        cudaFuncSetAttribute((const void*)gemm_mma<0,0>, cudaFuncAttributeMaxDynamicSharedMemorySize, DSMEM2);
        cudaFuncSetAttribute((const void*)gemm_mma<3,2>, cudaFuncAttributeMaxDynamicSharedMemorySize, DSMEM2);
        sinit = true;
    }

    void* p;
    float *h, *ee, *tmp, *P;
    __nv_bfloat16 *W1h,*W1l,*We2h,*We2l,*Wn1h,*Wn1l,*Wn2h,*Wn2l,*Wch,*Wcl,*Wr1h,*Wr1l;
    cudaGetSymbolAddress(&p, g_h);   h   = (float*)p;
    cudaGetSymbolAddress(&p, g_ee);  ee  = (float*)p;
    cudaGetSymbolAddress(&p, g_tmp); tmp = (float*)p;
    cudaGetSymbolAddress(&p, g_P);   P   = (float*)p;
    cudaGetSymbolAddress(&p, g_W1h);  W1h  = (__nv_bfloat16*)p;
    cudaGetSymbolAddress(&p, g_W1l);  W1l  = (__nv_bfloat16*)p;
    cudaGetSymbolAddress(&p, g_We2h); We2h = (__nv_bfloat16*)p;
    cudaGetSymbolAddress(&p, g_We2l); We2l = (__nv_bfloat16*)p;
    cudaGetSymbolAddress(&p, g_Wn1h); Wn1h = (__nv_bfloat16*)p;
    cudaGetSymbolAddress(&p, g_Wn1l); Wn1l = (__nv_bfloat16*)p;
    cudaGetSymbolAddress(&p, g_Wn2h); Wn2h = (__nv_bfloat16*)p;
    cudaGetSymbolAddress(&p, g_Wn2l); Wn2l = (__nv_bfloat16*)p;
    cudaGetSymbolAddress(&p, g_Wch);  Wch  = (__nv_bfloat16*)p;
    cudaGetSymbolAddress(&p, g_Wcl);  Wcl  = (__nv_bfloat16*)p;
    cudaGetSymbolAddress(&p, g_Wr1h); Wr1h = (__nv_bfloat16*)p;
    cudaGetSymbolAddress(&p, g_Wr1l); Wr1l = (__nv_bfloat16*)p;

    int gE = (E + 127)/128, gE2 = (E + 63)/64, gN = (N + 127)/128;

    cudaEventRecord(evF, 0);
    cudaStreamWaitEvent(s1, evF, 0);
    cudaStreamWaitEvent(s2, evF, 0);

    // main: sort + rbf chain
    zero_hist_k<<<(2*NBUCK + 255)/256, 256>>>();
    hist_k<<<148, 512>>>(dist, E);
    scan512_k<<<1, NBUCK>>>();
    scatter_perm_k<<<148, 512>>>(dist, E);
    rbf_klo_k<<<gE2, 64>>>(dist, E);
    rbf_split_k<<<gE2, 64>>>(dist, E);
    cudaEventRecord(evRBF, 0);

    // s1: node-side prep
    init_h_k<<<(N*128 + 255)/256, 256, 0, s1>>>(Z, node_emb, h, N);
    for (int i = 0; i < 3; i++) {
        split_pad_k<<<(128*128 + 255)/256, 256, 0, s1>>>(Wn1 + (size_t)i*128*128, Wn1h + (size_t)i*128*128, Wn1l + (size_t)i*128*128, 128, 128, 128, 0, 128, 128*128);
        split_pad_k<<<(128*128 + 255)/256, 256, 0, s1>>>(Wn2 + (size_t)i*128*128, Wn2h + (size_t)i*128*128, Wn2l + (size_t)i*128*128, 128, 128, 128, 0, 128, 128*128);
    }
    split_pad_k<<<(128*128 + 255)/256, 256, 0, s1>>>(Wr1, Wr1h, Wr1l, 128, 128, 128, 0, 128, 128*128);

    // s2: edge-side prep
    for (int i = 0; i < 3; i++) {
        split_pad_k<<<(512*384 + 255)/256, 256, 0, s2>>>(We1 + (size_t)i*428*428, W1h + (size_t)i*512*384, W1l + (size_t)i*512*384, 428, 300, 428, 128, 384, 512*384);
        split_pad_k<<<(128*448 + 255)/256, 256, 0, s2>>>(We2 + (size_t)i*128*428, We2h + (size_t)i*128*448, We2l + (size_t)i*128*448, 128, 428, 428, 0, 448, 128*448);
        split_pad_k<<<(128*128 + 255)/256, 256, 0, s2>>>(Wc  + (size_t)i*128*128, Wch  + (size_t)i*128*128, Wcl  + (size_t)i*128*128, 128, 128, 128, 0, 128, 128*128);
    }
    p_kernel<<<dim3(400, 3), 448, 0, s2>>>(edge_emb, We1, be1, P);
    cudaStreamWaitEvent(s2, evRBF, 0);

    for (int i = 0; i < 3; i++) {
        float* eeb = ee + (size_t)(i & 1) * E_MAXE * 128;
        if (i >= 2) cudaStreamWaitEvent(s2, evC[i-2], 0);
        fused_t_ee<<<gE2, 256, DSMEM4, s2>>>(W1h + (size_t)i*512*384, W1l + (size_t)i*512*384,
                                             We2h + (size_t)i*128*448, We2l + (size_t)i*128*448,
                                             P + (size_t)i*400*428, be2 + i*128, etype, eeb, E);
        cudaEventRecord(evB[i], s2);

        if (i >= 1) cudaStreamWaitEvent(s1, evC[i-1], 0);
        gemm_mma<1,0><<<gN, 256, DSMEM2, s1>>>(h, nullptr, 128, 128,
            Wn1h + (size_t)i*128*128, Wn1l + (size_t)i*128*128, 128,
            bn1 + i*128, tmp, N, nullptr, nullptr, nullptr);
        gemm_mma<0,0><<<gN, 256, DSMEM2, s1>>>(tmp, nullptr, 128, 128,
            Wn2h + (size_t)i*128*128, Wn2l + (size_t)i*128*128, 128,
            bn2 + i*128, tmp, N, nullptr, nullptr, nullptr);
        cudaEventRecord(evA[i], s1);

        cudaStreamWaitEvent(0, evA[i], 0);
        cudaStreamWaitEvent(0, evB[i], 0);
        gemm_mma<3,2><<<gE, 256, DSMEM2, 0>>>(tmp, eeb, 128, 128,
            Wch + (size_t)i*128*128, Wcl + (size_t)i*128*128, 128,
            bc + i*128, nullptr, E, src, dst, h);
        cudaEventRecord(evC[i], 0);
    }

    gemm_mma<1,0><<<gN, 256, DSMEM2, 0>>>(h, nullptr, 128, 128,
        Wr1h, Wr1l, 128, br1, tmp, N, nullptr, nullptr, nullptr);
    zero_f_k<<<(G + 255)/256, 256>>>(out, G);
    readout2_k<<<(N + 3)/4, 128>>>(tmp, Wr2, br2, gid, out, N);
}

// round 11
// speedup vs baseline: 1.6312x; 1.1120x over previous
#include <cuda_runtime.h>
#include <cuda_fp16.h>
#include <math.h>
#include <stdint.h>

#define N_RBF 300
#define NBUCK 512
#define N_MAXN 100352
#define E_MAXE 400384
#define GE2_MAX 6256
#define RBF_STEP (30.0f/299.0f)
#define RBF_INV  (299.0f/30.0f)
#define SLD 40
#define WK 32
#define BUFB 10240
#define DSMEM2 61440
#define DSMEM4 61440

__device__ float g_h  [(size_t)N_MAXN*128];
__device__ float g_ee [2*(size_t)E_MAXE*128];
__device__ float g_tmp[(size_t)N_MAXN*128];
__device__ float g_P  [3*400*428];
__device__ int   g_perm[E_MAXE];
__device__ int   g_hist[2*NBUCK];
__device__ int   g_klo [GE2_MAX];
__device__ __half g_rAh[(size_t)E_MAXE*WK];
__device__ __half g_W1h[3*512*384],  g_W1l[3*512*384];
__device__ __half g_We2h[3*128*448], g_We2l[3*128*448];
__device__ __half g_Wn1h[3*128*128], g_Wn1l[3*128*128];
__device__ __half g_Wn2h[3*128*128], g_Wn2l[3*128*128];
__device__ __half g_Wch [3*128*128], g_Wcl [3*128*128];
__device__ __half g_Wr1h[128*128],   g_Wr1l[128*128];

__device__ __forceinline__ uint32_t smem_u32(const void* p) {
    uint32_t a;
    asm("{ .reg .u64 t; cvta.to.shared.u64 t, %1; cvt.u32.u64 %0, t; }" : "=r"(a) : "l"(p));
    return a;
}
__device__ __forceinline__ void ldmx4(uint32_t& r0, uint32_t& r1, uint32_t& r2, uint32_t& r3, uint32_t a) {
    asm volatile("ldmatrix.sync.aligned.m8n8.x4.shared.b16 {%0,%1,%2,%3}, [%4];"
        : "=r"(r0), "=r"(r1), "=r"(r2), "=r"(r3) : "r"(a));
}
__device__ __forceinline__ void mma16816(float* c, const uint32_t* a, const uint32_t* b) {
    asm volatile("mma.sync.aligned.m16n8k16.row.col.f32.f16.f16.f32 "
        "{%0,%1,%2,%3},{%4,%5,%6,%7},{%8,%9},{%0,%1,%2,%3};"
        : "+f"(c[0]), "+f"(c[1]), "+f"(c[2]), "+f"(c[3])
        : "r"(a[0]), "r"(a[1]), "r"(a[2]), "r"(a[3]), "r"(b[0]), "r"(b[1]));
}
__device__ __forceinline__ uint32_t packh(float a, float b) {
    __half2 t = __floats2half2_rn(a, b);
    return *reinterpret_cast<uint32_t*>(&t);
}
__device__ __forceinline__ void redv2(float* addr, float v0, float v1) {
    asm volatile("red.global.add.v2.f32 [%0], {%1,%2};" :: "l"(addr), "f"(v0), "f"(v1) : "memory");
}
#define CPA16(dst, src) asm volatile("cp.async.cg.shared.global [%0], [%1], 16;" :: "r"(dst), "l"(src))
#define CPC()  asm volatile("cp.async.commit_group;" ::: "memory")
#define CPW0() asm volatile("cp.async.wait_group 0;" ::: "memory")

__global__ void zero_hist_k() { int i = blockIdx.x*256 + threadIdx.x; if (i < 2*NBUCK) g_hist[i] = 0; }
__global__ void zero_f_k(float* p, int n) { int i = blockIdx.x*256 + threadIdx.x; if (i < n) p[i] = 0.f; }
__device__ __forceinline__ int bucket_of(float d) {
    int b = (int)(d * (512.0f/30.0f));
    return min(max(b, 0), NBUCK-1);
}
__global__ void hist_k(const float* __restrict__ dist, int E) {
    __shared__ int lh[NBUCK];
    int tid = threadIdx.x;
    int per = (E + gridDim.x - 1) / gridDim.x;
    int lo = blockIdx.x * per, hi = min(E, lo + per);
    for (int i = tid; i < NBUCK; i += 512) lh[i] = 0;
    __syncthreads();
    for (int e = lo + tid; e < hi; e += 512) atomicAdd(&lh[bucket_of(dist[e])], 1);
    __syncthreads();
    for (int i = tid; i < NBUCK; i += 512) if (lh[i]) atomicAdd(&g_hist[i], lh[i]);
}
__global__ void scan512_k() {
    __shared__ int s[NBUCK];
    int tid = threadIdx.x;
    int v0 = g_hist[tid];
    s[tid] = v0; __syncthreads();
    for (int off = 1; off < NBUCK; off <<= 1) {
        int v = 0;
        if (tid >= off) v = s[tid - off];
        __syncthreads(); s[tid] += v; __syncthreads();
    }
    g_hist[NBUCK + tid] = s[tid] - v0;
}
__global__ void scatter_perm_k(const float* __restrict__ dist, int E) {
    __shared__ int lh[NBUCK], base[NBUCK];
    int tid = threadIdx.x;
    int per = (E + gridDim.x - 1) / gridDim.x;
    int lo = blockIdx.x * per, hi = min(E, lo + per);
    for (int i = tid; i < NBUCK; i += 512) lh[i] = 0;
    __syncthreads();
    for (int e = lo + tid; e < hi; e += 512) atomicAdd(&lh[bucket_of(dist[e])], 1);
    __syncthreads();
    for (int i = tid; i < NBUCK; i += 512)
        base[i] = lh[i] ? atomicAdd(&g_hist[NBUCK + i], lh[i]) : 0;
    __syncthreads();
    for (int i = tid; i < NBUCK; i += 512) lh[i] = 0;
    __syncthreads();
    for (int e = lo + tid; e < hi; e += 512) {
        int b = bucket_of(dist[e]);
        int r = atomicAdd(&lh[b], 1);
        g_perm[base[b] + r] = e;
    }
}
__global__ void init_h_k(const int* __restrict__ Z, const float* __restrict__ ne,
                         float* __restrict__ h, int N) {
    int idx = blockIdx.x*256 + threadIdx.x;
    if (idx < N*128) h[idx] = ne[Z[idx >> 7]*128 + (idx & 127)];
}
__global__ void split_pad_k(const float* __restrict__ src, __half* __restrict__ dh,
                            __half* __restrict__ dl,
                            int R, int Ks, int ld, int off, int Kpad, int tot) {
    int idx = blockIdx.x*256 + threadIdx.x;
    if (idx < tot) {
        int r = idx / Kpad, k = idx % Kpad;
        float v = (r < R && k < Ks) ? src[(size_t)r*ld + off + k] : 0.f;
        __half h = __float2half_rn(v);
        dh[idx] = h;
        dl[idx] = __float2half_rn(v - __half2float(h));
    }
}
__global__ void p_kernel(const float* __restrict__ edge_emb, const float* __restrict__ We1,
                         const float* __restrict__ be1, float* __restrict__ P) {
    int ty = blockIdx.x, layer = blockIdx.y, j = threadIdx.x;
    __shared__ float em[128];
    if (j < 128) em[j] = edge_emb[ty*128 + j];
    __syncthreads();
    if (j < 428) {
        const float* wrow = We1 + ((size_t)layer*428 + j)*428;
        float acc = be1[layer*428 + j];
        #pragma unroll 8
        for (int k = 0; k < 128; k++) acc = fmaf(em[k], wrow[k], acc);
        P[((size_t)layer*400 + ty)*428 + j] = acc;
    }
}
__global__ void rbf_klo_k(const float* __restrict__ dist, int E) {
    __shared__ float s[64];
    int tid = threadIdx.x, gr = blockIdx.x*64 + tid;
    s[tid] = dist[g_perm[min(gr, E-1)]];
    __syncthreads();
    for (int o = 32; o > 0; o >>= 1) {
        if (tid < o) s[tid] = fminf(s[tid], s[tid + o]);
        __syncthreads();
    }
    if (tid == 0) {
        int k = (int)floorf((s[0] - 1.055f) * RBF_INV);
        if (k < 0) k = 0;
        g_klo[blockIdx.x] = k & ~7;
    }
}
__global__ void rbf_split_k(const float* __restrict__ dist, int E) {
    int tid = threadIdx.x, gr = blockIdx.x*64 + tid;
    float d = dist[g_perm[min(gr, E-1)]];
    int k0 = g_klo[blockIdx.x];
    float vals[WK];
    #pragma unroll
    for (int i = 0; i < WK; i++) vals[i] = 0.f;
    int icen = (int)(d * RBF_INV) - k0;
    int ilo = max(0, icen - 10);
    int ihi = min(min(WK-1, icen + 10), 299 - k0);
    for (int i = ilo; i <= ihi; i++) {
        float x = d - (float)(k0 + i) * RBF_STEP;
        vals[i] = __expf(-RBF_INV * x * x);
    }
    size_t base = (size_t)gr * WK;
    #pragma unroll
    for (int i = 0; i < WK; i += 8) {
        uint4 H;
        H.x = packh(vals[i+0], vals[i+1]);
        H.y = packh(vals[i+2], vals[i+3]);
        H.z = packh(vals[i+4], vals[i+5]);
        H.w = packh(vals[i+6], vals[i+7]);
        *(uint4*)(g_rAh + base + i) = H;
    }
}

// ============ fused t -> ee kernel, 64-edge tiles, WK=32, fp16 2-term ============
// smem: Th 0..5120, Ah 5120..10240, W1h 10240(2x2560), W1l 15360(2x2560),
//       W2h 20480(2x10240), W2l 40960(2x10240) = 61440
__global__ void __launch_bounds__(256, 2)
fused_t_ee(const __half* __restrict__ W1h, const __half* __restrict__ W1l,
           const __half* __restrict__ W2h, const __half* __restrict__ W2l,
           const float* __restrict__ P, const float* __restrict__ be2,
           const int* __restrict__ etype, float* __restrict__ ee, int E) {
    extern __shared__ char ds[];
    __shared__ int sety[64];
    __shared__ float sbias[128];
    int tid = threadIdx.x, lane = tid & 31, warp = tid >> 5, bx = blockIdx.x;
    int klo = g_klo[bx];
    if (tid < 64) sety[tid] = etype[g_perm[min(bx*64 + tid, E-1)]];
    if (tid < 128) sbias[tid] = be2[tid];
    uint32_t b0 = smem_u32(ds);
    uint32_t uTh = b0;
    uint32_t uAh = b0 + 5120;
    uint32_t uW1h = b0 + 10240, uW1l = b0 + 15360;
    uint32_t uW2h = b0 + 20480, uW2l = b0 + 40960;

    // A tile 64xWK (stride SLD)
    {
        int row = tid >> 2, kk = (tid & 3) << 3;
        uint32_t d = (uint32_t)(row*SLD + kk)*2;
        size_t s = (size_t)(bx*64 + row)*WK + kk;
        CPA16(uAh + d, g_rAh + s);
    }
    // chunk 0 weights
    if (tid < 128) {
        int row = tid >> 2, kk = (tid & 3) << 3;
        uint32_t d = (uint32_t)(row*SLD + kk)*2;
        size_t s = (size_t)row*384 + klo + kk;
        CPA16(uW1h + d, W1h + s);
        CPA16(uW1l + d, W1l + s);
    }
    for (int i = tid; i < 512; i += 256) {
        int row = i >> 2, kk = (i & 3) * 8;
        uint32_t d = (uint32_t)(row*SLD + kk)*2;
        size_t s = (size_t)row*448 + kk;
        CPA16(uW2h + d, W2h + s);
        CPA16(uW2l + d, W2l + s);
    }
    CPC(); CPW0();
    __syncthreads();

    int arow = lane & 15, acol = (lane >> 4) << 3;
    int brow = (lane & 7) + ((lane >> 1) & 8), bcol = lane & 8;
    int r1 = (warp >> 1)*16, c1 = (warp & 1)*16;
    uint32_t a1off = (uint32_t)((r1 + arow)*SLD + acol)*2;
    uint32_t b1off = (uint32_t)((c1 + brow)*SLD + bcol)*2;
    int m0 = (warp >> 2)*32, n0 = (warp & 3)*32;
    uint32_t a2off[2];
    #pragma unroll
    for (int mi = 0; mi < 2; mi++) a2off[mi] = (uint32_t)((m0 + mi*16 + arow)*SLD + acol)*2;
    uint32_t b2off0 = (uint32_t)((n0 + brow)*SLD + bcol)*2;
    uint32_t b2off1 = (uint32_t)((n0 + 16 + brow)*SLD + bcol)*2;
    int lrow = lane >> 2, lcol = (lane & 3)*2;

    float eacc[2][4][4];
    #pragma unroll
    for (int mi = 0; mi < 2; mi++)
        #pragma unroll
        for (int ni = 0; ni < 4; ni++)
            #pragma unroll
            for (int q = 0; q < 4; q++) eacc[mi][ni][q] = 0.f;

    int buf = 0;
    for (int c = 0; c < 14; c++) {
        if (c < 13) {
            uint32_t cb = (uint32_t)(buf ^ 1);
            if (tid < 128) {
                int row = tid >> 2, kk = (tid & 3) << 3;
                uint32_t d = cb*2560 + (uint32_t)(row*SLD + kk)*2;
                size_t s = (size_t)((c+1)*32 + row)*384 + klo + kk;
                CPA16(uW1h + d, W1h + s);
                CPA16(uW1l + d, W1l + s);
            }
            for (int i = tid; i < 512; i += 256) {
                int row = i >> 2, kk = (i & 3) * 8;
                uint32_t d = cb*10240 + (uint32_t)(row*SLD + kk)*2;
                size_t s = (size_t)row*448 + (c+1)*32 + kk;
                CPA16(uW2h + d, W2h + s);
                CPA16(uW2l + d, W2l + s);
            }
            CPC();
        }
        // MMA1: t_chunk[64,32], K=32
        float acc1[2][4];
        #pragma unroll
        for (int ni = 0; ni < 2; ni++)
            #pragma unroll
            for (int q = 0; q < 4; q++) acc1[ni][q] = 0.f;
        {
            uint32_t w1b = (uint32_t)buf * 2560;
            #pragma unroll
            for (int ks = 0; ks < 2; ks++) {
                uint32_t ah[4], bh[4], bl[4];
                ldmx4(ah[0], ah[1], ah[2], ah[3], uAh + a1off + ks*32);
                ldmx4(bh[0], bh[1], bh[2], bh[3], uW1h + w1b + b1off + ks*32);
                ldmx4(bl[0], bl[1], bl[2], bl[3], uW1l + w1b + b1off + ks*32);
                #pragma unroll
                for (int ni = 0; ni < 2; ni++) {
                    mma16816(acc1[ni], ah, &bh[ni*2]);
                    mma16816(acc1[ni], ah, &bl[ni*2]);
                }
            }
        }
        // epilogue1: +P, relu, pack fp16 -> sT
        {
            int gcb = c*32;
            #pragma unroll
            for (int half = 0; half < 2; half++) {
                int r = r1 + lrow + half*8;
                const float* Pr = P + (size_t)sety[r]*428;
                #pragma unroll
                for (int ni = 0; ni < 2; ni++) {
                    int col = c1 + ni*8 + lcol;
                    int gcol = gcb + col;
                    float v0 = 0.f, v1 = 0.f;
                    if (gcol < 428) {
                        float2 pv = *(const float2*)(Pr + gcol);
                        v0 = fmaxf(acc1[ni][half*2+0] + pv.x, 0.f);
                        v1 = fmaxf(acc1[ni][half*2+1] + pv.y, 0.f);
                    }
                    uint32_t doff = (uint32_t)(r*SLD + col)*2;
                    *(uint32_t*)(ds + doff) = packh(v0, v1);
                }
            }
        }
        __syncthreads();
        // MMA2: ee += t_chunk @ We2_chunk^T
        {
            uint32_t w2b = (uint32_t)buf * 10240;
            #pragma unroll
            for (int ks = 0; ks < 2; ks++) {
                uint32_t bh[8], bl[8];
                ldmx4(bh[0], bh[1], bh[2], bh[3], uW2h + w2b + b2off0 + ks*32);
                ldmx4(bh[4], bh[5], bh[6], bh[7], uW2h + w2b + b2off1 + ks*32);
                ldmx4(bl[0], bl[1], bl[2], bl[3], uW2l + w2b + b2off0 + ks*32);
                ldmx4(bl[4], bl[5], bl[6], bl[7], uW2l + w2b + b2off1 + ks*32);
                #pragma unroll
                for (int mi = 0; mi < 2; mi++) {
                    uint32_t ah[4];
                    ldmx4(ah[0], ah[1], ah[2], ah[3], uTh + a2off[mi] + ks*32);
                    #pragma unroll
                    for (int ni = 0; ni < 4; ni++) {
                        mma16816(eacc[mi][ni], ah, &bh[ni*2]);
                        mma16816(eacc[mi][ni], ah, &bl[ni*2]);
                    }
                }
            }
        }
        if (c < 13) CPW0();
        __syncthreads();
        buf ^= 1;
    }

    int rowb = bx*64 + m0;
    #pragma unroll
    for (int mi = 0; mi < 2; mi++) {
        #pragma unroll
        for (int half = 0; half < 2; half++) {
            int row = rowb + mi*16 + lrow + half*8;
            if (row < E) {
                size_t cb = (size_t)row * 128;
                #pragma unroll
                for (int ni = 0; ni < 4; ni++) {
                    int col = n0 + ni*8 + lcol;
                    float2 o;
                    o.x = eacc[mi][ni][half*2+0] + sbias[col];
                    o.y = eacc[mi][ni][half*2+1] + sbias[col+1];
                    *(float2*)(ee + cb + col) = o;
                }
            }
        }
    }
}

// ============ generic pipelined GEMM (fp16 2-term) ============
// EPI: 0 store, 1 relu store, 3 tanh + red.v2 scatter to Hout[sidx[perm[row]]]
// AMODE: 0 fp32 rows direct; 2 product Af[gidx[perm[row]]]*A2[row]
template<int EPI, int AMODE>
__global__ void __launch_bounds__(256)
gemm_mma(const float* __restrict__ Af, const float* __restrict__ A2,
         int lda, int Kloop,
         const __half* __restrict__ Bh, const __half* __restrict__ Bl, int Kpad,
         const float* __restrict__ bias, float* __restrict__ C, int M,
         const int* __restrict__ gidx, const int* __restrict__ sidx, float* __restrict__ Hout) {
    extern __shared__ char ds[];
    __shared__ float sbias[128];
    int tid = threadIdx.x, lane = tid & 31, warp = tid >> 5;
    if (tid < 128) sbias[tid] = bias[tid];

    uint32_t b0 = smem_u32(ds);
    uint32_t uAh = b0, uBh = b0 + 2*BUFB, uBl = b0 + 4*BUFB;

    const float *p1[4], *p2[4];
    if (AMODE == 0) {
        #pragma unroll
        for (int i = 0; i < 4; i++) {
            int r = blockIdx.x*128 + i*32 + (tid >> 3);
            p1[i] = Af + (size_t)min(r, M-1) * lda;
        }
    } else {
        #pragma unroll
        for (int i = 0; i < 4; i++) {
            int r = blockIdx.x*128 + i*32 + (tid >> 3);
            int rc = min(r, M-1);
            p1[i] = Af + (size_t)gidx[g_perm[rc]] * 128;
            p2[i] = A2 + (size_t)rc * 128;
        }
    }
    int akoff = (tid & 7) << 2;
    int ckoff = (tid & 3) << 3;
    int crow  = tid >> 2;
    uint32_t cdst0 = ((uint32_t)crow * SLD + ckoff) * 2;
    uint32_t cdst1 = ((uint32_t)(crow + 64) * SLD + ckoff) * 2;
    uint32_t asts[4];
    #pragma unroll
    for (int i = 0; i < 4; i++) asts[i] = ((uint32_t)(i*32 + (tid >> 3)) * SLD + akoff) * 2;

    int m0 = (warp >> 2) * 64, n0 = (warp & 3) * 32;
    int arow = lane & 15, acol = (lane >> 4) << 3;
    int brow = (lane & 7) + ((lane >> 1) & 8), bcol = lane & 8;
    uint32_t aoff[4];
    #pragma unroll
    for (int mi = 0; mi < 4; mi++) aoff[mi] = ((m0 + mi*16 + arow)*SLD + acol) * 2;
    uint32_t boff0 = ((n0 + brow)*SLD + bcol) * 2;
    uint32_t boff1 = ((n0 + 16 + brow)*SLD + bcol) * 2;

    float acc[4][4][4];
    #pragma unroll
    for (int mi = 0; mi < 4; mi++)
        #pragma unroll
        for (int ni = 0; ni < 4; ni++)
            #pragma unroll
            for (int q = 0; q < 4; q++) acc[mi][ni][q] = 0.f;

    uint2 rAh[4];
    int nch = Kloop >> 5;

    {
        CPA16(uBh + cdst0, Bh + (size_t)crow * Kpad + ckoff);
        CPA16(uBh + cdst1, Bh + (size_t)(crow + 64) * Kpad + ckoff);
        CPA16(uBl + cdst0, Bl + (size_t)crow * Kpad + ckoff);
        CPA16(uBl + cdst1, Bl + (size_t)(crow + 64) * Kpad + ckoff);
        CPC();
        #pragma unroll
        for (int i = 0; i < 4; i++) {
            float4 f;
            if (AMODE == 0) f = *(const float4*)(p1[i] + akoff);
            else {
                float4 f1 = *(const float4*)(p1[i] + akoff);
                float4 f2 = *(const float4*)(p2[i] + akoff);
                f.x = f1.x*f2.x; f.y = f1.y*f2.y; f.z = f1.z*f2.z; f.w = f1.w*f2.w;
            }
            rAh[i].x = packh(f.x, f.y);
            rAh[i].y = packh(f.z, f.w);
        }
        #pragma unroll
        for (int i = 0; i < 4; i++) *(uint2*)(ds + asts[i]) = rAh[i];
        CPW0();
        __syncthreads();
    }

    int buf = 0;
    for (int c = 0; c < nch; c++) {
        int k1 = (c + 1) << 5;
        bool more = (c + 1) < nch;
        if (more) {
            uint32_t bb = (uint32_t)(buf ^ 1) * BUFB;
            CPA16(uBh + bb + cdst0, Bh + (size_t)crow * Kpad + k1 + ckoff);
            CPA16(uBh + bb + cdst1, Bh + (size_t)(crow + 64) * Kpad + k1 + ckoff);
            CPA16(uBl + bb + cdst0, Bl + (size_t)crow * Kpad + k1 + ckoff);
            CPA16(uBl + bb + cdst1, Bl + (size_t)(crow + 64) * Kpad + k1 + ckoff);
            CPC();
            #pragma unroll
            for (int i = 0; i < 4; i++) {
                float4 f;
                if (AMODE == 0) f = *(const float4*)(p1[i] + k1 + akoff);
                else {
                    float4 f1 = *(const float4*)(p1[i] + k1 + akoff);
                    float4 f2 = *(const float4*)(p2[i] + k1 + akoff);
                    f.x = f1.x*f2.x; f.y = f1.y*f2.y; f.z = f1.z*f2.z; f.w = f1.w*f2.w;
                }
                rAh[i].x = packh(f.x, f.y);
                rAh[i].y = packh(f.z, f.w);
            }
        }
        {
            uint32_t bb = (uint32_t)buf * BUFB;
            #pragma unroll
            for (int ks = 0; ks < 2; ks++) {
                uint32_t bh[8], bl[8];
                ldmx4(bh[0], bh[1], bh[2], bh[3], uBh + bb + boff0 + ks*32);
                ldmx4(bh[4], bh[5], bh[6], bh[7], uBh + bb + boff1 + ks*32);
                ldmx4(bl[0], bl[1], bl[2], bl[3], uBl + bb + boff0 + ks*32);
                ldmx4(bl[4], bl[5], bl[6], bl[7], uBl + bb + boff1 + ks*32);
                #pragma unroll
                for (int mi = 0; mi < 4; mi++) {
                    uint32_t ah[4];
                    ldmx4(ah[0], ah[1], ah[2], ah[3], uAh + bb + aoff[mi] + ks*32);
                    #pragma unroll
                    for (int ni = 0; ni < 4; ni++) {
                        mma16816(acc[mi][ni], ah, &bh[ni*2]);
                        mma16816(acc[mi][ni], ah, &bl[ni*2]);
                    }
                }
            }
        }
        if (more) {
            uint32_t bb = (uint32_t)(buf ^ 1) * BUFB;
            #pragma unroll
            for (int i = 0; i < 4; i++) *(uint2*)(ds + bb + asts[i]) = rAh[i];
            CPW0();
            __syncthreads();
            buf ^= 1;
        }
    }

    int rowb = blockIdx.x*128 + m0;
    #pragma unroll
    for (int mi = 0; mi < 4; mi++) {
        #pragma unroll
        for (int half = 0; half < 2; half++) {
            int row = rowb + mi*16 + (lane >> 2) + half*8;
            if (row < M) {
                if (EPI == 3) {
                    int dg = sidx[g_perm[row]];
                    float* Hr = Hout + (size_t)dg * 128;
                    #pragma unroll
                    for (int ni = 0; ni < 4; ni++) {
                        int col = n0 + ni*8 + (lane & 3)*2;
                        float v0 = tanhf(acc[mi][ni][half*2+0] + sbias[col]);
                        float v1 = tanhf(acc[mi][ni][half*2+1] + sbias[col+1]);
                        redv2(Hr + col, v0, v1);
                    }
                } else {
                    size_t cb = (size_t)row * 128;
                    #pragma unroll
                    for (int ni = 0; ni < 4; ni++) {
                        int col = n0 + ni*8 + (lane & 3)*2;
                        float v0 = acc[mi][ni][half*2+0] + sbias[col];
                        float v1 = acc[mi][ni][half*2+1] + sbias[col+1];
                        if (EPI == 1) { v0 = fmaxf(v0, 0.f); v1 = fmaxf(v1, 0.f); }
                        float2 o = make_float2(v0, v1);
                        *(float2*)(C + cb + col) = o;
                    }
                }
            }
        }
    }
}

__global__ void readout2_k(const float* __restrict__ rr, const float* __restrict__ Wr2,
                           const float* __restrict__ br2, const int* __restrict__ gid,
                           float* __restrict__ out, int N) {
    __shared__ float w[128];
    int tid = threadIdx.x;
    if (tid < 128) w[tid] = Wr2[tid];
    __syncthreads();
    int warp = tid >> 5, lane = tid & 31;
    int n = blockIdx.x*4 + warp;
    if (n >= N) return;
    const float* hr = rr + (size_t)n * 128;
    float s = 0.f;
    #pragma unroll
    for (int i = 0; i < 4; i++) s = fmaf(hr[lane + i*32], w[lane + i*32], s);
    #pragma unroll
    for (int o = 16; o > 0; o >>= 1) s += __shfl_down_sync(0xffffffffu, s, o);
    if (lane == 0) atomicAdd(&out[gid[n]], s + br2[0]);
}

extern "C" void kernel_launch(void* const* d_in, const int* in_sizes, int n_in,
                              void* d_out, int out_size) {
    const int*   Z     = (const int*)  d_in[0];
    const int*   etype = (const int*)  d_in[1];
    const float* dist  = (const float*)d_in[2];
    const int*   src   = (const int*)  d_in[3];
    const int*   dst   = (const int*)  d_in[4];
    const int*   gid   = (const int*)  d_in[5];
    const float* node_emb = (const float*)d_in[6];
    const float* edge_emb = (const float*)d_in[7];
    const float* Wn1 = (const float*)d_in[8];
    const float* bn1 = (const float*)d_in[9];
    const float* Wn2 = (const float*)d_in[10];
    const float* bn2 = (const float*)d_in[11];
    const float* We1 = (const float*)d_in[12];
    const float* be1 = (const float*)d_in[13];
    const float* We2 = (const float*)d_in[14];
    const float* be2 = (const float*)d_in[15];
    const float* Wc  = (const float*)d_in[16];
    const float* bc  = (const float*)d_in[17];
    const float* Wr1 = (const float*)d_in[18];
    const float* br1 = (const float*)d_in[19];
    const float* Wr2 = (const float*)d_in[20];
    const float* br2 = (const float*)d_in[21];

    int N = in_sizes[0], E = in_sizes[1], G = out_size;
    float* out = (float*)d_out;

    static cudaStream_t s1 = 0, s2 = 0;
    static cudaEvent_t evF, evRBF, evA[3], evB[3], evC[3];
    static bool sinit = false;
    if (!sinit) {
        cudaStreamCreateWithFlags(&s1, cudaStreamNonBlocking);
        cudaStreamCreateWithFlags(&s2, cudaStreamNonBlocking);
        cudaEventCreateWithFlags(&evF,   cudaEventDisableTiming);
        cudaEventCreateWithFlags(&evRBF, cudaEventDisableTiming);
        for (int i = 0; i < 3; i++) {
            cudaEventCreateWithFlags(&evA[i], cudaEventDisableTiming);
            cudaEventCreateWithFlags(&evB[i], cudaEventDisableTiming);
            cudaEventCreateWithFlags(&evC[i], cudaEventDisableTiming);
        }
        cudaFuncSetAttribute((const void*)fused_t_ee,    cudaFuncAttributeMaxDynamicSharedMemorySize, DSMEM4);
        cudaFuncSetAttribute((const void*)gemm_mma<1,0>, cudaFuncAttributeMaxDynamicSharedMemorySize, DSMEM2);
        cudaFuncSetAttribute((const void*)gemm_mma<0,0>, cudaFuncAttributeMaxDynamicSharedMemorySize, DSMEM2);
        cudaFuncSetAttribute((const void*)gemm_mma<3,2>, cudaFuncAttributeMaxDynamicSharedMemorySize, DSMEM2);
        sinit = true;
    }

    void* p;
    float *h, *ee, *tmp, *P;
    __half *W1h,*W1l,*We2h,*We2l,*Wn1h,*Wn1l,*Wn2h,*Wn2l,*Wch,*Wcl,*Wr1h,*Wr1l;
    cudaGetSymbolAddress(&p, g_h);   h   = (float*)p;
    cudaGetSymbolAddress(&p, g_ee);  ee  = (float*)p;
    cudaGetSymbolAddress(&p, g_tmp); tmp = (float*)p;
    cudaGetSymbolAddress(&p, g_P);   P   = (float*)p;
    cudaGetSymbolAddress(&p, g_W1h);  W1h  = (__half*)p;
    cudaGetSymbolAddress(&p, g_W1l);  W1l  = (__half*)p;
    cudaGetSymbolAddress(&p, g_We2h); We2h = (__half*)p;
    cudaGetSymbolAddress(&p, g_We2l); We2l = (__half*)p;
    cudaGetSymbolAddress(&p, g_Wn1h); Wn1h = (__half*)p;
    cudaGetSymbolAddress(&p, g_Wn1l); Wn1l = (__half*)p;
    cudaGetSymbolAddress(&p, g_Wn2h); Wn2h = (__half*)p;
    cudaGetSymbolAddress(&p, g_Wn2l); Wn2l = (__half*)p;
    cudaGetSymbolAddress(&p, g_Wch);  Wch  = (__half*)p;
    cudaGetSymbolAddress(&p, g_Wcl);  Wcl  = (__half*)p;
    cudaGetSymbolAddress(&p, g_Wr1h); Wr1h = (__half*)p;
    cudaGetSymbolAddress(&p, g_Wr1l); Wr1l = (__half*)p;

    int gE = (E + 127)/128, gE2 = (E + 63)/64, gN = (N + 127)/128;

    cudaEventRecord(evF, 0);
    cudaStreamWaitEvent(s1, evF, 0);
    cudaStreamWaitEvent(s2, evF, 0);

    // main: sort + rbf chain
    zero_hist_k<<<(2*NBUCK + 255)/256, 256>>>();
    hist_k<<<148, 512>>>(dist, E);
    scan512_k<<<1, NBUCK>>>();
    scatter_perm_k<<<148, 512>>>(dist, E);
    rbf_klo_k<<<gE2, 64>>>(dist, E);
    rbf_split_k<<<gE2, 64>>>(dist, E);
    cudaEventRecord(evRBF, 0);

    // s1: node-side prep
    init_h_k<<<(N*128 + 255)/256, 256, 0, s1>>>(Z, node_emb, h, N);
    for (int i = 0; i < 3; i++) {
        split_pad_k<<<(128*128 + 255)/256, 256, 0, s1>>>(Wn1 + (size_t)i*128*128, Wn1h + (size_t)i*128*128, Wn1l + (size_t)i*128*128, 128, 128, 128, 0, 128, 128*128);
        split_pad_k<<<(128*128 + 255)/256, 256, 0, s1>>>(Wn2 + (size_t)i*128*128, Wn2h + (size_t)i*128*128, Wn2l + (size_t)i*128*128, 128, 128, 128, 0, 128, 128*128);
    }
    split_pad_k<<<(128*128 + 255)/256, 256, 0, s1>>>(Wr1, Wr1h, Wr1l, 128, 128, 128, 0, 128, 128*128);

    // s2: edge-side prep
    for (int i = 0; i < 3; i++) {
        split_pad_k<<<(512*384 + 255)/256, 256, 0, s2>>>(We1 + (size_t)i*428*428, W1h + (size_t)i*512*384, W1l + (size_t)i*512*384, 428, 300, 428, 128, 384, 512*384);
        split_pad_k<<<(128*448 + 255)/256, 256, 0, s2>>>(We2 + (size_t)i*128*428, We2h + (size_t)i*128*448, We2l + (size_t)i*128*448, 128, 428, 428, 0, 448, 128*448);
        split_pad_k<<<(128*128 + 255)/256, 256, 0, s2>>>(Wc  + (size_t)i*128*128, Wch  + (size_t)i*128*128, Wcl  + (size_t)i*128*128, 128, 128, 128, 0, 128, 128*128);
    }
    p_kernel<<<dim3(400, 3), 448, 0, s2>>>(edge_emb, We1, be1, P);
    cudaStreamWaitEvent(s2, evRBF, 0);

    for (int i = 0; i < 3; i++) {
        float* eeb = ee + (size_t)(i & 1) * E_MAXE * 128;
        if (i >= 2) cudaStreamWaitEvent(s2, evC[i-2], 0);
        fused_t_ee<<<gE2, 256, DSMEM4, s2>>>(W1h + (size_t)i*512*384, W1l + (size_t)i*512*384,
                                             We2h + (size_t)i*128*448, We2l + (size_t)i*128*448,
                                             P + (size_t)i*400*428, be2 + i*128, etype, eeb, E);
        cudaEventRecord(evB[i], s2);

        if (i >= 1) cudaStreamWaitEvent(s1, evC[i-1], 0);
        gemm_mma<1,0><<<gN, 256, DSMEM2, s1>>>(h, nullptr, 128, 128,
            Wn1h + (size_t)i*128*128, Wn1l + (size_t)i*128*128, 128,
            bn1 + i*128, tmp, N, nullptr, nullptr, nullptr);
        gemm_mma<0,0><<<gN, 256, DSMEM2, s1>>>(tmp, nullptr, 128, 128,
            Wn2h + (size_t)i*128*128, Wn2l + (size_t)i*128*128, 128,
            bn2 + i*128, tmp, N, nullptr, nullptr, nullptr);
        cudaEventRecord(evA[i], s1);

        cudaStreamWaitEvent(0, evA[i], 0);
        cudaStreamWaitEvent(0, evB[i], 0);
        gemm_mma<3,2><<<gE, 256, DSMEM2, 0>>>(tmp, eeb, 128, 128,
            Wch + (size_t)i*128*128, Wcl + (size_t)i*128*128, 128,
            bc + i*128, nullptr, E, src, dst, h);
        cudaEventRecord(evC[i], 0);
    }

    gemm_mma<1,0><<<gN, 256, DSMEM2, 0>>>(h, nullptr, 128, 128,
        Wr1h, Wr1l, 128, br1, tmp, N, nullptr, nullptr, nullptr);
    zero_f_k<<<(G + 255)/256, 256>>>(out, G);
    readout2_k<<<(N + 3)/4, 128>>>(tmp, Wr2, br2, gid, out, N);
}

// round 12
// speedup vs baseline: 2.2812x; 1.3984x over previous
#include <cuda_runtime.h>
#include <cuda_fp16.h>
#include <math.h>
#include <stdint.h>

#define N_RBF 300
#define NBUCK 512
#define N_MAXN 100352
#define E_MAXE 400384
#define GE2_MAX 6256
#define RBF_STEP (30.0f/299.0f)
#define RBF_INV  (299.0f/30.0f)
#define SLD 40
#define WK 32
#define BUFB 10240
#define DSMEM2 40960
#define DSMEM4 35840

__device__ float g_h  [(size_t)N_MAXN*128];
__device__ float g_ee [2*(size_t)E_MAXE*128];
__device__ float g_tmp[(size_t)N_MAXN*128];
__device__ float g_P  [3*400*428];
__device__ int   g_perm[E_MAXE];
__device__ int   g_hist[2*NBUCK];
__device__ int   g_klo [GE2_MAX];
__device__ __half g_rAh[(size_t)E_MAXE*WK];
__device__ __half g_W1h[3*512*384];
__device__ __half g_We2h[3*128*448];
__device__ __half g_Wn1h[3*128*128];
__device__ __half g_Wn2h[3*128*128];
__device__ __half g_Wch [3*128*128];
__device__ __half g_Wr1h[128*128];

__device__ __forceinline__ uint32_t smem_u32(const void* p) {
    uint32_t a;
    asm("{ .reg .u64 t; cvta.to.shared.u64 t, %1; cvt.u32.u64 %0, t; }" : "=r"(a) : "l"(p));
    return a;
}
__device__ __forceinline__ void ldmx4(uint32_t& r0, uint32_t& r1, uint32_t& r2, uint32_t& r3, uint32_t a) {
    asm volatile("ldmatrix.sync.aligned.m8n8.x4.shared.b16 {%0,%1,%2,%3}, [%4];"
        : "=r"(r0), "=r"(r1), "=r"(r2), "=r"(r3) : "r"(a));
}
__device__ __forceinline__ void mma16816(float* c, const uint32_t* a, const uint32_t* b) {
    asm volatile("mma.sync.aligned.m16n8k16.row.col.f32.f16.f16.f32 "
        "{%0,%1,%2,%3},{%4,%5,%6,%7},{%8,%9},{%0,%1,%2,%3};"
        : "+f"(c[0]), "+f"(c[1]), "+f"(c[2]), "+f"(c[3])
        : "r"(a[0]), "r"(a[1]), "r"(a[2]), "r"(a[3]), "r"(b[0]), "r"(b[1]));
}
__device__ __forceinline__ uint32_t packh(float a, float b) {
    __half2 t = __floats2half2_rn(a, b);
    return *reinterpret_cast<uint32_t*>(&t);
}
__device__ __forceinline__ void redv2(float* addr, float v0, float v1) {
    asm volatile("red.global.add.v2.f32 [%0], {%1,%2};" :: "l"(addr), "f"(v0), "f"(v1) : "memory");
}
#define CPA16(dst, src) asm volatile("cp.async.cg.shared.global [%0], [%1], 16;" :: "r"(dst), "l"(src))
#define CPC()  asm volatile("cp.async.commit_group;" ::: "memory")
#define CPW0() asm volatile("cp.async.wait_group 0;" ::: "memory")

__global__ void zero_hist_k() { int i = blockIdx.x*256 + threadIdx.x; if (i < 2*NBUCK) g_hist[i] = 0; }
__global__ void zero_f_k(float* p, int n) { int i = blockIdx.x*256 + threadIdx.x; if (i < n) p[i] = 0.f; }
__device__ __forceinline__ int bucket_of(float d) {
    int b = (int)(d * (512.0f/30.0f));
    return min(max(b, 0), NBUCK-1);
}
__global__ void hist_k(const float* __restrict__ dist, int E) {
    __shared__ int lh[NBUCK];
    int tid = threadIdx.x;
    int per = (E + gridDim.x - 1) / gridDim.x;
    int lo = blockIdx.x * per, hi = min(E, lo + per);
    for (int i = tid; i < NBUCK; i += 512) lh[i] = 0;
    __syncthreads();
    for (int e = lo + tid; e < hi; e += 512) atomicAdd(&lh[bucket_of(dist[e])], 1);
    __syncthreads();
    for (int i = tid; i < NBUCK; i += 512) if (lh[i]) atomicAdd(&g_hist[i], lh[i]);
}
__global__ void scan512_k() {
    __shared__ int s[NBUCK];
    int tid = threadIdx.x;
    int v0 = g_hist[tid];
    s[tid] = v0; __syncthreads();
    for (int off = 1; off < NBUCK; off <<= 1) {
        int v = 0;
        if (tid >= off) v = s[tid - off];
        __syncthreads(); s[tid] += v; __syncthreads();
    }
    g_hist[NBUCK + tid] = s[tid] - v0;
}
__global__ void scatter_perm_k(const float* __restrict__ dist, int E) {
    __shared__ int lh[NBUCK], base[NBUCK];
    int tid = threadIdx.x;
    int per = (E + gridDim.x - 1) / gridDim.x;
    int lo = blockIdx.x * per, hi = min(E, lo + per);
    for (int i = tid; i < NBUCK; i += 512) lh[i] = 0;
    __syncthreads();
    for (int e = lo + tid; e < hi; e += 512) atomicAdd(&lh[bucket_of(dist[e])], 1);
    __syncthreads();
    for (int i = tid; i < NBUCK; i += 512)
        base[i] = lh[i] ? atomicAdd(&g_hist[NBUCK + i], lh[i]) : 0;
    __syncthreads();
    for (int i = tid; i < NBUCK; i += 512) lh[i] = 0;
    __syncthreads();
    for (int e = lo + tid; e < hi; e += 512) {
        int b = bucket_of(dist[e]);
        int r = atomicAdd(&lh[b], 1);
        g_perm[base[b] + r] = e;
    }
}
__global__ void init_h_k(const int* __restrict__ Z, const float* __restrict__ ne,
                         float* __restrict__ h, int N) {
    int idx = blockIdx.x*256 + threadIdx.x;
    if (idx < N*128) h[idx] = ne[Z[idx >> 7]*128 + (idx & 127)];
}
// convert+pad fp32 -> fp16 (single term)
__global__ void conv_pad_k(const float* __restrict__ src, __half* __restrict__ dh,
                           int R, int Ks, int ld, int off, int Kpad, int tot) {
    int idx = blockIdx.x*256 + threadIdx.x;
    if (idx < tot) {
        int r = idx / Kpad, k = idx % Kpad;
        float v = (r < R && k < Ks) ? src[(size_t)r*ld + off + k] : 0.f;
        dh[idx] = __float2half_rn(v);
    }
}
__global__ void p_kernel(const float* __restrict__ edge_emb, const float* __restrict__ We1,
                         const float* __restrict__ be1, float* __restrict__ P) {
    int ty = blockIdx.x, layer = blockIdx.y, j = threadIdx.x;
    __shared__ float em[128];
    if (j < 128) em[j] = edge_emb[ty*128 + j];
    __syncthreads();
    if (j < 428) {
        const float* wrow = We1 + ((size_t)layer*428 + j)*428;
        float acc = be1[layer*428 + j];
        #pragma unroll 8
        for (int k = 0; k < 128; k++) acc = fmaf(em[k], wrow[k], acc);
        P[((size_t)layer*400 + ty)*428 + j] = acc;
    }
}
__global__ void rbf_klo_k(const float* __restrict__ dist, int E) {
    __shared__ float s[64];
    int tid = threadIdx.x, gr = blockIdx.x*64 + tid;
    s[tid] = dist[g_perm[min(gr, E-1)]];
    __syncthreads();
    for (int o = 32; o > 0; o >>= 1) {
        if (tid < o) s[tid] = fminf(s[tid], s[tid + o]);
        __syncthreads();
    }
    if (tid == 0) {
        int k = (int)floorf((s[0] - 1.055f) * RBF_INV);
        if (k < 0) k = 0;
        g_klo[blockIdx.x] = k & ~7;
    }
}
__global__ void rbf_split_k(const float* __restrict__ dist, int E) {
    int tid = threadIdx.x, gr = blockIdx.x*64 + tid;
    float d = dist[g_perm[min(gr, E-1)]];
    int k0 = g_klo[blockIdx.x];
    float vals[WK];
    #pragma unroll
    for (int i = 0; i < WK; i++) vals[i] = 0.f;
    int icen = (int)(d * RBF_INV) - k0;
    int ilo = max(0, icen - 10);
    int ihi = min(min(WK-1, icen + 10), 299 - k0);
    for (int i = ilo; i <= ihi; i++) {
        float x = d - (float)(k0 + i) * RBF_STEP;
        vals[i] = __expf(-RBF_INV * x * x);
    }
    size_t base = (size_t)gr * WK;
    #pragma unroll
    for (int i = 0; i < WK; i += 8) {
        uint4 H;
        H.x = packh(vals[i+0], vals[i+1]);
        H.y = packh(vals[i+2], vals[i+3]);
        H.z = packh(vals[i+4], vals[i+5]);
        H.w = packh(vals[i+6], vals[i+7]);
        *(uint4*)(g_rAh + base + i) = H;
    }
}

// ============ fused t -> ee kernel, 64-edge tiles, WK=32, single fp16 ============
// smem: Th 0..5120, Ah 5120..10240, W1 10240(2x2560), W2 15360(2x10240) = 35840
__global__ void __launch_bounds__(256, 2)
fused_t_ee(const __half* __restrict__ W1, const __half* __restrict__ W2,
           const float* __restrict__ P, const float* __restrict__ be2,
           const int* __restrict__ etype, float* __restrict__ ee, int E) {
    extern __shared__ char ds[];
    __shared__ int sety[64];
    __shared__ float sbias[128];
    int tid = threadIdx.x, lane = tid & 31, warp = tid >> 5, bx = blockIdx.x;
    int klo = g_klo[bx];
    if (tid < 64) sety[tid] = etype[g_perm[min(bx*64 + tid, E-1)]];
    if (tid < 128) sbias[tid] = be2[tid];
    uint32_t b0 = smem_u32(ds);
    uint32_t uTh = b0;
    uint32_t uAh = b0 + 5120;
    uint32_t uW1 = b0 + 10240;
    uint32_t uW2 = b0 + 15360;

    // A tile 64xWK (stride SLD)
    {
        int row = tid >> 2, kk = (tid & 3) << 3;
        uint32_t d = (uint32_t)(row*SLD + kk)*2;
        size_t s = (size_t)(bx*64 + row)*WK + kk;
        CPA16(uAh + d, g_rAh + s);
    }
    // chunk 0 weights
    if (tid < 128) {
        int row = tid >> 2, kk = (tid & 3) << 3;
        uint32_t d = (uint32_t)(row*SLD + kk)*2;
        size_t s = (size_t)row*384 + klo + kk;
        CPA16(uW1 + d, W1 + s);
    }
    for (int i = tid; i < 512; i += 256) {
        int row = i >> 2, kk = (i & 3) * 8;
        uint32_t d = (uint32_t)(row*SLD + kk)*2;
        size_t s = (size_t)row*448 + kk;
        CPA16(uW2 + d, W2 + s);
    }
    CPC(); CPW0();
    __syncthreads();

    int arow = lane & 15, acol = (lane >> 4) << 3;
    int brow = (lane & 7) + ((lane >> 1) & 8), bcol = lane & 8;
    int r1 = (warp >> 1)*16, c1 = (warp & 1)*16;
    uint32_t a1off = (uint32_t)((r1 + arow)*SLD + acol)*2;
    uint32_t b1off = (uint32_t)((c1 + brow)*SLD + bcol)*2;
    int m0 = (warp >> 2)*32, n0 = (warp & 3)*32;
    uint32_t a2off[2];
    #pragma unroll
    for (int mi = 0; mi < 2; mi++) a2off[mi] = (uint32_t)((m0 + mi*16 + arow)*SLD + acol)*2;
    uint32_t b2off0 = (uint32_t)((n0 + brow)*SLD + bcol)*2;
    uint32_t b2off1 = (uint32_t)((n0 + 16 + brow)*SLD + bcol)*2;
    int lrow = lane >> 2, lcol = (lane & 3)*2;

    float eacc[2][4][4];
    #pragma unroll
    for (int mi = 0; mi < 2; mi++)
        #pragma unroll
        for (int ni = 0; ni < 4; ni++)
            #pragma unroll
            for (int q = 0; q < 4; q++) eacc[mi][ni][q] = 0.f;

    int buf = 0;
    for (int c = 0; c < 14; c++) {
        if (c < 13) {
            uint32_t cb = (uint32_t)(buf ^ 1);
            if (tid < 128) {
                int row = tid >> 2, kk = (tid & 3) << 3;
                uint32_t d = cb*2560 + (uint32_t)(row*SLD + kk)*2;
                size_t s = (size_t)((c+1)*32 + row)*384 + klo + kk;
                CPA16(uW1 + d, W1 + s);
            }
            for (int i = tid; i < 512; i += 256) {
                int row = i >> 2, kk = (i & 3) * 8;
                uint32_t d = cb*10240 + (uint32_t)(row*SLD + kk)*2;
                size_t s = (size_t)row*448 + (c+1)*32 + kk;
                CPA16(uW2 + d, W2 + s);
            }
            CPC();
        }
        // MMA1: t_chunk[64,32], K=32
        float acc1[2][4];
        #pragma unroll
        for (int ni = 0; ni < 2; ni++)
            #pragma unroll
            for (int q = 0; q < 4; q++) acc1[ni][q] = 0.f;
        {
            uint32_t w1b = (uint32_t)buf * 2560;
            #pragma unroll
            for (int ks = 0; ks < 2; ks++) {
                uint32_t ah[4], bh[4];
                ldmx4(ah[0], ah[1], ah[2], ah[3], uAh + a1off + ks*32);
                ldmx4(bh[0], bh[1], bh[2], bh[3], uW1 + w1b + b1off + ks*32);
                #pragma unroll
                for (int ni = 0; ni < 2; ni++)
                    mma16816(acc1[ni], ah, &bh[ni*2]);
            }
        }
        // epilogue1: +P, relu, pack fp16 -> sT
        {
            int gcb = c*32;
            #pragma unroll
            for (int half = 0; half < 2; half++) {
                int r = r1 + lrow + half*8;
                const float* Pr = P + (size_t)sety[r]*428;
                #pragma unroll
                for (int ni = 0; ni < 2; ni++) {
                    int col = c1 + ni*8 + lcol;
                    int gcol = gcb + col;
                    float v0 = 0.f, v1 = 0.f;
                    if (gcol < 428) {
                        float2 pv = *(const float2*)(Pr + gcol);
                        v0 = fmaxf(acc1[ni][half*2+0] + pv.x, 0.f);
                        v1 = fmaxf(acc1[ni][half*2+1] + pv.y, 0.f);
                    }
                    uint32_t doff = (uint32_t)(r*SLD + col)*2;
                    *(uint32_t*)(ds + doff) = packh(v0, v1);
                }
            }
        }
        __syncthreads();
        // MMA2: ee += t_chunk @ We2_chunk^T
        {
            uint32_t w2b = (uint32_t)buf * 10240;
            #pragma unroll
            for (int ks = 0; ks < 2; ks++) {
                uint32_t bh[8];
                ldmx4(bh[0], bh[1], bh[2], bh[3], uW2 + w2b + b2off0 + ks*32);
                ldmx4(bh[4], bh[5], bh[6], bh[7], uW2 + w2b + b2off1 + ks*32);
                #pragma unroll
                for (int mi = 0; mi < 2; mi++) {
                    uint32_t ah[4];
                    ldmx4(ah[0], ah[1], ah[2], ah[3], uTh + a2off[mi] + ks*32);
                    #pragma unroll
                    for (int ni = 0; ni < 4; ni++)
                        mma16816(eacc[mi][ni], ah, &bh[ni*2]);
                }
            }
        }
        if (c < 13) CPW0();
        __syncthreads();
        buf ^= 1;
    }

    int rowb = bx*64 + m0;
    #pragma unroll
    for (int mi = 0; mi < 2; mi++) {
        #pragma unroll
        for (int half = 0; half < 2; half++) {
            int row = rowb + mi*16 + lrow + half*8;
            if (row < E) {
                size_t cb = (size_t)row * 128;
                #pragma unroll
                for (int ni = 0; ni < 4; ni++) {
                    int col = n0 + ni*8 + lcol;
                    float2 o;
                    o.x = eacc[mi][ni][half*2+0] + sbias[col];
                    o.y = eacc[mi][ni][half*2+1] + sbias[col+1];
                    *(float2*)(ee + cb + col) = o;
                }
            }
        }
    }
}

// ============ generic pipelined GEMM (single fp16) ============
// EPI: 0 store, 1 relu store, 3 tanh + red.v2 scatter to Hout[sidx[perm[row]]]
// AMODE: 0 fp32 rows direct; 2 product Af[gidx[perm[row]]]*A2[row]
template<int EPI, int AMODE>
__global__ void __launch_bounds__(256)
gemm_mma(const float* __restrict__ Af, const float* __restrict__ A2,
         int lda, int Kloop,
         const __half* __restrict__ Bh, int Kpad,
         const float* __restrict__ bias, float* __restrict__ C, int M,
         const int* __restrict__ gidx, const int* __restrict__ sidx, float* __restrict__ Hout) {
    extern __shared__ char ds[];
    __shared__ float sbias[128];
    int tid = threadIdx.x, lane = tid & 31, warp = tid >> 5;
    if (tid < 128) sbias[tid] = bias[tid];

    uint32_t b0 = smem_u32(ds);
    uint32_t uAh = b0, uBh = b0 + 2*BUFB;

    const float *p1[4], *p2[4];
    if (AMODE == 0) {
        #pragma unroll
        for (int i = 0; i < 4; i++) {
            int r = blockIdx.x*128 + i*32 + (tid >> 3);
            p1[i] = Af + (size_t)min(r, M-1) * lda;
        }
    } else {
        #pragma unroll
        for (int i = 0; i < 4; i++) {
            int r = blockIdx.x*128 + i*32 + (tid >> 3);
            int rc = min(r, M-1);
            p1[i] = Af + (size_t)gidx[g_perm[rc]] * 128;
            p2[i] = A2 + (size_t)rc * 128;
        }
    }
    int akoff = (tid & 7) << 2;
    int ckoff = (tid & 3) << 3;
    int crow  = tid >> 2;
    uint32_t cdst0 = ((uint32_t)crow * SLD + ckoff) * 2;
    uint32_t cdst1 = ((uint32_t)(crow + 64) * SLD + ckoff) * 2;
    uint32_t asts[4];
    #pragma unroll
    for (int i = 0; i < 4; i++) asts[i] = ((uint32_t)(i*32 + (tid >> 3)) * SLD + akoff) * 2;

    int m0 = (warp >> 2) * 64, n0 = (warp & 3) * 32;
    int arow = lane & 15, acol = (lane >> 4) << 3;
    int brow = (lane & 7) + ((lane >> 1) & 8), bcol = lane & 8;
    uint32_t aoff[4];
    #pragma unroll
    for (int mi = 0; mi < 4; mi++) aoff[mi] = ((m0 + mi*16 + arow)*SLD + acol) * 2;
    uint32_t boff0 = ((n0 + brow)*SLD + bcol) * 2;
    uint32_t boff1 = ((n0 + 16 + brow)*SLD + bcol) * 2;

    float acc[4][4][4];
    #pragma unroll
    for (int mi = 0; mi < 4; mi++)
        #pragma unroll
        for (int ni = 0; ni < 4; ni++)
            #pragma unroll
            for (int q = 0; q < 4; q++) acc[mi][ni][q] = 0.f;

    uint2 rAh[4];
    int nch = Kloop >> 5;

    {
        CPA16(uBh + cdst0, Bh + (size_t)crow * Kpad + ckoff);
        CPA16(uBh + cdst1, Bh + (size_t)(crow + 64) * Kpad + ckoff);
        CPC();
        #pragma unroll
        for (int i = 0; i < 4; i++) {
            float4 f;
            if (AMODE == 0) f = *(const float4*)(p1[i] + akoff);
            else {
                float4 f1 = *(const float4*)(p1[i] + akoff);
                float4 f2 = *(const float4*)(p2[i] + akoff);
                f.x = f1.x*f2.x; f.y = f1.y*f2.y; f.z = f1.z*f2.z; f.w = f1.w*f2.w;
            }
            rAh[i].x = packh(f.x, f.y);
            rAh[i].y = packh(f.z, f.w);
        }
        #pragma unroll
        for (int i = 0; i < 4; i++) *(uint2*)(ds + asts[i]) = rAh[i];
        CPW0();
        __syncthreads();
    }

    int buf = 0;
    for (int c = 0; c < nch; c++) {
        int k1 = (c + 1) << 5;
        bool more = (c + 1) < nch;
        if (more) {
            uint32_t bb = (uint32_t)(buf ^ 1) * BUFB;
            CPA16(uBh + bb + cdst0, Bh + (size_t)crow * Kpad + k1 + ckoff);
            CPA16(uBh + bb + cdst1, Bh + (size_t)(crow + 64) * Kpad + k1 + ckoff);
            CPC();
            #pragma unroll
            for (int i = 0; i < 4; i++) {
                float4 f;
                if (AMODE == 0) f = *(const float4*)(p1[i] + k1 + akoff);
                else {
                    float4 f1 = *(const float4*)(p1[i] + k1 + akoff);
                    float4 f2 = *(const float4*)(p2[i] + k1 + akoff);
                    f.x = f1.x*f2.x; f.y = f1.y*f2.y; f.z = f1.z*f2.z; f.w = f1.w*f2.w;
                }
                rAh[i].x = packh(f.x, f.y);
                rAh[i].y = packh(f.z, f.w);
            }
        }
        {
            uint32_t bb = (uint32_t)buf * BUFB;
            #pragma unroll
            for (int ks = 0; ks < 2; ks++) {
                uint32_t bh[8];
                ldmx4(bh[0], bh[1], bh[2], bh[3], uBh + bb + boff0 + ks*32);
                ldmx4(bh[4], bh[5], bh[6], bh[7], uBh + bb + boff1 + ks*32);
                #pragma unroll
                for (int mi = 0; mi < 4; mi++) {
                    uint32_t ah[4];
                    ldmx4(ah[0], ah[1], ah[2], ah[3], uAh + bb + aoff[mi] + ks*32);
                    #pragma unroll
                    for (int ni = 0; ni < 4; ni++)
                        mma16816(acc[mi][ni], ah, &bh[ni*2]);
                }
            }
        }
        if (more) {
            uint32_t bb = (uint32_t)(buf ^ 1) * BUFB;
            #pragma unroll
            for (int i = 0; i < 4; i++) *(uint2*)(ds + bb + asts[i]) = rAh[i];
            CPW0();
            __syncthreads();
            buf ^= 1;
        }
    }

    int rowb = blockIdx.x*128 + m0;
    #pragma unroll
    for (int mi = 0; mi < 4; mi++) {
        #pragma unroll
        for (int half = 0; half < 2; half++) {
            int row = rowb + mi*16 + (lane >> 2) + half*8;
            if (row < M) {
                if (EPI == 3) {
                    int dg = sidx[g_perm[row]];
                    float* Hr = Hout + (size_t)dg * 128;
                    #pragma unroll
                    for (int ni = 0; ni < 4; ni++) {
                        int col = n0 + ni*8 + (lane & 3)*2;
                        float v0 = tanhf(acc[mi][ni][half*2+0] + sbias[col]);
                        float v1 = tanhf(acc[mi][ni][half*2+1] + sbias[col+1]);
                        redv2(Hr + col, v0, v1);
                    }
                } else {
                    size_t cb = (size_t)row * 128;
                    #pragma unroll
                    for (int ni = 0; ni < 4; ni++) {
                        int col = n0 + ni*8 + (lane & 3)*2;
                        float v0 = acc[mi][ni][half*2+0] + sbias[col];
                        float v1 = acc[mi][ni][half*2+1] + sbias[col+1];
                        if (EPI == 1) { v0 = fmaxf(v0, 0.f); v1 = fmaxf(v1, 0.f); }
                        float2 o = make_float2(v0, v1);
                        *(float2*)(C + cb + col) = o;
                    }
                }
            }
        }
    }
}

__global__ void readout2_k(const float* __restrict__ rr, const float* __restrict__ Wr2,
                           const float* __restrict__ br2, const int* __restrict__ gid,
                           float* __restrict__ out, int N) {
    __shared__ float w[128];
    int tid = threadIdx.x;
    if (tid < 128) w[tid] = Wr2[tid];
    __syncthreads();
    int warp = tid >> 5, lane = tid & 31;
    int n = blockIdx.x*4 + warp;
    if (n >= N) return;
    const float* hr = rr + (size_t)n * 128;
    float s = 0.f;
    #pragma unroll
    for (int i = 0; i < 4; i++) s = fmaf(hr[lane + i*32], w[lane + i*32], s);
    #pragma unroll
    for (int o = 16; o > 0; o >>= 1) s += __shfl_down_sync(0xffffffffu, s, o);
    if (lane == 0) atomicAdd(&out[gid[n]], s + br2[0]);
}

extern "C" void kernel_launch(void* const* d_in, const int* in_sizes, int n_in,
                              void* d_out, int out_size) {
    const int*   Z     = (const int*)  d_in[0];
    const int*   etype = (const int*)  d_in[1];
    const float* dist  = (const float*)d_in[2];
    const int*   src   = (const int*)  d_in[3];
    const int*   dst   = (const int*)  d_in[4];
    const int*   gid   = (const int*)  d_in[5];
    const float* node_emb = (const float*)d_in[6];
    const float* edge_emb = (const float*)d_in[7];
    const float* Wn1 = (const float*)d_in[8];
    const float* bn1 = (const float*)d_in[9];
    const float* Wn2 = (const float*)d_in[10];
    const float* bn2 = (const float*)d_in[11];
    const float* We1 = (const float*)d_in[12];
    const float* be1 = (const float*)d_in[13];
    const float* We2 = (const float*)d_in[14];
    const float* be2 = (const float*)d_in[15];
    const float* Wc  = (const float*)d_in[16];
    const float* bc  = (const float*)d_in[17];
    const float* Wr1 = (const float*)d_in[18];
    const float* br1 = (const float*)d_in[19];
    const float* Wr2 = (const float*)d_in[20];
    const float* br2 = (const float*)d_in[21];

    int N = in_sizes[0], E = in_sizes[1], G = out_size;
    float* out = (float*)d_out;

    static cudaStream_t s1 = 0, s2 = 0;
    static cudaEvent_t evF, evRBF, evA[3], evB[3], evC[3];
    static bool sinit = false;
    if (!sinit) {
        cudaStreamCreateWithFlags(&s1, cudaStreamNonBlocking);
        cudaStreamCreateWithFlags(&s2, cudaStreamNonBlocking);
        cudaEventCreateWithFlags(&evF,   cudaEventDisableTiming);
        cudaEventCreateWithFlags(&evRBF, cudaEventDisableTiming);
        for (int i = 0; i < 3; i++) {
            cudaEventCreateWithFlags(&evA[i], cudaEventDisableTiming);
            cudaEventCreateWithFlags(&evB[i], cudaEventDisableTiming);
            cudaEventCreateWithFlags(&evC[i], cudaEventDisableTiming);
        }
        cudaFuncSetAttribute((const void*)fused_t_ee,    cudaFuncAttributeMaxDynamicSharedMemorySize, DSMEM4);
        cudaFuncSetAttribute((const void*)gemm_mma<1,0>, cudaFuncAttributeMaxDynamicSharedMemorySize, DSMEM2);
        cudaFuncSetAttribute((const void*)gemm_mma<0,0>, cudaFuncAttributeMaxDynamicSharedMemorySize, DSMEM2);
        cudaFuncSetAttribute((const void*)gemm_mma<3,2>, cudaFuncAttributeMaxDynamicSharedMemorySize, DSMEM2);
        sinit = true;
    }

    void* p;
    float *h, *ee, *tmp, *P;
    __half *W1h,*We2h,*Wn1h,*Wn2h,*Wch,*Wr1h;
    cudaGetSymbolAddress(&p, g_h);   h   = (float*)p;
    cudaGetSymbolAddress(&p, g_ee);  ee  = (float*)p;
    cudaGetSymbolAddress(&p, g_tmp); tmp = (float*)p;
    cudaGetSymbolAddress(&p, g_P);   P   = (float*)p;
    cudaGetSymbolAddress(&p, g_W1h);  W1h  = (__half*)p;
    cudaGetSymbolAddress(&p, g_We2h); We2h = (__half*)p;
    cudaGetSymbolAddress(&p, g_Wn1h); Wn1h = (__half*)p;
    cudaGetSymbolAddress(&p, g_Wn2h); Wn2h = (__half*)p;
    cudaGetSymbolAddress(&p, g_Wch);  Wch  = (__half*)p;
    cudaGetSymbolAddress(&p, g_Wr1h); Wr1h = (__half*)p;

    int gE = (E + 127)/128, gE2 = (E + 63)/64, gN = (N + 127)/128;

    cudaEventRecord(evF, 0);
    cudaStreamWaitEvent(s1, evF, 0);
    cudaStreamWaitEvent(s2, evF, 0);

    // main: sort + rbf chain
    zero_hist_k<<<(2*NBUCK + 255)/256, 256>>>();
    hist_k<<<148, 512>>>(dist, E);
    scan512_k<<<1, NBUCK>>>();
    scatter_perm_k<<<148, 512>>>(dist, E);
    rbf_klo_k<<<gE2, 64>>>(dist, E);
    rbf_split_k<<<gE2, 64>>>(dist, E);
    cudaEventRecord(evRBF, 0);

    // s1: node-side prep
    init_h_k<<<(N*128 + 255)/256, 256, 0, s1>>>(Z, node_emb, h, N);
    for (int i = 0; i < 3; i++) {
        conv_pad_k<<<(128*128 + 255)/256, 256, 0, s1>>>(Wn1 + (size_t)i*128*128, Wn1h + (size_t)i*128*128, 128, 128, 128, 0, 128, 128*128);
        conv_pad_k<<<(128*128 + 255)/256, 256, 0, s1>>>(Wn2 + (size_t)i*128*128, Wn2h + (size_t)i*128*128, 128, 128, 128, 0, 128, 128*128);
    }
    conv_pad_k<<<(128*128 + 255)/256, 256, 0, s1>>>(Wr1, Wr1h, 128, 128, 128, 0, 128, 128*128);

    // s2: edge-side prep
    for (int i = 0; i < 3; i++) {
        conv_pad_k<<<(512*384 + 255)/256, 256, 0, s2>>>(We1 + (size_t)i*428*428, W1h + (size_t)i*512*384, 428, 300, 428, 128, 384, 512*384);
        conv_pad_k<<<(128*448 + 255)/256, 256, 0, s2>>>(We2 + (size_t)i*128*428, We2h + (size_t)i*128*448, 128, 428, 428, 0, 448, 128*448);
        conv_pad_k<<<(128*128 + 255)/256, 256, 0, s2>>>(Wc  + (size_t)i*128*128, Wch  + (size_t)i*128*128, 128, 128, 128, 0, 128, 128*128);
    }
    p_kernel<<<dim3(400, 3), 448, 0, s2>>>(edge_emb, We1, be1, P);
    cudaStreamWaitEvent(s2, evRBF, 0);

    for (int i = 0; i < 3; i++) {
        float* eeb = ee + (size_t)(i & 1) * E_MAXE * 128;
        if (i >= 2) cudaStreamWaitEvent(s2, evC[i-2], 0);
        fused_t_ee<<<gE2, 256, DSMEM4, s2>>>(W1h + (size_t)i*512*384,
                                             We2h + (size_t)i*128*448,
                                             P + (size_t)i*400*428, be2 + i*128, etype, eeb, E);
        cudaEventRecord(evB[i], s2);

        if (i >= 1) cudaStreamWaitEvent(s1, evC[i-1], 0);
        gemm_mma<1,0><<<gN, 256, DSMEM2, s1>>>(h, nullptr, 128, 128,
            Wn1h + (size_t)i*128*128, 128,
            bn1 + i*128, tmp, N, nullptr, nullptr, nullptr);
        gemm_mma<0,0><<<gN, 256, DSMEM2, s1>>>(tmp, nullptr, 128, 128,
            Wn2h + (size_t)i*128*128, 128,
            bn2 + i*128, tmp, N, nullptr, nullptr, nullptr);
        cudaEventRecord(evA[i], s1);

        cudaStreamWaitEvent(0, evA[i], 0);
        cudaStreamWaitEvent(0, evB[i], 0);
        gemm_mma<3,2><<<gE, 256, DSMEM2, 0>>>(tmp, eeb, 128, 128,
            Wch + (size_t)i*128*128, 128,
            bc + i*128, nullptr, E, src, dst, h);
        cudaEventRecord(evC[i], 0);
    }

    gemm_mma<1,0><<<gN, 256, DSMEM2, 0>>>(h, nullptr, 128, 128,
        Wr1h, 128, br1, tmp, N, nullptr, nullptr, nullptr);
    zero_f_k<<<(G + 255)/256, 256>>>(out, G);
    readout2_k<<<(N + 3)/4, 128>>>(tmp, Wr2, br2, gid, out, N);
}